// round 2
// baseline (speedup 1.0000x reference)
#include <cuda_runtime.h>
#include <cstdint>

#define NN 50000
#define EE 800000
#define CC 256
#define HH 8
#define DD 32
#define FF 512          // ffn hidden
#define SCALE 0.17677669529663689f   // 32^-0.5

// ---------------- scratch (device globals; no allocation) ----------------
__device__ float g_Q[(size_t)NN * CC];
__device__ float g_K[(size_t)NN * CC];
__device__ float g_V[(size_t)NN * CC];
__device__ float g_score[(size_t)EE * HH];   // scores, then reused for unnormalized w
__device__ float g_max[(size_t)NN * HH];
__device__ float g_sum[(size_t)NN * HH];
__device__ float g_agg[(size_t)NN * CC];     // attention aggregation; later reused for ffn2 out
__device__ float g_h1[(size_t)NN * CC];      // ln1 output
__device__ float g_tmp[(size_t)NN * FF];     // Wo out (first N*C), then ffn hidden

// ---------------- zero init ----------------
__global__ void zero_kernel() {
    int idx = blockIdx.x * blockDim.x + threadIdx.x;
    if (idx < NN * CC) g_agg[idx] = 0.f;
    if (idx < NN * HH) { g_max[idx] = 0.f; g_sum[idx] = 0.f; }
}

// ---------------- GEMM: C[M,N] = A[M,K] @ B[K,N] (+bias)(+gelu) ----------------
// BM=128 BN=64 BK=32, 256 threads, 8x4 per thread
template<int BIAS, int GELU>
__global__ __launch_bounds__(256) void gemm_kernel(
    const float* __restrict__ A, const float* __restrict__ B,
    const float* __restrict__ bias, float* __restrict__ C,
    int M, int N, int K)
{
    const int BM = 128, BN = 64, BK = 32;
    __shared__ float As[BK][BM + 4];
    __shared__ float Bs[BK][BN];
    int tid = threadIdx.x;
    int row0 = blockIdx.y * BM;
    int col0 = blockIdx.x * BN;
    int ty = tid >> 4;          // 0..15 -> rows ty*8..+7
    int tx = tid & 15;          // 0..15 -> cols tx*4..+3

    float acc[8][4];
#pragma unroll
    for (int i = 0; i < 8; i++)
#pragma unroll
        for (int j = 0; j < 4; j++) acc[i][j] = 0.f;

    for (int kt = 0; kt < K; kt += BK) {
        // A tile 128x32 -> 1024 float4, 4 per thread, transpose into As[k][m]
#pragma unroll
        for (int j = 0; j < 4; j++) {
            int idx = tid + 256 * j;
            int m = idx >> 3;
            int kk = (idx & 7) * 4;
            float4 v = make_float4(0.f, 0.f, 0.f, 0.f);
            int gr = row0 + m;
            if (gr < M) v = *(const float4*)(A + (size_t)gr * K + kt + kk);
            As[kk + 0][m] = v.x; As[kk + 1][m] = v.y;
            As[kk + 2][m] = v.z; As[kk + 3][m] = v.w;
        }
        // B tile 32x64 -> 512 float4, 2 per thread
#pragma unroll
        for (int j = 0; j < 2; j++) {
            int idx = tid + 256 * j;
            int k = idx >> 4;
            int n4 = idx & 15;
            *(float4*)&Bs[k][n4 * 4] =
                *(const float4*)(B + (size_t)(kt + k) * N + col0 + n4 * 4);
        }
        __syncthreads();
#pragma unroll
        for (int k = 0; k < BK; k++) {
            float a[8], b[4];
#pragma unroll
            for (int i = 0; i < 8; i++) a[i] = As[k][ty * 8 + i];
#pragma unroll
            for (int j = 0; j < 4; j++) b[j] = Bs[k][tx * 4 + j];
#pragma unroll
            for (int i = 0; i < 8; i++)
#pragma unroll
                for (int j = 0; j < 4; j++) acc[i][j] += a[i] * b[j];
        }
        __syncthreads();
    }

    float bv[4] = {0.f, 0.f, 0.f, 0.f};
    if (BIAS) {
#pragma unroll
        for (int j = 0; j < 4; j++) bv[j] = bias[col0 + tx * 4 + j];
    }
#pragma unroll
    for (int i = 0; i < 8; i++) {
        int gr = row0 + ty * 8 + i;
        if (gr < M) {
            float4 o;
            float* op = &o.x;
#pragma unroll
            for (int j = 0; j < 4; j++) {
                float v = acc[i][j] + bv[j];
                if (GELU) v = 0.5f * v * (1.f + erff(v * 0.70710678118654752f));
                op[j] = v;
            }
            *(float4*)(C + (size_t)gr * N + col0 + tx * 4) = o;
        }
    }
}

// ---------------- edge scores + segmented max ----------------
// one warp per edge; lane -> head h = lane>>2, sub = lane&3 (8 floats each)
__global__ __launch_bounds__(256) void edge_score_kernel(const int* __restrict__ ei)
{
    int warp = (blockIdx.x * 256 + threadIdx.x) >> 5;
    if (warp >= EE) return;
    int lane = threadIdx.x & 31;
    int h = lane >> 2, sub = lane & 3;
    int src = ei[warp];
    int dst = ei[EE + warp];
    const float4* q = (const float4*)(g_Q + (size_t)dst * CC + h * DD + sub * 8);
    const float4* k = (const float4*)(g_K + (size_t)src * CC + h * DD + sub * 8);
    float4 q0 = q[0], q1 = q[1];
    float4 k0 = k[0], k1 = k[1];
    float dot = q0.x * k0.x + q0.y * k0.y + q0.z * k0.z + q0.w * k0.w
              + q1.x * k1.x + q1.y * k1.y + q1.z * k1.z + q1.w * k1.w;
    dot += __shfl_xor_sync(0xffffffffu, dot, 1);
    dot += __shfl_xor_sync(0xffffffffu, dot, 2);
    if (sub == 0) {
        float s = dot * SCALE;
        g_score[(size_t)warp * HH + h] = s;
        // max buffer initialized to 0 -> result always >= 0; int compare valid for
        // nonnegative floats, and negative candidates can never win: skip them.
        if (s > 0.f)
            atomicMax((int*)&g_max[(size_t)dst * HH + h], __float_as_int(s));
    }
}

// ---------------- w = exp(s - max[dst]) ; segmented sum ----------------
__global__ __launch_bounds__(256) void edge_exp_kernel(const int* __restrict__ ei)
{
    int idx = blockIdx.x * 256 + threadIdx.x;
    if (idx >= EE * HH) return;
    int e = idx >> 3, h = idx & 7;
    int dst = ei[EE + e];
    float s = g_score[idx];
    float m = g_max[(size_t)dst * HH + h];
    float w = expf(s - m);
    g_score[idx] = w;
    atomicAdd(&g_sum[(size_t)dst * HH + h], w);
}

// ---------------- message passing: agg[dst] += V[src] * w/(sum+1e-8) ----------------
__global__ __launch_bounds__(256) void edge_msg_kernel(const int* __restrict__ ei)
{
    int warp = (blockIdx.x * 256 + threadIdx.x) >> 5;
    if (warp >= EE) return;
    int lane = threadIdx.x & 31;
    int h = lane >> 2, sub = lane & 3;
    int src = ei[warp];
    int dst = ei[EE + warp];
    float w = g_score[(size_t)warp * HH + h];
    float s = g_sum[(size_t)dst * HH + h];
    float coef = w / (s + 1e-8f);
    const float4* vp = (const float4*)(g_V + (size_t)src * CC + h * DD + sub * 8);
    float4 v0 = vp[0], v1 = vp[1];
    float* op = g_agg + (size_t)dst * CC + h * DD + sub * 8;
    asm volatile("red.global.add.v4.f32 [%0], {%1,%2,%3,%4};" ::
                 "l"(op), "f"(v0.x * coef), "f"(v0.y * coef),
                 "f"(v0.z * coef), "f"(v0.w * coef) : "memory");
    asm volatile("red.global.add.v4.f32 [%0], {%1,%2,%3,%4};" ::
                 "l"(op + 4), "f"(v1.x * coef), "f"(v1.y * coef),
                 "f"(v1.z * coef), "f"(v1.w * coef) : "memory");
}

// ---------------- layernorm(out = LN(a + b) * g + bb) ----------------
// 64 threads per row (float4 each), 4 rows per 256-thread block
__global__ __launch_bounds__(256) void ln_kernel(
    const float* __restrict__ a, const float* __restrict__ b,
    const float* __restrict__ g, const float* __restrict__ bb,
    float* __restrict__ out)
{
    __shared__ float red[8][2];
    int r = threadIdx.x >> 6;          // 0..3
    int t = threadIdx.x & 63;          // 0..63
    size_t row = (size_t)blockIdx.x * 4 + r;
    float4 va = ((const float4*)(a + row * CC))[t];
    float4 vb = ((const float4*)(b + row * CC))[t];
    float4 v = make_float4(va.x + vb.x, va.y + vb.y, va.z + vb.z, va.w + vb.w);
    float s = v.x + v.y + v.z + v.w;
    float q = v.x * v.x + v.y * v.y + v.z * v.z + v.w * v.w;
#pragma unroll
    for (int o = 16; o; o >>= 1) {
        s += __shfl_xor_sync(0xffffffffu, s, o);
        q += __shfl_xor_sync(0xffffffffu, q, o);
    }
    int wid = threadIdx.x >> 5;
    if ((threadIdx.x & 31) == 0) { red[wid][0] = s; red[wid][1] = q; }
    __syncthreads();
    int wp = r * 2;
    s = red[wp][0] + red[wp + 1][0];
    q = red[wp][1] + red[wp + 1][1];
    float mu = s * (1.f / 256.f);
    float var = q * (1.f / 256.f) - mu * mu;
    float rs = rsqrtf(var + 1e-5f);
    float4 gg = ((const float4*)g)[t];
    float4 bv = ((const float4*)bb)[t];
    float4 o;
    o.x = (v.x - mu) * rs * gg.x + bv.x;
    o.y = (v.y - mu) * rs * gg.y + bv.y;
    o.z = (v.z - mu) * rs * gg.z + bv.z;
    o.w = (v.w - mu) * rs * gg.w + bv.w;
    ((float4*)(out + row * CC))[t] = o;
}

// ---------------- launch ----------------
extern "C" void kernel_launch(void* const* d_in, const int* in_sizes, int n_in,
                              void* d_out, int out_size)
{
    const float* x      = (const float*)d_in[0];
    const int*   ei     = (const int*)d_in[1];       // int32 (JAX x64 disabled)
    const float* Wq     = (const float*)d_in[3];
    const float* Wk     = (const float*)d_in[4];
    const float* Wv     = (const float*)d_in[5];
    const float* Wo_w   = (const float*)d_in[6];
    const float* Wo_b   = (const float*)d_in[7];
    const float* ln1_g  = (const float*)d_in[8];
    const float* ln1_b  = (const float*)d_in[9];
    const float* ln2_g  = (const float*)d_in[10];
    const float* ln2_b  = (const float*)d_in[11];
    const float* ffn_w1 = (const float*)d_in[12];
    const float* ffn_b1 = (const float*)d_in[13];
    const float* ffn_w2 = (const float*)d_in[14];
    const float* ffn_b2 = (const float*)d_in[15];
    float* out = (float*)d_out;

    float *pQ, *pK, *pV, *pAgg, *pTmp, *pH1;
    cudaGetSymbolAddress((void**)&pQ,   g_Q);
    cudaGetSymbolAddress((void**)&pK,   g_K);
    cudaGetSymbolAddress((void**)&pV,   g_V);
    cudaGetSymbolAddress((void**)&pAgg, g_agg);
    cudaGetSymbolAddress((void**)&pTmp, g_tmp);
    cudaGetSymbolAddress((void**)&pH1,  g_h1);

    dim3 gemm_block(256);
    dim3 grid_c(CC / 64, (NN + 127) / 128);   // N=256
    dim3 grid_f(FF / 64, (NN + 127) / 128);   // N=512

    // 0. zero max/sum/agg
    zero_kernel<<<(NN * CC + 255) / 256, 256>>>();

    // 1. Q,K,V projections
    gemm_kernel<0, 0><<<grid_c, gemm_block>>>(x, Wq, nullptr, pQ, NN, CC, CC);
    gemm_kernel<0, 0><<<grid_c, gemm_block>>>(x, Wk, nullptr, pK, NN, CC, CC);
    gemm_kernel<0, 0><<<grid_c, gemm_block>>>(x, Wv, nullptr, pV, NN, CC, CC);

    // 2. edge scores + segmented max
    edge_score_kernel<<<(EE * 32 + 255) / 256, 256>>>(ei);
    // 3. exp + segmented sum
    edge_exp_kernel<<<(EE * HH + 255) / 256, 256>>>(ei);
    // 4. weighted scatter of V
    edge_msg_kernel<<<(EE * 32 + 255) / 256, 256>>>(ei);

    // 5. output projection (+bias) -> tmp
    gemm_kernel<1, 0><<<grid_c, gemm_block>>>(pAgg, Wo_w, Wo_b, pTmp, NN, CC, CC);
    // 6. LN1(x + tmp) -> h1
    ln_kernel<<<NN / 4, 256>>>(pTmp, x, ln1_g, ln1_b, pH1);
    // 7. FFN1 + GELU -> tmp (N x 512)
    gemm_kernel<1, 1><<<grid_f, gemm_block>>>(pH1, ffn_w1, ffn_b1, pTmp, NN, FF, CC);
    // 8. FFN2 -> agg (reuse)
    gemm_kernel<1, 0><<<grid_c, gemm_block>>>(pTmp, ffn_w2, ffn_b2, pAgg, NN, CC, FF);
    // 9. LN2(h1 + agg) -> out
    ln_kernel<<<NN / 4, 256>>>(pAgg, pH1, ln2_g, ln2_b, out);
}

// round 4
// speedup vs baseline: 1.3368x; 1.3368x over previous
#include <cuda_runtime.h>
#include <cuda_bf16.h>
#include <cstdint>

#define NN 50000
#define EE 800000
#define CC 256
#define HH 8
#define DD 32
#define FF 512
#define SCALE 0.17677669529663689f

// ---------------- scratch ----------------
__device__ float g_Q[(size_t)NN * CC];
__device__ float g_K[(size_t)NN * CC];
__device__ float g_V[(size_t)NN * CC];
__device__ float g_score[(size_t)EE * HH];
__device__ float g_max[(size_t)NN * HH];
__device__ float g_sum[(size_t)NN * HH];
__device__ float g_agg[(size_t)NN * CC];
__device__ float g_h1[(size_t)NN * CC];
__device__ float g_tmp[(size_t)NN * FF];

// ---------------- helpers ----------------
__device__ __forceinline__ uint32_t smem_u32(const void* p) {
    uint32_t a;
    asm("{ .reg .u64 t; cvta.to.shared.u64 t, %1; cvt.u32.u64 %0, t; }" : "=r"(a) : "l"(p));
    return a;
}
#define SWZ(off) ((off) ^ (((off) >> 3) & 0x70))

__device__ __forceinline__ void ldm_x4(uint32_t* r, uint32_t addr) {
    asm volatile("ldmatrix.sync.aligned.m8n8.x4.shared.b16 {%0,%1,%2,%3}, [%4];"
        : "=r"(r[0]), "=r"(r[1]), "=r"(r[2]), "=r"(r[3]) : "r"(addr));
}
__device__ __forceinline__ void mma_bf16(float* d, const uint32_t* a, const uint32_t* b) {
    asm volatile("mma.sync.aligned.m16n8k16.row.col.f32.bf16.bf16.f32 "
        "{%0,%1,%2,%3}, {%4,%5,%6,%7}, {%8,%9}, {%0,%1,%2,%3};"
        : "+f"(d[0]), "+f"(d[1]), "+f"(d[2]), "+f"(d[3])
        : "r"(a[0]), "r"(a[1]), "r"(a[2]), "r"(a[3]), "r"(b[0]), "r"(b[1]));
}
// split fp32 pair -> bf16x2 hi/lo
__device__ __forceinline__ void split2(float x, float y, uint32_t& hi, uint32_t& lo) {
    __nv_bfloat162 h = __float22bfloat162_rn(make_float2(x, y));
    float2 hf = __bfloat1622float2(h);
    __nv_bfloat162 l = __float22bfloat162_rn(make_float2(x - hf.x, y - hf.y));
    hi = *(uint32_t*)&h;
    lo = *(uint32_t*)&l;
}

// ---------------- tensor-core GEMM via mma.sync ----------------
// C[M,N] = A[M,K] @ B[K,N] (+bias)(+gelu)
// CTA 128x128, BK=64. bf16 split: Ah*Bh + Ah*Bl + Al*Bh, fp32 accum in regs.
// 8 warps as 2(M) x 4(N); warp tile 64x32; mma m16n8k16.
#define MMA_SMEM_BYTES (4 * 16384)

template<int BIAS, int GELU>
__global__ __launch_bounds__(256) void mma_gemm(
    const float* __restrict__ A, const float* __restrict__ B,
    const float* __restrict__ bias, float* __restrict__ C,
    int M, int N, int K)
{
    extern __shared__ char smem[];
    uint32_t sb = smem_u32(smem);
    uint32_t sAh = sb, sAl = sb + 16384, sBh = sb + 32768, sBl = sb + 49152;

    int tid = threadIdx.x, wid = tid >> 5, lane = tid & 31;
    int row0 = blockIdx.y * 128;
    int col0 = blockIdx.x * 128;
    int Am0 = (wid >> 2) * 64;       // warp M offset
    int Bn0 = (wid & 3) * 32;        // warp N offset

    // per-thread ldmatrix byte-offset bases (pre-swizzle)
    uint32_t arow[4], brow[2];
#pragma unroll
    for (int mt = 0; mt < 4; mt++)
        arow[mt] = (uint32_t)((Am0 + mt * 16 + (lane & 15)) * 128 + (lane >> 4) * 16);
#pragma unroll
    for (int ntp = 0; ntp < 2; ntp++)
        brow[ntp] = (uint32_t)((Bn0 + ntp * 16 + (lane >> 4) * 8 + (lane & 7)) * 128
                               + ((lane >> 3) & 1) * 16);

    float d[4][4][4];
#pragma unroll
    for (int i = 0; i < 4; i++)
#pragma unroll
        for (int j = 0; j < 4; j++)
#pragma unroll
            for (int e = 0; e < 4; e++) d[i][j][e] = 0.f;

    for (int kt = 0; kt < K; kt += 64) {
        // ---- load & split A tile: 128 rows x 64 k ----
#pragma unroll
        for (int j = 0; j < 8; j++) {
            int idx = tid + 256 * j;
            int m = idx >> 4;
            int kq = idx & 15;
            float4 v = make_float4(0.f, 0.f, 0.f, 0.f);
            int gr = row0 + m;
            if (gr < M) v = *(const float4*)(A + (size_t)gr * K + kt + kq * 4);
            uint32_t h0, l0, h1, l1;
            split2(v.x, v.y, h0, l0);
            split2(v.z, v.w, h1, l1);
            uint32_t off = SWZ((uint32_t)(m * 128 + kq * 8));
            asm volatile("st.shared.v2.u32 [%0], {%1, %2};" :: "r"(sAh + off), "r"(h0), "r"(h1) : "memory");
            asm volatile("st.shared.v2.u32 [%0], {%1, %2};" :: "r"(sAl + off), "r"(l0), "r"(l1) : "memory");
        }
        // ---- load, transpose & split B tile: 64 k x 128 n -> BT[n][k] ----
#pragma unroll
        for (int j = 0; j < 2; j++) {
            int c = tid + 256 * j;
            int n4 = c & 31;
            int kg = c >> 5;
            const float* bp = B + (size_t)(kt + kg * 4) * N + col0 + n4 * 4;
            float4 r0 = *(const float4*)(bp);
            float4 r1 = *(const float4*)(bp + N);
            float4 r2 = *(const float4*)(bp + 2 * (size_t)N);
            float4 r3 = *(const float4*)(bp + 3 * (size_t)N);
            const float* q0 = &r0.x; const float* q1 = &r1.x;
            const float* q2 = &r2.x; const float* q3 = &r3.x;
#pragma unroll
            for (int j2 = 0; j2 < 4; j2++) {
                uint32_t h0, l0, h1, l1;
                split2(q0[j2], q1[j2], h0, l0);
                split2(q2[j2], q3[j2], h1, l1);
                uint32_t off = SWZ((uint32_t)((n4 * 4 + j2) * 128 + kg * 8));
                asm volatile("st.shared.v2.u32 [%0], {%1, %2};" :: "r"(sBh + off), "r"(h0), "r"(h1) : "memory");
                asm volatile("st.shared.v2.u32 [%0], {%1, %2};" :: "r"(sBl + off), "r"(l0), "r"(l1) : "memory");
            }
        }
        __syncthreads();

        // ---- compute: 4 k-steps of m16n8k16 ----
#pragma unroll
        for (int ks = 0; ks < 4; ks++) {
            uint32_t aH[4][4], aL[4][4], bH[4][2], bL[4][2];
#pragma unroll
            for (int mt = 0; mt < 4; mt++) {
                ldm_x4(aH[mt], sAh + SWZ(arow[mt] + ks * 32));
                ldm_x4(aL[mt], sAl + SWZ(arow[mt] + ks * 32));
            }
#pragma unroll
            for (int ntp = 0; ntp < 2; ntp++) {
                ldm_x4(&bH[ntp * 2][0], sBh + SWZ(brow[ntp] + ks * 32));
                ldm_x4(&bL[ntp * 2][0], sBl + SWZ(brow[ntp] + ks * 32));
            }
#pragma unroll
            for (int mt = 0; mt < 4; mt++)
#pragma unroll
                for (int nt = 0; nt < 4; nt++) {
                    mma_bf16(d[mt][nt], aH[mt], bH[nt]);
                    mma_bf16(d[mt][nt], aH[mt], bL[nt]);
                    mma_bf16(d[mt][nt], aL[mt], bH[nt]);
                }
        }
        __syncthreads();
    }

    // ---- epilogue ----
#pragma unroll
    for (int nt = 0; nt < 4; nt++) {
        int c = col0 + Bn0 + nt * 8 + (lane & 3) * 2;
        float b0 = 0.f, b1 = 0.f;
        if (BIAS) { b0 = bias[c]; b1 = bias[c + 1]; }
#pragma unroll
        for (int mt = 0; mt < 4; mt++) {
            int r0 = row0 + Am0 + mt * 16 + (lane >> 2);
#pragma unroll
            for (int half = 0; half < 2; half++) {
                int r = r0 + half * 8;
                if (r < M) {
                    float v0 = d[mt][nt][half * 2 + 0] + b0;
                    float v1 = d[mt][nt][half * 2 + 1] + b1;
                    if (GELU) {
                        v0 = 0.5f * v0 * (1.f + erff(v0 * 0.70710678118654752f));
                        v1 = 0.5f * v1 * (1.f + erff(v1 * 0.70710678118654752f));
                    }
                    *(float2*)(C + (size_t)r * N + c) = make_float2(v0, v1);
                }
            }
        }
    }
}

// ---------------- zero init ----------------
__global__ void zero_kernel() {
    int idx = blockIdx.x * blockDim.x + threadIdx.x;
    if (idx < NN * CC) g_agg[idx] = 0.f;
    if (idx < NN * HH) { g_max[idx] = 0.f; g_sum[idx] = 0.f; }
}

// ---------------- edge scores + segmented max ----------------
__global__ __launch_bounds__(256) void edge_score_kernel(const int* __restrict__ ei)
{
    int warp = (blockIdx.x * 256 + threadIdx.x) >> 5;
    if (warp >= EE) return;
    int lane = threadIdx.x & 31;
    int h = lane >> 2, sub = lane & 3;
    int src = ei[warp];
    int dst = ei[EE + warp];
    const float4* q = (const float4*)(g_Q + (size_t)dst * CC + h * DD + sub * 8);
    const float4* k = (const float4*)(g_K + (size_t)src * CC + h * DD + sub * 8);
    float4 q0 = q[0], q1 = q[1];
    float4 k0 = k[0], k1 = k[1];
    float dot = q0.x * k0.x + q0.y * k0.y + q0.z * k0.z + q0.w * k0.w
              + q1.x * k1.x + q1.y * k1.y + q1.z * k1.z + q1.w * k1.w;
    dot += __shfl_xor_sync(0xffffffffu, dot, 1);
    dot += __shfl_xor_sync(0xffffffffu, dot, 2);
    if (sub == 0) {
        float s = dot * SCALE;
        g_score[(size_t)warp * HH + h] = s;
        if (s > 0.f)
            atomicMax((int*)&g_max[(size_t)dst * HH + h], __float_as_int(s));
    }
}

// ---------------- w = exp(s - max[dst]); segmented sum ----------------
__global__ __launch_bounds__(256) void edge_exp_kernel(const int* __restrict__ ei)
{
    int idx = blockIdx.x * 256 + threadIdx.x;
    if (idx >= EE * HH) return;
    int e = idx >> 3, h = idx & 7;
    int dst = ei[EE + e];
    float s = g_score[idx];
    float m = g_max[(size_t)dst * HH + h];
    float w = expf(s - m);
    g_score[idx] = w;
    atomicAdd(&g_sum[(size_t)dst * HH + h], w);
}

// ---------------- message passing ----------------
__global__ __launch_bounds__(256) void edge_msg_kernel(const int* __restrict__ ei)
{
    int warp = (blockIdx.x * 256 + threadIdx.x) >> 5;
    if (warp >= EE) return;
    int lane = threadIdx.x & 31;
    int h = lane >> 2, sub = lane & 3;
    int src = ei[warp];
    int dst = ei[EE + warp];
    float w = g_score[(size_t)warp * HH + h];
    float s = g_sum[(size_t)dst * HH + h];
    float coef = w / (s + 1e-8f);
    const float4* vp = (const float4*)(g_V + (size_t)src * CC + h * DD + sub * 8);
    float4 v0 = vp[0], v1 = vp[1];
    float* op = g_agg + (size_t)dst * CC + h * DD + sub * 8;
    asm volatile("red.global.add.v4.f32 [%0], {%1,%2,%3,%4};" ::
                 "l"(op), "f"(v0.x * coef), "f"(v0.y * coef),
                 "f"(v0.z * coef), "f"(v0.w * coef) : "memory");
    asm volatile("red.global.add.v4.f32 [%0], {%1,%2,%3,%4};" ::
                 "l"(op + 4), "f"(v1.x * coef), "f"(v1.y * coef),
                 "f"(v1.z * coef), "f"(v1.w * coef) : "memory");
}

// ---------------- layernorm ----------------
__global__ __launch_bounds__(256) void ln_kernel(
    const float* __restrict__ a, const float* __restrict__ b,
    const float* __restrict__ g, const float* __restrict__ bb,
    float* __restrict__ out)
{
    __shared__ float red[8][2];
    int r = threadIdx.x >> 6;
    int t = threadIdx.x & 63;
    size_t row = (size_t)blockIdx.x * 4 + r;
    float4 va = ((const float4*)(a + row * CC))[t];
    float4 vb = ((const float4*)(b + row * CC))[t];
    float4 v = make_float4(va.x + vb.x, va.y + vb.y, va.z + vb.z, va.w + vb.w);
    float s = v.x + v.y + v.z + v.w;
    float q = v.x * v.x + v.y * v.y + v.z * v.z + v.w * v.w;
#pragma unroll
    for (int o = 16; o; o >>= 1) {
        s += __shfl_xor_sync(0xffffffffu, s, o);
        q += __shfl_xor_sync(0xffffffffu, q, o);
    }
    int wid = threadIdx.x >> 5;
    if ((threadIdx.x & 31) == 0) { red[wid][0] = s; red[wid][1] = q; }
    __syncthreads();
    int wp = r * 2;
    s = red[wp][0] + red[wp + 1][0];
    q = red[wp][1] + red[wp + 1][1];
    float mu = s * (1.f / 256.f);
    float var = q * (1.f / 256.f) - mu * mu;
    float rs = rsqrtf(var + 1e-5f);
    float4 gg = ((const float4*)g)[t];
    float4 bv = ((const float4*)bb)[t];
    float4 o;
    o.x = (v.x - mu) * rs * gg.x + bv.x;
    o.y = (v.y - mu) * rs * gg.y + bv.y;
    o.z = (v.z - mu) * rs * gg.z + bv.z;
    o.w = (v.w - mu) * rs * gg.w + bv.w;
    ((float4*)(out + row * CC))[t] = o;
}

// ---------------- launch ----------------
extern "C" void kernel_launch(void* const* d_in, const int* in_sizes, int n_in,
                              void* d_out, int out_size)
{
    const float* x      = (const float*)d_in[0];
    const int*   ei     = (const int*)d_in[1];
    const float* Wq     = (const float*)d_in[3];
    const float* Wk     = (const float*)d_in[4];
    const float* Wv     = (const float*)d_in[5];
    const float* Wo_w   = (const float*)d_in[6];
    const float* Wo_b   = (const float*)d_in[7];
    const float* ln1_g  = (const float*)d_in[8];
    const float* ln1_b  = (const float*)d_in[9];
    const float* ln2_g  = (const float*)d_in[10];
    const float* ln2_b  = (const float*)d_in[11];
    const float* ffn_w1 = (const float*)d_in[12];
    const float* ffn_b1 = (const float*)d_in[13];
    const float* ffn_w2 = (const float*)d_in[14];
    const float* ffn_b2 = (const float*)d_in[15];
    float* out = (float*)d_out;

    float *pQ, *pK, *pV, *pAgg, *pTmp, *pH1;
    cudaGetSymbolAddress((void**)&pQ,   g_Q);
    cudaGetSymbolAddress((void**)&pK,   g_K);
    cudaGetSymbolAddress((void**)&pV,   g_V);
    cudaGetSymbolAddress((void**)&pAgg, g_agg);
    cudaGetSymbolAddress((void**)&pTmp, g_tmp);
    cudaGetSymbolAddress((void**)&pH1,  g_h1);

    cudaFuncSetAttribute(mma_gemm<0, 0>, cudaFuncAttributeMaxDynamicSharedMemorySize, MMA_SMEM_BYTES);
    cudaFuncSetAttribute(mma_gemm<1, 0>, cudaFuncAttributeMaxDynamicSharedMemorySize, MMA_SMEM_BYTES);
    cudaFuncSetAttribute(mma_gemm<1, 1>, cudaFuncAttributeMaxDynamicSharedMemorySize, MMA_SMEM_BYTES);

    const int MT = (NN + 127) / 128;     // 391
    dim3 grid_c(CC / 128, MT);           // N=256
    dim3 grid_f(FF / 128, MT);           // N=512

    zero_kernel<<<(NN * CC + 255) / 256, 256>>>();

    mma_gemm<0, 0><<<grid_c, 256, MMA_SMEM_BYTES>>>(x, Wq, nullptr, pQ, NN, CC, CC);
    mma_gemm<0, 0><<<grid_c, 256, MMA_SMEM_BYTES>>>(x, Wk, nullptr, pK, NN, CC, CC);
    mma_gemm<0, 0><<<grid_c, 256, MMA_SMEM_BYTES>>>(x, Wv, nullptr, pV, NN, CC, CC);

    edge_score_kernel<<<(EE * 32 + 255) / 256, 256>>>(ei);
    edge_exp_kernel<<<(EE * HH + 255) / 256, 256>>>(ei);
    edge_msg_kernel<<<(EE * 32 + 255) / 256, 256>>>(ei);

    mma_gemm<1, 0><<<grid_c, 256, MMA_SMEM_BYTES>>>(pAgg, Wo_w, Wo_b, pTmp, NN, CC, CC);
    ln_kernel<<<NN / 4, 256>>>(pTmp, x, ln1_g, ln1_b, pH1);
    mma_gemm<1, 1><<<grid_f, 256, MMA_SMEM_BYTES>>>(pH1, ffn_w1, ffn_b1, pTmp, NN, FF, CC);
    mma_gemm<1, 0><<<grid_c, 256, MMA_SMEM_BYTES>>>(pTmp, ffn_w2, ffn_b2, pAgg, NN, CC, FF);
    ln_kernel<<<NN / 4, 256>>>(pAgg, pH1, ln2_g, ln2_b, out);
}

// round 5
// speedup vs baseline: 1.7849x; 1.3352x over previous
#include <cuda_runtime.h>
#include <cuda_bf16.h>
#include <cstdint>

#define NN 50000
#define EE 800000
#define CC 256
#define HH 8
#define DD 32
#define FF 512
#define SCALE 0.17677669529663689f

#define W_QKV 0
#define W_WO  196608
#define W_F1  262144
#define W_F2  393216
#define W_TOT 524288

// ---------------- scratch ----------------
__device__ float g_QKV[(size_t)NN * 768];     // fused Q|K|V fp32
__device__ float g_score[(size_t)EE * HH];
__device__ float g_max[(size_t)NN * HH];
__device__ float g_sum[(size_t)NN * HH];
__device__ float g_agg[(size_t)NN * CC];      // attn agg; later ffn2 out
__device__ float g_wo[(size_t)NN * CC];       // Wo out
__device__ float g_h1[(size_t)NN * CC];       // ln1 out fp32
__device__ __nv_bfloat16 g_Xh[(size_t)NN * CC],  g_Xl[(size_t)NN * CC];
__device__ __nv_bfloat16 g_Ah[(size_t)NN * CC],  g_Al[(size_t)NN * CC];   // agg split
__device__ __nv_bfloat16 g_Hh[(size_t)NN * CC],  g_Hl[(size_t)NN * CC];   // h1 split
__device__ __nv_bfloat16 g_Th[(size_t)NN * FF],  g_Tl[(size_t)NN * FF];   // ffn hidden split
__device__ __nv_bfloat16 g_Wh[W_TOT], g_Wl[W_TOT];                        // weights split, k-major

// ---------------- helpers ----------------
__device__ __forceinline__ uint32_t smem_u32(const void* p) {
    uint32_t a;
    asm("{ .reg .u64 t; cvta.to.shared.u64 t, %1; cvt.u32.u64 %0, t; }" : "=r"(a) : "l"(p));
    return a;
}
#define SWZ(off) ((off) ^ (((off) >> 3) & 0x70))

__device__ __forceinline__ void ldm_x4(uint32_t* r, uint32_t addr) {
    asm volatile("ldmatrix.sync.aligned.m8n8.x4.shared.b16 {%0,%1,%2,%3}, [%4];"
        : "=r"(r[0]), "=r"(r[1]), "=r"(r[2]), "=r"(r[3]) : "r"(addr));
}
__device__ __forceinline__ void mma_bf16(float* d, const uint32_t* a, const uint32_t* b) {
    asm volatile("mma.sync.aligned.m16n8k16.row.col.f32.bf16.bf16.f32 "
        "{%0,%1,%2,%3}, {%4,%5,%6,%7}, {%8,%9}, {%0,%1,%2,%3};"
        : "+f"(d[0]), "+f"(d[1]), "+f"(d[2]), "+f"(d[3])
        : "r"(a[0]), "r"(a[1]), "r"(a[2]), "r"(a[3]), "r"(b[0]), "r"(b[1]));
}
__device__ __forceinline__ void split2(float x, float y, uint32_t& hi, uint32_t& lo) {
    __nv_bfloat162 h = __float22bfloat162_rn(make_float2(x, y));
    float2 hf = __bfloat1622float2(h);
    __nv_bfloat162 l = __float22bfloat162_rn(make_float2(x - hf.x, y - hf.y));
    hi = *(uint32_t*)&h;
    lo = *(uint32_t*)&l;
}
__device__ __forceinline__ void cpa16(uint32_t dst, const void* src, uint32_t sz) {
    asm volatile("cp.async.cg.shared.global [%0], [%1], 16, %2;"
        :: "r"(dst), "l"(src), "r"(sz) : "memory");
}
#define CP_COMMIT() asm volatile("cp.async.commit_group;" ::: "memory")
#define CP_WAIT1()  asm volatile("cp.async.wait_group 1;" ::: "memory")

// ---------------- weight prep: transpose+split into k-major bf16 ----------------
__global__ void prep_weights(const float* __restrict__ Wq, const float* __restrict__ Wk,
                             const float* __restrict__ Wv, const float* __restrict__ Wo,
                             const float* __restrict__ F1, const float* __restrict__ F2)
{
    int idx = blockIdx.x * 256 + threadIdx.x;
    if (idx >= W_TOT) return;
    float w;
    if (idx < W_WO) {                       // QKV fused: [n<768][k<256]
        int n = idx >> 8, k = idx & 255;
        if (n < 256)      w = Wq[k * 256 + n];
        else if (n < 512) w = Wk[k * 256 + (n - 256)];
        else              w = Wv[k * 256 + (n - 512)];
    } else if (idx < W_F1) {                // Wo: [n<256][k<256]
        int l = idx - W_WO;
        int n = l >> 8, k = l & 255;
        w = Wo[k * 256 + n];
    } else if (idx < W_F2) {                // ffn1: [n<512][k<256]
        int l = idx - W_F1;
        int n = l >> 8, k = l & 255;
        w = F1[k * 512 + n];
    } else {                                // ffn2: [n<256][k<512]
        int l = idx - W_F2;
        int n = l >> 9, k = l & 511;
        w = F2[k * 256 + n];
    }
    __nv_bfloat16 h = __float2bfloat16(w);
    g_Wh[idx] = h;
    g_Wl[idx] = __float2bfloat16(w - __bfloat162float(h));
}

// ---------------- fp32 -> bf16 hi/lo split (vectorized) ----------------
__global__ void conv_split(const float* __restrict__ in, __nv_bfloat16* __restrict__ oh,
                           __nv_bfloat16* __restrict__ ol, int n4)
{
    int i = blockIdx.x * 256 + threadIdx.x;
    if (i >= n4) return;
    float4 v = ((const float4*)in)[i];
    uint32_t h0, l0, h1, l1;
    split2(v.x, v.y, h0, l0);
    split2(v.z, v.w, h1, l1);
    ((uint2*)oh)[i] = make_uint2(h0, h1);
    ((uint2*)ol)[i] = make_uint2(l0, l1);
}

// ---------------- pipelined bf16-split GEMM via mma.sync + cp.async ----------------
// C[M,N] = (Ah+Al)[M,K] @ (Bh+Bl)^T[N,K]  (B stored k-major per n-row)
// CTA 128x128, BK=64, 2-stage cp.async double buffer. 8 warps 2(M)x4(N).
#define GEMM_SMEM (2 * 65536)

template<int BIAS, int GELU, int OSPLIT>
__global__ __launch_bounds__(256) void mma_gemm(
    const __nv_bfloat16* __restrict__ Agh, const __nv_bfloat16* __restrict__ Agl,
    const __nv_bfloat16* __restrict__ Bgh, const __nv_bfloat16* __restrict__ Bgl,
    const float* __restrict__ bias, float* __restrict__ C,
    __nv_bfloat16* __restrict__ Ch, __nv_bfloat16* __restrict__ Cl,
    int M, int N, int K)
{
    extern __shared__ char smem[];
    uint32_t sb = smem_u32(smem);
    int tid = threadIdx.x, wid = tid >> 5, lane = tid & 31;
    int row0 = blockIdx.y * 128;
    int col0 = blockIdx.x * 128;
    int Am0 = (wid >> 2) * 64;
    int Bn0 = (wid & 3) * 32;

    uint32_t arow[4], brow[2];
#pragma unroll
    for (int mt = 0; mt < 4; mt++)
        arow[mt] = (uint32_t)((Am0 + mt * 16 + (lane & 15)) * 128 + (lane >> 4) * 16);
#pragma unroll
    for (int ntp = 0; ntp < 2; ntp++)
        brow[ntp] = (uint32_t)((Bn0 + ntp * 16 + (lane >> 4) * 8 + (lane & 7)) * 128
                               + ((lane >> 3) & 1) * 16);

    float d[4][4][4];
#pragma unroll
    for (int i = 0; i < 4; i++)
#pragma unroll
        for (int j = 0; j < 4; j++)
#pragma unroll
            for (int e = 0; e < 4; e++) d[i][j][e] = 0.f;

    // stage loader: 4 arrays x 4 chunks per thread = 16 cp.async
    auto load_stage = [&](int st, int kt) {
        uint32_t base = sb + st * 65536;
#pragma unroll
        for (int j = 0; j < 4; j++) {
            int id = tid + 256 * j;
            int r = id >> 3, c = id & 7;
            uint32_t off = SWZ((uint32_t)(r * 128 + c * 16));
            int gr = row0 + r;
            uint32_t sz = (gr < M) ? 16u : 0u;
            int grc = (gr < M) ? gr : (M - 1);
            const __nv_bfloat16* pa = Agh + (size_t)grc * K + kt + c * 8;
            const __nv_bfloat16* pal = Agl + (size_t)grc * K + kt + c * 8;
            cpa16(base + off, pa, sz);
            cpa16(base + 16384 + off, pal, sz);
            int gn = col0 + r;
            const __nv_bfloat16* pb = Bgh + (size_t)gn * K + kt + c * 8;
            const __nv_bfloat16* pbl = Bgl + (size_t)gn * K + kt + c * 8;
            cpa16(base + 32768 + off, pb, 16u);
            cpa16(base + 49152 + off, pbl, 16u);
        }
    };

    load_stage(0, 0);
    CP_COMMIT();

    const int nIter = K >> 6;
    for (int it = 0; it < nIter; ++it) {
        if (it + 1 < nIter) load_stage((it + 1) & 1, (it + 1) << 6);
        CP_COMMIT();
        CP_WAIT1();
        __syncthreads();

        uint32_t sAh = sb + (it & 1) * 65536;
        uint32_t sAl = sAh + 16384, sBh = sAh + 32768, sBl = sAh + 49152;
#pragma unroll
        for (int ks = 0; ks < 4; ks++) {
            uint32_t aH[4][4], aL[4][4], bH[4][2], bL[4][2];
#pragma unroll
            for (int mt = 0; mt < 4; mt++) {
                ldm_x4(aH[mt], sAh + SWZ(arow[mt] + ks * 32));
                ldm_x4(aL[mt], sAl + SWZ(arow[mt] + ks * 32));
            }
#pragma unroll
            for (int ntp = 0; ntp < 2; ntp++) {
                ldm_x4(&bH[ntp * 2][0], sBh + SWZ(brow[ntp] + ks * 32));
                ldm_x4(&bL[ntp * 2][0], sBl + SWZ(brow[ntp] + ks * 32));
            }
#pragma unroll
            for (int mt = 0; mt < 4; mt++)
#pragma unroll
                for (int nt = 0; nt < 4; nt++) {
                    mma_bf16(d[mt][nt], aH[mt], bH[nt]);
                    mma_bf16(d[mt][nt], aH[mt], bL[nt]);
                    mma_bf16(d[mt][nt], aL[mt], bH[nt]);
                }
        }
        __syncthreads();
    }

    // ---- epilogue ----
#pragma unroll
    for (int nt = 0; nt < 4; nt++) {
        int c = col0 + Bn0 + nt * 8 + (lane & 3) * 2;
        float b0 = 0.f, b1 = 0.f;
        if (BIAS) { b0 = bias[c]; b1 = bias[c + 1]; }
#pragma unroll
        for (int mt = 0; mt < 4; mt++) {
            int r0 = row0 + Am0 + mt * 16 + (lane >> 2);
#pragma unroll
            for (int half = 0; half < 2; half++) {
                int r = r0 + half * 8;
                if (r < M) {
                    float v0 = d[mt][nt][half * 2 + 0] + b0;
                    float v1 = d[mt][nt][half * 2 + 1] + b1;
                    if (GELU) {
                        v0 = 0.5f * v0 * (1.f + erff(v0 * 0.70710678118654752f));
                        v1 = 0.5f * v1 * (1.f + erff(v1 * 0.70710678118654752f));
                    }
                    if (OSPLIT) {
                        uint32_t h, l;
                        split2(v0, v1, h, l);
                        *(uint32_t*)(Ch + (size_t)r * N + c) = h;
                        *(uint32_t*)(Cl + (size_t)r * N + c) = l;
                    } else {
                        *(float2*)(C + (size_t)r * N + c) = make_float2(v0, v1);
                    }
                }
            }
        }
    }
}

// ---------------- zero init ----------------
__global__ void zero_kernel() {
    int idx = blockIdx.x * blockDim.x + threadIdx.x;
    if (idx < NN * CC) g_agg[idx] = 0.f;
    if (idx < NN * HH) { g_max[idx] = 0.f; g_sum[idx] = 0.f; }
}

// ---------------- edge scores + segmented max ----------------
__global__ __launch_bounds__(256) void edge_score_kernel(const int* __restrict__ ei)
{
    int warp = (blockIdx.x * 256 + threadIdx.x) >> 5;
    if (warp >= EE) return;
    int lane = threadIdx.x & 31;
    int h = lane >> 2, sub = lane & 3;
    int src = ei[warp];
    int dst = ei[EE + warp];
    const float4* q = (const float4*)(g_QKV + (size_t)dst * 768 + h * DD + sub * 8);
    const float4* k = (const float4*)(g_QKV + (size_t)src * 768 + 256 + h * DD + sub * 8);
    float4 q0 = q[0], q1 = q[1];
    float4 k0 = k[0], k1 = k[1];
    float dot = q0.x * k0.x + q0.y * k0.y + q0.z * k0.z + q0.w * k0.w
              + q1.x * k1.x + q1.y * k1.y + q1.z * k1.z + q1.w * k1.w;
    dot += __shfl_xor_sync(0xffffffffu, dot, 1);
    dot += __shfl_xor_sync(0xffffffffu, dot, 2);
    if (sub == 0) {
        float s = dot * SCALE;
        g_score[(size_t)warp * HH + h] = s;
        if (s > 0.f)
            atomicMax((int*)&g_max[(size_t)dst * HH + h], __float_as_int(s));
    }
}

// ---------------- w = exp(s - max[dst]); segmented sum ----------------
__global__ __launch_bounds__(256) void edge_exp_kernel(const int* __restrict__ ei)
{
    int idx = blockIdx.x * 256 + threadIdx.x;
    if (idx >= EE * HH) return;
    int e = idx >> 3, h = idx & 7;
    int dst = ei[EE + e];
    float s = g_score[idx];
    float m = g_max[(size_t)dst * HH + h];
    float w = expf(s - m);
    g_score[idx] = w;
    atomicAdd(&g_sum[(size_t)dst * HH + h], w);
}

// ---------------- message passing ----------------
__global__ __launch_bounds__(256) void edge_msg_kernel(const int* __restrict__ ei)
{
    int warp = (blockIdx.x * 256 + threadIdx.x) >> 5;
    if (warp >= EE) return;
    int lane = threadIdx.x & 31;
    int h = lane >> 2, sub = lane & 3;
    int src = ei[warp];
    int dst = ei[EE + warp];
    float w = g_score[(size_t)warp * HH + h];
    float s = g_sum[(size_t)dst * HH + h];
    float coef = w / (s + 1e-8f);
    const float4* vp = (const float4*)(g_QKV + (size_t)src * 768 + 512 + h * DD + sub * 8);
    float4 v0 = vp[0], v1 = vp[1];
    float* op = g_agg + (size_t)dst * CC + h * DD + sub * 8;
    asm volatile("red.global.add.v4.f32 [%0], {%1,%2,%3,%4};" ::
                 "l"(op), "f"(v0.x * coef), "f"(v0.y * coef),
                 "f"(v0.z * coef), "f"(v0.w * coef) : "memory");
    asm volatile("red.global.add.v4.f32 [%0], {%1,%2,%3,%4};" ::
                 "l"(op + 4), "f"(v1.x * coef), "f"(v1.y * coef),
                 "f"(v1.z * coef), "f"(v1.w * coef) : "memory");
}

// ---------------- layernorm (+ optional bf16 split output) ----------------
template<int SPLIT>
__global__ __launch_bounds__(256) void ln_kernel(
    const float* __restrict__ a, const float* __restrict__ b,
    const float* __restrict__ g, const float* __restrict__ bb,
    float* __restrict__ out, __nv_bfloat16* __restrict__ oh,
    __nv_bfloat16* __restrict__ ol)
{
    __shared__ float red[8][2];
    int r = threadIdx.x >> 6;
    int t = threadIdx.x & 63;
    size_t row = (size_t)blockIdx.x * 4 + r;
    float4 va = ((const float4*)(a + row * CC))[t];
    float4 vb = ((const float4*)(b + row * CC))[t];
    float4 v = make_float4(va.x + vb.x, va.y + vb.y, va.z + vb.z, va.w + vb.w);
    float s = v.x + v.y + v.z + v.w;
    float q = v.x * v.x + v.y * v.y + v.z * v.z + v.w * v.w;
#pragma unroll
    for (int o = 16; o; o >>= 1) {
        s += __shfl_xor_sync(0xffffffffu, s, o);
        q += __shfl_xor_sync(0xffffffffu, q, o);
    }
    int wid = threadIdx.x >> 5;
    if ((threadIdx.x & 31) == 0) { red[wid][0] = s; red[wid][1] = q; }
    __syncthreads();
    int wp = r * 2;
    s = red[wp][0] + red[wp + 1][0];
    q = red[wp][1] + red[wp + 1][1];
    float mu = s * (1.f / 256.f);
    float var = q * (1.f / 256.f) - mu * mu;
    float rs = rsqrtf(var + 1e-5f);
    float4 gg = ((const float4*)g)[t];
    float4 bv = ((const float4*)bb)[t];
    float4 o;
    o.x = (v.x - mu) * rs * gg.x + bv.x;
    o.y = (v.y - mu) * rs * gg.y + bv.y;
    o.z = (v.z - mu) * rs * gg.z + bv.z;
    o.w = (v.w - mu) * rs * gg.w + bv.w;
    ((float4*)(out + row * CC))[t] = o;
    if (SPLIT) {
        uint32_t h0, l0, h1, l1;
        split2(o.x, o.y, h0, l0);
        split2(o.z, o.w, h1, l1);
        ((uint2*)(oh + row * CC))[t] = make_uint2(h0, h1);
        ((uint2*)(ol + row * CC))[t] = make_uint2(l0, l1);
    }
}

// ---------------- launch ----------------
extern "C" void kernel_launch(void* const* d_in, const int* in_sizes, int n_in,
                              void* d_out, int out_size)
{
    const float* x      = (const float*)d_in[0];
    const int*   ei     = (const int*)d_in[1];
    const float* Wq     = (const float*)d_in[3];
    const float* Wk     = (const float*)d_in[4];
    const float* Wv     = (const float*)d_in[5];
    const float* Wo_w   = (const float*)d_in[6];
    const float* Wo_b   = (const float*)d_in[7];
    const float* ln1_g  = (const float*)d_in[8];
    const float* ln1_b  = (const float*)d_in[9];
    const float* ln2_g  = (const float*)d_in[10];
    const float* ln2_b  = (const float*)d_in[11];
    const float* ffn_w1 = (const float*)d_in[12];
    const float* ffn_b1 = (const float*)d_in[13];
    const float* ffn_w2 = (const float*)d_in[14];
    const float* ffn_b2 = (const float*)d_in[15];
    float* out = (float*)d_out;

    float *pQKV, *pAgg, *pWo, *pH1;
    __nv_bfloat16 *pXh, *pXl, *pAh, *pAl, *pHh, *pHl, *pTh, *pTl, *pWth, *pWtl;
    cudaGetSymbolAddress((void**)&pQKV, g_QKV);
    cudaGetSymbolAddress((void**)&pAgg, g_agg);
    cudaGetSymbolAddress((void**)&pWo,  g_wo);
    cudaGetSymbolAddress((void**)&pH1,  g_h1);
    cudaGetSymbolAddress((void**)&pXh,  g_Xh);
    cudaGetSymbolAddress((void**)&pXl,  g_Xl);
    cudaGetSymbolAddress((void**)&pAh,  g_Ah);
    cudaGetSymbolAddress((void**)&pAl,  g_Al);
    cudaGetSymbolAddress((void**)&pHh,  g_Hh);
    cudaGetSymbolAddress((void**)&pHl,  g_Hl);
    cudaGetSymbolAddress((void**)&pTh,  g_Th);
    cudaGetSymbolAddress((void**)&pTl,  g_Tl);
    cudaGetSymbolAddress((void**)&pWth, g_Wh);
    cudaGetSymbolAddress((void**)&pWtl, g_Wl);

    cudaFuncSetAttribute(mma_gemm<0, 0, 0>, cudaFuncAttributeMaxDynamicSharedMemorySize, GEMM_SMEM);
    cudaFuncSetAttribute(mma_gemm<1, 0, 0>, cudaFuncAttributeMaxDynamicSharedMemorySize, GEMM_SMEM);
    cudaFuncSetAttribute(mma_gemm<1, 1, 1>, cudaFuncAttributeMaxDynamicSharedMemorySize, GEMM_SMEM);

    const int MT = (NN + 127) / 128;     // 391

    // prep
    zero_kernel<<<(NN * CC + 255) / 256, 256>>>();
    prep_weights<<<(W_TOT + 255) / 256, 256>>>(Wq, Wk, Wv, Wo_w, ffn_w1, ffn_w2);
    conv_split<<<(NN * CC / 4 + 255) / 256, 256>>>(x, pXh, pXl, NN * CC / 4);

    // fused QKV: [NN,768] = X @ Wqkv
    mma_gemm<0, 0, 0><<<dim3(6, MT), 256, GEMM_SMEM>>>(
        pXh, pXl, pWth + W_QKV, pWtl + W_QKV, nullptr, pQKV, nullptr, nullptr, NN, 768, CC);

    edge_score_kernel<<<(EE * 32 + 255) / 256, 256>>>(ei);
    edge_exp_kernel<<<(EE * HH + 255) / 256, 256>>>(ei);
    edge_msg_kernel<<<(EE * 32 + 255) / 256, 256>>>(ei);

    conv_split<<<(NN * CC / 4 + 255) / 256, 256>>>(pAgg, pAh, pAl, NN * CC / 4);
    // Wo projection
    mma_gemm<1, 0, 0><<<dim3(2, MT), 256, GEMM_SMEM>>>(
        pAh, pAl, pWth + W_WO, pWtl + W_WO, Wo_b, pWo, nullptr, nullptr, NN, CC, CC);
    // LN1 -> h1 (fp32 + split)
    ln_kernel<1><<<NN / 4, 256>>>(pWo, x, ln1_g, ln1_b, pH1, pHh, pHl);
    // FFN1 + GELU -> hidden split
    mma_gemm<1, 1, 1><<<dim3(4, MT), 256, GEMM_SMEM>>>(
        pHh, pHl, pWth + W_F1, pWtl + W_F1, ffn_b1, nullptr, pTh, pTl, NN, FF, CC);
    // FFN2 -> agg (reuse)
    mma_gemm<1, 0, 0><<<dim3(2, MT), 256, GEMM_SMEM>>>(
        pTh, pTl, pWth + W_F2, pWtl + W_F2, ffn_b2, pAgg, nullptr, nullptr, NN, CC, FF);
    // LN2 -> out
    ln_kernel<0><<<NN / 4, 256>>>(pAgg, pH1, ln2_g, ln2_b, out, nullptr, nullptr);
}

// round 6
// speedup vs baseline: 2.2045x; 1.2351x over previous
#include <cuda_runtime.h>
#include <cuda_bf16.h>
#include <cstdint>

#define NN 50000
#define EE 800000
#define CC 256
#define HH 8
#define DD 32
#define FF 512
#define SCALE 0.17677669529663689f
#define CAP 96

#define W_QKV 0
#define W_WO  196608
#define W_F1  262144
#define W_F2  393216
#define W_TOT 524288

// ---------------- scratch ----------------
__device__ float g_QKV[(size_t)NN * 768];     // fused Q|K|V fp32
__device__ float g_agg[(size_t)NN * CC];      // ffn2 out
__device__ float g_wo[(size_t)NN * CC];       // Wo out
__device__ float g_h1[(size_t)NN * CC];       // ln1 out fp32
__device__ __nv_bfloat16 g_Xh[(size_t)NN * CC],  g_Xl[(size_t)NN * CC];
__device__ __nv_bfloat16 g_Ah[(size_t)NN * CC],  g_Al[(size_t)NN * CC];   // attn agg split
__device__ __nv_bfloat16 g_Hh[(size_t)NN * CC],  g_Hl[(size_t)NN * CC];   // h1 split
__device__ __nv_bfloat16 g_Th[(size_t)NN * FF],  g_Tl[(size_t)NN * FF];   // ffn hidden split
__device__ __nv_bfloat16 g_Wh[W_TOT], g_Wl[W_TOT];                        // weights split, k-major
__device__ int g_cnt[NN], g_ofs[NN], g_cur[NN];
__device__ int g_ss[EE];                      // src sorted by dst

// ---------------- helpers ----------------
__device__ __forceinline__ uint32_t smem_u32(const void* p) {
    uint32_t a;
    asm("{ .reg .u64 t; cvta.to.shared.u64 t, %1; cvt.u32.u64 %0, t; }" : "=r"(a) : "l"(p));
    return a;
}
#define SWZ(off) ((off) ^ (((off) >> 3) & 0x70))

__device__ __forceinline__ void ldm_x4(uint32_t* r, uint32_t addr) {
    asm volatile("ldmatrix.sync.aligned.m8n8.x4.shared.b16 {%0,%1,%2,%3}, [%4];"
        : "=r"(r[0]), "=r"(r[1]), "=r"(r[2]), "=r"(r[3]) : "r"(addr));
}
__device__ __forceinline__ void mma_bf16(float* d, const uint32_t* a, const uint32_t* b) {
    asm volatile("mma.sync.aligned.m16n8k16.row.col.f32.bf16.bf16.f32 "
        "{%0,%1,%2,%3}, {%4,%5,%6,%7}, {%8,%9}, {%0,%1,%2,%3};"
        : "+f"(d[0]), "+f"(d[1]), "+f"(d[2]), "+f"(d[3])
        : "r"(a[0]), "r"(a[1]), "r"(a[2]), "r"(a[3]), "r"(b[0]), "r"(b[1]));
}
__device__ __forceinline__ void split2(float x, float y, uint32_t& hi, uint32_t& lo) {
    __nv_bfloat162 h = __float22bfloat162_rn(make_float2(x, y));
    float2 hf = __bfloat1622float2(h);
    __nv_bfloat162 l = __float22bfloat162_rn(make_float2(x - hf.x, y - hf.y));
    hi = *(uint32_t*)&h;
    lo = *(uint32_t*)&l;
}
__device__ __forceinline__ void cpa16(uint32_t dst, const void* src, uint32_t sz) {
    asm volatile("cp.async.cg.shared.global [%0], [%1], 16, %2;"
        :: "r"(dst), "l"(src), "r"(sz) : "memory");
}
#define CP_COMMIT() asm volatile("cp.async.commit_group;" ::: "memory")
#define CP_WAIT1()  asm volatile("cp.async.wait_group 1;" ::: "memory")

// ---------------- weight prep ----------------
__global__ void prep_weights(const float* __restrict__ Wq, const float* __restrict__ Wk,
                             const float* __restrict__ Wv, const float* __restrict__ Wo,
                             const float* __restrict__ F1, const float* __restrict__ F2)
{
    int idx = blockIdx.x * 256 + threadIdx.x;
    if (idx >= W_TOT) return;
    float w;
    if (idx < W_WO) {
        int n = idx >> 8, k = idx & 255;
        if (n < 256)      w = Wq[k * 256 + n];
        else if (n < 512) w = Wk[k * 256 + (n - 256)];
        else              w = Wv[k * 256 + (n - 512)];
    } else if (idx < W_F1) {
        int l = idx - W_WO;
        int n = l >> 8, k = l & 255;
        w = Wo[k * 256 + n];
    } else if (idx < W_F2) {
        int l = idx - W_F1;
        int n = l >> 8, k = l & 255;
        w = F1[k * 512 + n];
    } else {
        int l = idx - W_F2;
        int n = l >> 9, k = l & 511;
        w = F2[k * 256 + n];
    }
    __nv_bfloat16 h = __float2bfloat16(w);
    g_Wh[idx] = h;
    g_Wl[idx] = __float2bfloat16(w - __bfloat162float(h));
}

// ---------------- fp32 -> bf16 hi/lo split ----------------
__global__ void conv_split(const float* __restrict__ in, __nv_bfloat16* __restrict__ oh,
                           __nv_bfloat16* __restrict__ ol, int n4)
{
    int i = blockIdx.x * 256 + threadIdx.x;
    if (i >= n4) return;
    float4 v = ((const float4*)in)[i];
    uint32_t h0, l0, h1, l1;
    split2(v.x, v.y, h0, l0);
    split2(v.z, v.w, h1, l1);
    ((uint2*)oh)[i] = make_uint2(h0, h1);
    ((uint2*)ol)[i] = make_uint2(l0, l1);
}

// ---------------- pipelined bf16-split GEMM (unchanged from R5) ----------------
#define GEMM_SMEM (2 * 65536)

template<int BIAS, int GELU, int OSPLIT>
__global__ __launch_bounds__(256) void mma_gemm(
    const __nv_bfloat16* __restrict__ Agh, const __nv_bfloat16* __restrict__ Agl,
    const __nv_bfloat16* __restrict__ Bgh, const __nv_bfloat16* __restrict__ Bgl,
    const float* __restrict__ bias, float* __restrict__ C,
    __nv_bfloat16* __restrict__ Ch, __nv_bfloat16* __restrict__ Cl,
    int M, int N, int K)
{
    extern __shared__ char smem[];
    uint32_t sb = smem_u32(smem);
    int tid = threadIdx.x, wid = tid >> 5, lane = tid & 31;
    int row0 = blockIdx.y * 128;
    int col0 = blockIdx.x * 128;
    int Am0 = (wid >> 2) * 64;
    int Bn0 = (wid & 3) * 32;

    uint32_t arow[4], brow[2];
#pragma unroll
    for (int mt = 0; mt < 4; mt++)
        arow[mt] = (uint32_t)((Am0 + mt * 16 + (lane & 15)) * 128 + (lane >> 4) * 16);
#pragma unroll
    for (int ntp = 0; ntp < 2; ntp++)
        brow[ntp] = (uint32_t)((Bn0 + ntp * 16 + (lane >> 4) * 8 + (lane & 7)) * 128
                               + ((lane >> 3) & 1) * 16);

    float d[4][4][4];
#pragma unroll
    for (int i = 0; i < 4; i++)
#pragma unroll
        for (int j = 0; j < 4; j++)
#pragma unroll
            for (int e = 0; e < 4; e++) d[i][j][e] = 0.f;

    auto load_stage = [&](int st, int kt) {
        uint32_t base = sb + st * 65536;
#pragma unroll
        for (int j = 0; j < 4; j++) {
            int id = tid + 256 * j;
            int r = id >> 3, c = id & 7;
            uint32_t off = SWZ((uint32_t)(r * 128 + c * 16));
            int gr = row0 + r;
            uint32_t sz = (gr < M) ? 16u : 0u;
            int grc = (gr < M) ? gr : (M - 1);
            cpa16(base + off, Agh + (size_t)grc * K + kt + c * 8, sz);
            cpa16(base + 16384 + off, Agl + (size_t)grc * K + kt + c * 8, sz);
            int gn = col0 + r;
            cpa16(base + 32768 + off, Bgh + (size_t)gn * K + kt + c * 8, 16u);
            cpa16(base + 49152 + off, Bgl + (size_t)gn * K + kt + c * 8, 16u);
        }
    };

    load_stage(0, 0);
    CP_COMMIT();

    const int nIter = K >> 6;
    for (int it = 0; it < nIter; ++it) {
        if (it + 1 < nIter) load_stage((it + 1) & 1, (it + 1) << 6);
        CP_COMMIT();
        CP_WAIT1();
        __syncthreads();

        uint32_t sAh = sb + (it & 1) * 65536;
        uint32_t sAl = sAh + 16384, sBh = sAh + 32768, sBl = sAh + 49152;
#pragma unroll
        for (int ks = 0; ks < 4; ks++) {
            uint32_t aH[4][4], aL[4][4], bH[4][2], bL[4][2];
#pragma unroll
            for (int mt = 0; mt < 4; mt++) {
                ldm_x4(aH[mt], sAh + SWZ(arow[mt] + ks * 32));
                ldm_x4(aL[mt], sAl + SWZ(arow[mt] + ks * 32));
            }
#pragma unroll
            for (int ntp = 0; ntp < 2; ntp++) {
                ldm_x4(&bH[ntp * 2][0], sBh + SWZ(brow[ntp] + ks * 32));
                ldm_x4(&bL[ntp * 2][0], sBl + SWZ(brow[ntp] + ks * 32));
            }
#pragma unroll
            for (int mt = 0; mt < 4; mt++)
#pragma unroll
                for (int nt = 0; nt < 4; nt++) {
                    mma_bf16(d[mt][nt], aH[mt], bH[nt]);
                    mma_bf16(d[mt][nt], aH[mt], bL[nt]);
                    mma_bf16(d[mt][nt], aL[mt], bH[nt]);
                }
        }
        __syncthreads();
    }

#pragma unroll
    for (int nt = 0; nt < 4; nt++) {
        int c = col0 + Bn0 + nt * 8 + (lane & 3) * 2;
        float b0 = 0.f, b1 = 0.f;
        if (BIAS) { b0 = bias[c]; b1 = bias[c + 1]; }
#pragma unroll
        for (int mt = 0; mt < 4; mt++) {
            int r0 = row0 + Am0 + mt * 16 + (lane >> 2);
#pragma unroll
            for (int half = 0; half < 2; half++) {
                int r = r0 + half * 8;
                if (r < M) {
                    float v0 = d[mt][nt][half * 2 + 0] + b0;
                    float v1 = d[mt][nt][half * 2 + 1] + b1;
                    if (GELU) {
                        v0 = 0.5f * v0 * (1.f + erff(v0 * 0.70710678118654752f));
                        v1 = 0.5f * v1 * (1.f + erff(v1 * 0.70710678118654752f));
                    }
                    if (OSPLIT) {
                        uint32_t h, l;
                        split2(v0, v1, h, l);
                        *(uint32_t*)(Ch + (size_t)r * N + c) = h;
                        *(uint32_t*)(Cl + (size_t)r * N + c) = l;
                    } else {
                        *(float2*)(C + (size_t)r * N + c) = make_float2(v0, v1);
                    }
                }
            }
        }
    }
}

// ---------------- CSR sort: hist -> scan -> scatter ----------------
__global__ void zero_cnt() {
    int i = blockIdx.x * 256 + threadIdx.x;
    if (i < NN) g_cnt[i] = 0;
}
__global__ void hist_kernel(const int* __restrict__ ei) {
    int e = blockIdx.x * 256 + threadIdx.x;
    if (e < EE) atomicAdd(&g_cnt[ei[EE + e]], 1);
}
__global__ __launch_bounds__(1024) void scan_kernel() {
    __shared__ int part[1024];
    const int CH = 49;                         // 1024*49 >= 50000
    int t = threadIdx.x;
    int base = t * CH;
    int s = 0;
    for (int j = 0; j < CH; j++) {
        int i = base + j;
        if (i < NN) s += g_cnt[i];
    }
    part[t] = s;
    __syncthreads();
    for (int off = 1; off < 1024; off <<= 1) {
        int v = (t >= off) ? part[t - off] : 0;
        __syncthreads();
        part[t] += v;
        __syncthreads();
    }
    int run = (t == 0) ? 0 : part[t - 1];
    for (int j = 0; j < CH; j++) {
        int i = base + j;
        if (i < NN) {
            g_ofs[i] = run;
            g_cur[i] = run;
            run += g_cnt[i];
        }
    }
}
__global__ void scatter_kernel(const int* __restrict__ ei) {
    int e = blockIdx.x * 256 + threadIdx.x;
    if (e >= EE) return;
    int dst = ei[EE + e];
    int pos = atomicAdd(&g_cur[dst], 1);
    g_ss[pos] = ei[e];
}

// ---------------- fused per-dst attention (softmax + aggregate) ----------------
// 1 warp = 1 dst. lane -> head h = lane>>2, sub = lane&3 (8 V-dims each).
// Two passes over the dst's edge list; scores cached in smem (cap CAP, fallback recompute).
__global__ __launch_bounds__(256) void attn_kernel(
    __nv_bfloat16* __restrict__ oh, __nv_bfloat16* __restrict__ ol)
{
    __shared__ float sc[8][CAP * 8];
    int tid = threadIdx.x;
    int w = tid >> 5, lane = tid & 31;
    int h = lane >> 2, sub = lane & 3;
    int dst = blockIdx.x * 8 + w;

    const float* qp = g_QKV + (size_t)dst * 768 + h * DD + sub * 8;
    float4 q0 = ((const float4*)qp)[0], q1 = ((const float4*)qp)[1];
    int beg = g_ofs[dst], cnt = g_cnt[dst];

    // ---- pass 1: scores + per-head max (init 0 = reference's zero-init clamp) ----
    float m = 0.f;
    for (int i = 0; i < cnt; i++) {
        int src = g_ss[beg + i];
        const float* kp = g_QKV + (size_t)src * 768 + 256 + h * DD + sub * 8;
        float4 k0 = ((const float4*)kp)[0], k1 = ((const float4*)kp)[1];
        float dot = q0.x * k0.x + q0.y * k0.y + q0.z * k0.z + q0.w * k0.w
                  + q1.x * k1.x + q1.y * k1.y + q1.z * k1.z + q1.w * k1.w;
        dot += __shfl_xor_sync(0xffffffffu, dot, 1);
        dot += __shfl_xor_sync(0xffffffffu, dot, 2);
        float s = dot * SCALE;
        m = fmaxf(m, s);
        if (sub == 0 && i < CAP) sc[w][i * 8 + h] = s;
    }
    __syncwarp();

    // ---- pass 2: w = exp(s-m), gather V, accumulate ----
    float sum = 0.f;
    float4 a0 = make_float4(0.f, 0.f, 0.f, 0.f);
    float4 a1 = make_float4(0.f, 0.f, 0.f, 0.f);
    for (int i = 0; i < cnt; i++) {
        int src = g_ss[beg + i];
        float s;
        if (i < CAP) {
            s = sc[w][i * 8 + h];
        } else {  // fallback (never triggers for Poisson(16) degrees; correctness net)
            const float* kp = g_QKV + (size_t)src * 768 + 256 + h * DD + sub * 8;
            float4 k0 = ((const float4*)kp)[0], k1 = ((const float4*)kp)[1];
            float dot = q0.x * k0.x + q0.y * k0.y + q0.z * k0.z + q0.w * k0.w
                      + q1.x * k1.x + q1.y * k1.y + q1.z * k1.z + q1.w * k1.w;
            dot += __shfl_xor_sync(0xffffffffu, dot, 1);
            dot += __shfl_xor_sync(0xffffffffu, dot, 2);
            s = dot * SCALE;
        }
        float wgt = __expf(s - m);
        sum += wgt;
        const float* vp = g_QKV + (size_t)src * 768 + 512 + h * DD + sub * 8;
        float4 v0 = ((const float4*)vp)[0], v1 = ((const float4*)vp)[1];
        a0.x += wgt * v0.x; a0.y += wgt * v0.y; a0.z += wgt * v0.z; a0.w += wgt * v0.w;
        a1.x += wgt * v1.x; a1.y += wgt * v1.y; a1.z += wgt * v1.z; a1.w += wgt * v1.w;
    }
    float inv = 1.f / (sum + 1e-8f);
    uint32_t h0, l0, h1, l1, h2, l2, h3, l3;
    split2(a0.x * inv, a0.y * inv, h0, l0);
    split2(a0.z * inv, a0.w * inv, h1, l1);
    split2(a1.x * inv, a1.y * inv, h2, l2);
    split2(a1.z * inv, a1.w * inv, h3, l3);
    size_t ob = (size_t)dst * CC + h * DD + sub * 8;
    *(uint4*)(oh + ob) = make_uint4(h0, h1, h2, h3);
    *(uint4*)(ol + ob) = make_uint4(l0, l1, l2, l3);
}

// ---------------- layernorm (+ optional bf16 split output) ----------------
template<int SPLIT>
__global__ __launch_bounds__(256) void ln_kernel(
    const float* __restrict__ a, const float* __restrict__ b,
    const float* __restrict__ g, const float* __restrict__ bb,
    float* __restrict__ out, __nv_bfloat16* __restrict__ oh,
    __nv_bfloat16* __restrict__ ol)
{
    __shared__ float red[8][2];
    int r = threadIdx.x >> 6;
    int t = threadIdx.x & 63;
    size_t row = (size_t)blockIdx.x * 4 + r;
    float4 va = ((const float4*)(a + row * CC))[t];
    float4 vb = ((const float4*)(b + row * CC))[t];
    float4 v = make_float4(va.x + vb.x, va.y + vb.y, va.z + vb.z, va.w + vb.w);
    float s = v.x + v.y + v.z + v.w;
    float q = v.x * v.x + v.y * v.y + v.z * v.z + v.w * v.w;
#pragma unroll
    for (int o = 16; o; o >>= 1) {
        s += __shfl_xor_sync(0xffffffffu, s, o);
        q += __shfl_xor_sync(0xffffffffu, q, o);
    }
    int wid = threadIdx.x >> 5;
    if ((threadIdx.x & 31) == 0) { red[wid][0] = s; red[wid][1] = q; }
    __syncthreads();
    int wp = r * 2;
    s = red[wp][0] + red[wp + 1][0];
    q = red[wp][1] + red[wp + 1][1];
    float mu = s * (1.f / 256.f);
    float var = q * (1.f / 256.f) - mu * mu;
    float rs = rsqrtf(var + 1e-5f);
    float4 gg = ((const float4*)g)[t];
    float4 bv = ((const float4*)bb)[t];
    float4 o;
    o.x = (v.x - mu) * rs * gg.x + bv.x;
    o.y = (v.y - mu) * rs * gg.y + bv.y;
    o.z = (v.z - mu) * rs * gg.z + bv.z;
    o.w = (v.w - mu) * rs * gg.w + bv.w;
    ((float4*)(out + row * CC))[t] = o;
    if (SPLIT) {
        uint32_t h0, l0, h1, l1;
        split2(o.x, o.y, h0, l0);
        split2(o.z, o.w, h1, l1);
        ((uint2*)(oh + row * CC))[t] = make_uint2(h0, h1);
        ((uint2*)(ol + row * CC))[t] = make_uint2(l0, l1);
    }
}

// ---------------- launch ----------------
extern "C" void kernel_launch(void* const* d_in, const int* in_sizes, int n_in,
                              void* d_out, int out_size)
{
    const float* x      = (const float*)d_in[0];
    const int*   ei     = (const int*)d_in[1];
    const float* Wq     = (const float*)d_in[3];
    const float* Wk     = (const float*)d_in[4];
    const float* Wv     = (const float*)d_in[5];
    const float* Wo_w   = (const float*)d_in[6];
    const float* Wo_b   = (const float*)d_in[7];
    const float* ln1_g  = (const float*)d_in[8];
    const float* ln1_b  = (const float*)d_in[9];
    const float* ln2_g  = (const float*)d_in[10];
    const float* ln2_b  = (const float*)d_in[11];
    const float* ffn_w1 = (const float*)d_in[12];
    const float* ffn_b1 = (const float*)d_in[13];
    const float* ffn_w2 = (const float*)d_in[14];
    const float* ffn_b2 = (const float*)d_in[15];
    float* out = (float*)d_out;

    float *pQKV, *pAgg, *pWo, *pH1;
    __nv_bfloat16 *pXh, *pXl, *pAh, *pAl, *pHh, *pHl, *pTh, *pTl, *pWth, *pWtl;
    cudaGetSymbolAddress((void**)&pQKV, g_QKV);
    cudaGetSymbolAddress((void**)&pAgg, g_agg);
    cudaGetSymbolAddress((void**)&pWo,  g_wo);
    cudaGetSymbolAddress((void**)&pH1,  g_h1);
    cudaGetSymbolAddress((void**)&pXh,  g_Xh);
    cudaGetSymbolAddress((void**)&pXl,  g_Xl);
    cudaGetSymbolAddress((void**)&pAh,  g_Ah);
    cudaGetSymbolAddress((void**)&pAl,  g_Al);
    cudaGetSymbolAddress((void**)&pHh,  g_Hh);
    cudaGetSymbolAddress((void**)&pHl,  g_Hl);
    cudaGetSymbolAddress((void**)&pTh,  g_Th);
    cudaGetSymbolAddress((void**)&pTl,  g_Tl);
    cudaGetSymbolAddress((void**)&pWth, g_Wh);
    cudaGetSymbolAddress((void**)&pWtl, g_Wl);

    cudaFuncSetAttribute(mma_gemm<0, 0, 0>, cudaFuncAttributeMaxDynamicSharedMemorySize, GEMM_SMEM);
    cudaFuncSetAttribute(mma_gemm<1, 0, 0>, cudaFuncAttributeMaxDynamicSharedMemorySize, GEMM_SMEM);
    cudaFuncSetAttribute(mma_gemm<1, 1, 1>, cudaFuncAttributeMaxDynamicSharedMemorySize, GEMM_SMEM);

    const int MT = (NN + 127) / 128;     // 391

    // prep
    prep_weights<<<(W_TOT + 255) / 256, 256>>>(Wq, Wk, Wv, Wo_w, ffn_w1, ffn_w2);
    conv_split<<<(NN * CC / 4 + 255) / 256, 256>>>(x, pXh, pXl, NN * CC / 4);

    // CSR sort by dst (independent of QKV; same stream serializes correctly)
    zero_cnt<<<(NN + 255) / 256, 256>>>();
    hist_kernel<<<(EE + 255) / 256, 256>>>(ei);
    scan_kernel<<<1, 1024>>>();
    scatter_kernel<<<(EE + 255) / 256, 256>>>(ei);

    // fused QKV: [NN,768] = X @ Wqkv
    mma_gemm<0, 0, 0><<<dim3(6, MT), 256, GEMM_SMEM>>>(
        pXh, pXl, pWth + W_QKV, pWtl + W_QKV, nullptr, pQKV, nullptr, nullptr, NN, 768, CC);

    // fused attention -> split agg
    attn_kernel<<<NN / 8, 256>>>(pAh, pAl);

    // Wo projection
    mma_gemm<1, 0, 0><<<dim3(2, MT), 256, GEMM_SMEM>>>(
        pAh, pAl, pWth + W_WO, pWtl + W_WO, Wo_b, pWo, nullptr, nullptr, NN, CC, CC);
    // LN1 -> h1 (fp32 + split)
    ln_kernel<1><<<NN / 4, 256>>>(pWo, x, ln1_g, ln1_b, pH1, pHh, pHl);
    // FFN1 + GELU -> hidden split
    mma_gemm<1, 1, 1><<<dim3(4, MT), 256, GEMM_SMEM>>>(
        pHh, pHl, pWth + W_F1, pWtl + W_F1, ffn_b1, nullptr, pTh, pTl, NN, FF, CC);
    // FFN2 -> agg
    mma_gemm<1, 0, 0><<<dim3(2, MT), 256, GEMM_SMEM>>>(
        pTh, pTl, pWth + W_F2, pWtl + W_F2, ffn_b2, pAgg, nullptr, nullptr, NN, CC, FF);
    // LN2 -> out
    ln_kernel<0><<<NN / 4, 256>>>(pAgg, pH1, ln2_g, ln2_b, out, nullptr, nullptr);
}

// round 7
// speedup vs baseline: 2.5836x; 1.1720x over previous
#include <cuda_runtime.h>
#include <cuda_bf16.h>
#include <cstdint>

#define NN 50000
#define EE 800000
#define CC 256
#define HH 8
#define DD 32
#define FF 512
#define SCALE 0.17677669529663689f
#define CAP 96

#define W_QKV 0
#define W_WO  196608
#define W_F1  262144
#define W_F2  393216
#define W_TOT 524288

// ---------------- scratch ----------------
__device__ float g_QKV[(size_t)NN * 768];     // fused Q|K|V fp32
__device__ float g_agg[(size_t)NN * CC];      // ffn2 out
__device__ float g_wo[(size_t)NN * CC];       // Wo out
__device__ float g_h1[(size_t)NN * CC];       // ln1 out fp32
__device__ __nv_bfloat16 g_Xh[(size_t)NN * CC],  g_Xl[(size_t)NN * CC];
__device__ __nv_bfloat16 g_Ah[(size_t)NN * CC],  g_Al[(size_t)NN * CC];   // attn agg split
__device__ __nv_bfloat16 g_Hh[(size_t)NN * CC],  g_Hl[(size_t)NN * CC];   // h1 split
__device__ __nv_bfloat16 g_Th[(size_t)NN * FF],  g_Tl[(size_t)NN * FF];   // ffn hidden split
__device__ __nv_bfloat16 g_Wh[W_TOT];                                     // weights bf16, k-major
__device__ int g_cnt[NN], g_ofs[NN], g_cur[NN];
__device__ int g_ss[EE];                      // src sorted by dst

// ---------------- helpers ----------------
__device__ __forceinline__ uint32_t smem_u32(const void* p) {
    uint32_t a;
    asm("{ .reg .u64 t; cvta.to.shared.u64 t, %1; cvt.u32.u64 %0, t; }" : "=r"(a) : "l"(p));
    return a;
}
#define SWZ(off) ((off) ^ (((off) >> 3) & 0x70))

__device__ __forceinline__ void ldm_x4(uint32_t* r, uint32_t addr) {
    asm volatile("ldmatrix.sync.aligned.m8n8.x4.shared.b16 {%0,%1,%2,%3}, [%4];"
        : "=r"(r[0]), "=r"(r[1]), "=r"(r[2]), "=r"(r[3]) : "r"(addr));
}
__device__ __forceinline__ void mma_bf16(float* d, const uint32_t* a, const uint32_t* b) {
    asm volatile("mma.sync.aligned.m16n8k16.row.col.f32.bf16.bf16.f32 "
        "{%0,%1,%2,%3}, {%4,%5,%6,%7}, {%8,%9}, {%0,%1,%2,%3};"
        : "+f"(d[0]), "+f"(d[1]), "+f"(d[2]), "+f"(d[3])
        : "r"(a[0]), "r"(a[1]), "r"(a[2]), "r"(a[3]), "r"(b[0]), "r"(b[1]));
}
__device__ __forceinline__ void split2(float x, float y, uint32_t& hi, uint32_t& lo) {
    __nv_bfloat162 h = __float22bfloat162_rn(make_float2(x, y));
    float2 hf = __bfloat1622float2(h);
    __nv_bfloat162 l = __float22bfloat162_rn(make_float2(x - hf.x, y - hf.y));
    hi = *(uint32_t*)&h;
    lo = *(uint32_t*)&l;
}
__device__ __forceinline__ void cpa16(uint32_t dst, const void* src, uint32_t sz) {
    asm volatile("cp.async.cg.shared.global [%0], [%1], 16, %2;"
        :: "r"(dst), "l"(src), "r"(sz) : "memory");
}
#define CP_COMMIT() asm volatile("cp.async.commit_group;" ::: "memory")
#define CP_WAIT1()  asm volatile("cp.async.wait_group 1;" ::: "memory")

// ---------------- weight prep: transpose to k-major bf16 ----------------
__global__ void prep_weights(const float* __restrict__ Wq, const float* __restrict__ Wk,
                             const float* __restrict__ Wv, const float* __restrict__ Wo,
                             const float* __restrict__ F1, const float* __restrict__ F2)
{
    int idx = blockIdx.x * 256 + threadIdx.x;
    if (idx >= W_TOT) return;
    float w;
    if (idx < W_WO) {
        int n = idx >> 8, k = idx & 255;
        if (n < 256)      w = Wq[k * 256 + n];
        else if (n < 512) w = Wk[k * 256 + (n - 256)];
        else              w = Wv[k * 256 + (n - 512)];
    } else if (idx < W_F1) {
        int l = idx - W_WO;
        int n = l >> 8, k = l & 255;
        w = Wo[k * 256 + n];
    } else if (idx < W_F2) {
        int l = idx - W_F1;
        int n = l >> 8, k = l & 255;
        w = F1[k * 512 + n];
    } else {
        int l = idx - W_F2;
        int n = l >> 9, k = l & 511;
        w = F2[k * 256 + n];
    }
    g_Wh[idx] = __float2bfloat16(w);
}

// ---------------- fp32 -> bf16 hi/lo split ----------------
__global__ void conv_split(const float* __restrict__ in, __nv_bfloat16* __restrict__ oh,
                           __nv_bfloat16* __restrict__ ol, int n4)
{
    int i = blockIdx.x * 256 + threadIdx.x;
    if (i >= n4) return;
    float4 v = ((const float4*)in)[i];
    uint32_t h0, l0, h1, l1;
    split2(v.x, v.y, h0, l0);
    split2(v.z, v.w, h1, l1);
    ((uint2*)oh)[i] = make_uint2(h0, h1);
    ((uint2*)ol)[i] = make_uint2(l0, l1);
}

// ---------------- pipelined 2-term split GEMM ----------------
// C = (Ah+Al) @ Bh^T;  A split bf16 (exact to ~2^-16), B plain bf16.
// CTA 128x128, BK=64, 2-stage; stage = Ah|Al|Bh = 48KB -> 96KB total, 2 CTA/SM.
#define STG 49152
#define GEMM_SMEM (2 * STG)

template<int BIAS, int GELU, int OSPLIT>
__global__ __launch_bounds__(256, 2) void mma_gemm(
    const __nv_bfloat16* __restrict__ Agh, const __nv_bfloat16* __restrict__ Agl,
    const __nv_bfloat16* __restrict__ Bgh,
    const float* __restrict__ bias, float* __restrict__ C,
    __nv_bfloat16* __restrict__ Ch, __nv_bfloat16* __restrict__ Cl,
    int M, int N, int K)
{
    extern __shared__ char smem[];
    uint32_t sb = smem_u32(smem);
    int tid = threadIdx.x, wid = tid >> 5, lane = tid & 31;
    int row0 = blockIdx.y * 128;
    int col0 = blockIdx.x * 128;
    int Am0 = (wid >> 2) * 64;
    int Bn0 = (wid & 3) * 32;

    uint32_t arow[4], brow[2];
#pragma unroll
    for (int mt = 0; mt < 4; mt++)
        arow[mt] = (uint32_t)((Am0 + mt * 16 + (lane & 15)) * 128 + (lane >> 4) * 16);
#pragma unroll
    for (int ntp = 0; ntp < 2; ntp++)
        brow[ntp] = (uint32_t)((Bn0 + ntp * 16 + (lane >> 4) * 8 + (lane & 7)) * 128
                               + ((lane >> 3) & 1) * 16);

    float d[4][4][4];
#pragma unroll
    for (int i = 0; i < 4; i++)
#pragma unroll
        for (int j = 0; j < 4; j++)
#pragma unroll
            for (int e = 0; e < 4; e++) d[i][j][e] = 0.f;

    auto load_stage = [&](int st, int kt) {
        uint32_t base = sb + st * STG;
#pragma unroll
        for (int j = 0; j < 4; j++) {
            int id = tid + 256 * j;
            int r = id >> 3, c = id & 7;
            uint32_t off = SWZ((uint32_t)(r * 128 + c * 16));
            int gr = row0 + r;
            uint32_t sz = (gr < M) ? 16u : 0u;
            int grc = (gr < M) ? gr : (M - 1);
            cpa16(base + off, Agh + (size_t)grc * K + kt + c * 8, sz);
            cpa16(base + 16384 + off, Agl + (size_t)grc * K + kt + c * 8, sz);
            int gn = col0 + r;
            cpa16(base + 32768 + off, Bgh + (size_t)gn * K + kt + c * 8, 16u);
        }
    };

    load_stage(0, 0);
    CP_COMMIT();

    const int nIter = K >> 6;
    for (int it = 0; it < nIter; ++it) {
        if (it + 1 < nIter) load_stage((it + 1) & 1, (it + 1) << 6);
        CP_COMMIT();
        CP_WAIT1();
        __syncthreads();

        uint32_t sAh = sb + (it & 1) * STG;
        uint32_t sAl = sAh + 16384, sBh = sAh + 32768;
#pragma unroll
        for (int ks = 0; ks < 4; ks++) {
            uint32_t aH[4][4], aL[4][4], bH[4][2];
#pragma unroll
            for (int mt = 0; mt < 4; mt++) {
                ldm_x4(aH[mt], sAh + SWZ(arow[mt] + ks * 32));
                ldm_x4(aL[mt], sAl + SWZ(arow[mt] + ks * 32));
            }
#pragma unroll
            for (int ntp = 0; ntp < 2; ntp++)
                ldm_x4(&bH[ntp * 2][0], sBh + SWZ(brow[ntp] + ks * 32));
#pragma unroll
            for (int mt = 0; mt < 4; mt++)
#pragma unroll
                for (int nt = 0; nt < 4; nt++) {
                    mma_bf16(d[mt][nt], aH[mt], bH[nt]);
                    mma_bf16(d[mt][nt], aL[mt], bH[nt]);
                }
        }
        __syncthreads();
    }

#pragma unroll
    for (int nt = 0; nt < 4; nt++) {
        int c = col0 + Bn0 + nt * 8 + (lane & 3) * 2;
        float b0 = 0.f, b1 = 0.f;
        if (BIAS) { b0 = bias[c]; b1 = bias[c + 1]; }
#pragma unroll
        for (int mt = 0; mt < 4; mt++) {
            int r0 = row0 + Am0 + mt * 16 + (lane >> 2);
#pragma unroll
            for (int half = 0; half < 2; half++) {
                int r = r0 + half * 8;
                if (r < M) {
                    float v0 = d[mt][nt][half * 2 + 0] + b0;
                    float v1 = d[mt][nt][half * 2 + 1] + b1;
                    if (GELU) {
                        v0 = 0.5f * v0 * (1.f + erff(v0 * 0.70710678118654752f));
                        v1 = 0.5f * v1 * (1.f + erff(v1 * 0.70710678118654752f));
                    }
                    if (OSPLIT) {
                        uint32_t h, l;
                        split2(v0, v1, h, l);
                        *(uint32_t*)(Ch + (size_t)r * N + c) = h;
                        *(uint32_t*)(Cl + (size_t)r * N + c) = l;
                    } else {
                        *(float2*)(C + (size_t)r * N + c) = make_float2(v0, v1);
                    }
                }
            }
        }
    }
}

// ---------------- CSR sort: hist -> scan -> scatter ----------------
__global__ void zero_cnt() {
    int i = blockIdx.x * 256 + threadIdx.x;
    if (i < NN) g_cnt[i] = 0;
}
__global__ void hist_kernel(const int* __restrict__ ei) {
    int e = blockIdx.x * 256 + threadIdx.x;
    if (e < EE) atomicAdd(&g_cnt[ei[EE + e]], 1);
}
__global__ __launch_bounds__(1024) void scan_kernel() {
    __shared__ int part[1024];
    const int CH = 49;
    int t = threadIdx.x;
    int base = t * CH;
    int s = 0;
    for (int j = 0; j < CH; j++) {
        int i = base + j;
        if (i < NN) s += g_cnt[i];
    }
    part[t] = s;
    __syncthreads();
    for (int off = 1; off < 1024; off <<= 1) {
        int v = (t >= off) ? part[t - off] : 0;
        __syncthreads();
        part[t] += v;
        __syncthreads();
    }
    int run = (t == 0) ? 0 : part[t - 1];
    for (int j = 0; j < CH; j++) {
        int i = base + j;
        if (i < NN) {
            g_ofs[i] = run;
            g_cur[i] = run;
            run += g_cnt[i];
        }
    }
}
__global__ void scatter_kernel(const int* __restrict__ ei) {
    int e = blockIdx.x * 256 + threadIdx.x;
    if (e >= EE) return;
    int dst = ei[EE + e];
    int pos = atomicAdd(&g_cur[dst], 1);
    g_ss[pos] = ei[e];
}

// ---------------- fused per-dst attention ----------------
// 1 warp = 1 dst; 2-way unrolled passes for MLP.
__global__ __launch_bounds__(256) void attn_kernel(
    __nv_bfloat16* __restrict__ oh, __nv_bfloat16* __restrict__ ol)
{
    __shared__ float sc[8][CAP * 8];
    int tid = threadIdx.x;
    int w = tid >> 5, lane = tid & 31;
    int h = lane >> 2, sub = lane & 3;
    int dst = blockIdx.x * 8 + w;

    const float* qp = g_QKV + (size_t)dst * 768 + h * DD + sub * 8;
    float4 q0 = ((const float4*)qp)[0], q1 = ((const float4*)qp)[1];
    int beg = g_ofs[dst], cnt = g_cnt[dst];

    // ---- pass 1: scores + per-head max (init 0 = reference clamp) ----
    float m = 0.f;
    int i = 0;
    for (; i + 1 < cnt; i += 2) {
        int s0 = g_ss[beg + i], s1 = g_ss[beg + i + 1];
        const float* kp0 = g_QKV + (size_t)s0 * 768 + 256 + h * DD + sub * 8;
        const float* kp1 = g_QKV + (size_t)s1 * 768 + 256 + h * DD + sub * 8;
        float4 ka = ((const float4*)kp0)[0], kb = ((const float4*)kp0)[1];
        float4 kc = ((const float4*)kp1)[0], kd = ((const float4*)kp1)[1];
        float d0 = q0.x * ka.x + q0.y * ka.y + q0.z * ka.z + q0.w * ka.w
                 + q1.x * kb.x + q1.y * kb.y + q1.z * kb.z + q1.w * kb.w;
        float d1 = q0.x * kc.x + q0.y * kc.y + q0.z * kc.z + q0.w * kc.w
                 + q1.x * kd.x + q1.y * kd.y + q1.z * kd.z + q1.w * kd.w;
        d0 += __shfl_xor_sync(0xffffffffu, d0, 1);
        d1 += __shfl_xor_sync(0xffffffffu, d1, 1);
        d0 += __shfl_xor_sync(0xffffffffu, d0, 2);
        d1 += __shfl_xor_sync(0xffffffffu, d1, 2);
        float sa = d0 * SCALE, sb2 = d1 * SCALE;
        m = fmaxf(m, fmaxf(sa, sb2));
        if (sub == 0 && i + 1 < CAP) {
            sc[w][i * 8 + h] = sa;
            sc[w][(i + 1) * 8 + h] = sb2;
        }
    }
    if (i < cnt) {
        int s0 = g_ss[beg + i];
        const float* kp0 = g_QKV + (size_t)s0 * 768 + 256 + h * DD + sub * 8;
        float4 ka = ((const float4*)kp0)[0], kb = ((const float4*)kp0)[1];
        float d0 = q0.x * ka.x + q0.y * ka.y + q0.z * ka.z + q0.w * ka.w
                 + q1.x * kb.x + q1.y * kb.y + q1.z * kb.z + q1.w * kb.w;
        d0 += __shfl_xor_sync(0xffffffffu, d0, 1);
        d0 += __shfl_xor_sync(0xffffffffu, d0, 2);
        float sa = d0 * SCALE;
        m = fmaxf(m, sa);
        if (sub == 0 && i < CAP) sc[w][i * 8 + h] = sa;
    }
    __syncwarp();

    // ---- pass 2: exp + gather V + accumulate (2-way unrolled) ----
    float sum = 0.f;
    float4 a0 = make_float4(0.f, 0.f, 0.f, 0.f);
    float4 a1 = make_float4(0.f, 0.f, 0.f, 0.f);
    int lim = (cnt < CAP) ? cnt : CAP;   // recompute fallback beyond CAP
    i = 0;
    for (; i + 1 < lim; i += 2) {
        int s0 = g_ss[beg + i], s1 = g_ss[beg + i + 1];
        float wa = __expf(sc[w][i * 8 + h] - m);
        float wb = __expf(sc[w][(i + 1) * 8 + h] - m);
        const float* vp0 = g_QKV + (size_t)s0 * 768 + 512 + h * DD + sub * 8;
        const float* vp1 = g_QKV + (size_t)s1 * 768 + 512 + h * DD + sub * 8;
        float4 va = ((const float4*)vp0)[0], vb = ((const float4*)vp0)[1];
        float4 vc = ((const float4*)vp1)[0], vd = ((const float4*)vp1)[1];
        sum += wa + wb;
        a0.x += wa * va.x + wb * vc.x; a0.y += wa * va.y + wb * vc.y;
        a0.z += wa * va.z + wb * vc.z; a0.w += wa * va.w + wb * vc.w;
        a1.x += wa * vb.x + wb * vd.x; a1.y += wa * vb.y + wb * vd.y;
        a1.z += wa * vb.z + wb * vd.z; a1.w += wa * vb.w + wb * vd.w;
    }
    for (; i < cnt; i++) {
        int s0 = g_ss[beg + i];
        float s;
        if (i < CAP) {
            s = sc[w][i * 8 + h];
        } else {
            const float* kp0 = g_QKV + (size_t)s0 * 768 + 256 + h * DD + sub * 8;
            float4 ka = ((const float4*)kp0)[0], kb = ((const float4*)kp0)[1];
            float d0 = q0.x * ka.x + q0.y * ka.y + q0.z * ka.z + q0.w * ka.w
                     + q1.x * kb.x + q1.y * kb.y + q1.z * kb.z + q1.w * kb.w;
            d0 += __shfl_xor_sync(0xffffffffu, d0, 1);
            d0 += __shfl_xor_sync(0xffffffffu, d0, 2);
            s = d0 * SCALE;
        }
        float wa = __expf(s - m);
        sum += wa;
        const float* vp0 = g_QKV + (size_t)s0 * 768 + 512 + h * DD + sub * 8;
        float4 va = ((const float4*)vp0)[0], vb = ((const float4*)vp0)[1];
        a0.x += wa * va.x; a0.y += wa * va.y; a0.z += wa * va.z; a0.w += wa * va.w;
        a1.x += wa * vb.x; a1.y += wa * vb.y; a1.z += wa * vb.z; a1.w += wa * vb.w;
    }
    float inv = 1.f / (sum + 1e-8f);
    uint32_t h0, l0, h1, l1, h2, l2, h3, l3;
    split2(a0.x * inv, a0.y * inv, h0, l0);
    split2(a0.z * inv, a0.w * inv, h1, l1);
    split2(a1.x * inv, a1.y * inv, h2, l2);
    split2(a1.z * inv, a1.w * inv, h3, l3);
    size_t ob = (size_t)dst * CC + h * DD + sub * 8;
    *(uint4*)(oh + ob) = make_uint4(h0, h1, h2, h3);
    *(uint4*)(ol + ob) = make_uint4(l0, l1, l2, l3);
}

// ---------------- layernorm ----------------
template<int SPLIT>
__global__ __launch_bounds__(256) void ln_kernel(
    const float* __restrict__ a, const float* __restrict__ b,
    const float* __restrict__ g, const float* __restrict__ bb,
    float* __restrict__ out, __nv_bfloat16* __restrict__ oh,
    __nv_bfloat16* __restrict__ ol)
{
    __shared__ float red[8][2];
    int r = threadIdx.x >> 6;
    int t = threadIdx.x & 63;
    size_t row = (size_t)blockIdx.x * 4 + r;
    float4 va = ((const float4*)(a + row * CC))[t];
    float4 vb = ((const float4*)(b + row * CC))[t];
    float4 v = make_float4(va.x + vb.x, va.y + vb.y, va.z + vb.z, va.w + vb.w);
    float s = v.x + v.y + v.z + v.w;
    float q = v.x * v.x + v.y * v.y + v.z * v.z + v.w * v.w;
#pragma unroll
    for (int o = 16; o; o >>= 1) {
        s += __shfl_xor_sync(0xffffffffu, s, o);
        q += __shfl_xor_sync(0xffffffffu, q, o);
    }
    int wid = threadIdx.x >> 5;
    if ((threadIdx.x & 31) == 0) { red[wid][0] = s; red[wid][1] = q; }
    __syncthreads();
    int wp = r * 2;
    s = red[wp][0] + red[wp + 1][0];
    q = red[wp][1] + red[wp + 1][1];
    float mu = s * (1.f / 256.f);
    float var = q * (1.f / 256.f) - mu * mu;
    float rs = rsqrtf(var + 1e-5f);
    float4 gg = ((const float4*)g)[t];
    float4 bv = ((const float4*)bb)[t];
    float4 o;
    o.x = (v.x - mu) * rs * gg.x + bv.x;
    o.y = (v.y - mu) * rs * gg.y + bv.y;
    o.z = (v.z - mu) * rs * gg.z + bv.z;
    o.w = (v.w - mu) * rs * gg.w + bv.w;
    ((float4*)(out + row * CC))[t] = o;
    if (SPLIT) {
        uint32_t h0, l0, h1, l1;
        split2(o.x, o.y, h0, l0);
        split2(o.z, o.w, h1, l1);
        ((uint2*)(oh + row * CC))[t] = make_uint2(h0, h1);
        ((uint2*)(ol + row * CC))[t] = make_uint2(l0, l1);
    }
}

// ---------------- launch ----------------
extern "C" void kernel_launch(void* const* d_in, const int* in_sizes, int n_in,
                              void* d_out, int out_size)
{
    const float* x      = (const float*)d_in[0];
    const int*   ei     = (const int*)d_in[1];
    const float* Wq     = (const float*)d_in[3];
    const float* Wk     = (const float*)d_in[4];
    const float* Wv     = (const float*)d_in[5];
    const float* Wo_w   = (const float*)d_in[6];
    const float* Wo_b   = (const float*)d_in[7];
    const float* ln1_g  = (const float*)d_in[8];
    const float* ln1_b  = (const float*)d_in[9];
    const float* ln2_g  = (const float*)d_in[10];
    const float* ln2_b  = (const float*)d_in[11];
    const float* ffn_w1 = (const float*)d_in[12];
    const float* ffn_b1 = (const float*)d_in[13];
    const float* ffn_w2 = (const float*)d_in[14];
    const float* ffn_b2 = (const float*)d_in[15];
    float* out = (float*)d_out;

    float *pQKV, *pAgg, *pWo, *pH1;
    __nv_bfloat16 *pXh, *pXl, *pAh, *pAl, *pHh, *pHl, *pTh, *pTl, *pWth;
    cudaGetSymbolAddress((void**)&pQKV, g_QKV);
    cudaGetSymbolAddress((void**)&pAgg, g_agg);
    cudaGetSymbolAddress((void**)&pWo,  g_wo);
    cudaGetSymbolAddress((void**)&pH1,  g_h1);
    cudaGetSymbolAddress((void**)&pXh,  g_Xh);
    cudaGetSymbolAddress((void**)&pXl,  g_Xl);
    cudaGetSymbolAddress((void**)&pAh,  g_Ah);
    cudaGetSymbolAddress((void**)&pAl,  g_Al);
    cudaGetSymbolAddress((void**)&pHh,  g_Hh);
    cudaGetSymbolAddress((void**)&pHl,  g_Hl);
    cudaGetSymbolAddress((void**)&pTh,  g_Th);
    cudaGetSymbolAddress((void**)&pTl,  g_Tl);
    cudaGetSymbolAddress((void**)&pWth, g_Wh);

    cudaFuncSetAttribute(mma_gemm<0, 0, 0>, cudaFuncAttributeMaxDynamicSharedMemorySize, GEMM_SMEM);
    cudaFuncSetAttribute(mma_gemm<1, 0, 0>, cudaFuncAttributeMaxDynamicSharedMemorySize, GEMM_SMEM);
    cudaFuncSetAttribute(mma_gemm<1, 1, 1>, cudaFuncAttributeMaxDynamicSharedMemorySize, GEMM_SMEM);

    const int MT = (NN + 127) / 128;     // 391

    // prep
    prep_weights<<<(W_TOT + 255) / 256, 256>>>(Wq, Wk, Wv, Wo_w, ffn_w1, ffn_w2);
    conv_split<<<(NN * CC / 4 + 255) / 256, 256>>>(x, pXh, pXl, NN * CC / 4);

    // CSR sort by dst
    zero_cnt<<<(NN + 255) / 256, 256>>>();
    hist_kernel<<<(EE + 255) / 256, 256>>>(ei);
    scan_kernel<<<1, 1024>>>();
    scatter_kernel<<<(EE + 255) / 256, 256>>>(ei);

    // fused QKV
    mma_gemm<0, 0, 0><<<dim3(6, MT), 256, GEMM_SMEM>>>(
        pXh, pXl, pWth + W_QKV, nullptr, pQKV, nullptr, nullptr, NN, 768, CC);

    // fused attention -> split agg
    attn_kernel<<<NN / 8, 256>>>(pAh, pAl);

    // Wo projection
    mma_gemm<1, 0, 0><<<dim3(2, MT), 256, GEMM_SMEM>>>(
        pAh, pAl, pWth + W_WO, Wo_b, pWo, nullptr, nullptr, NN, CC, CC);
    // LN1
    ln_kernel<1><<<NN / 4, 256>>>(pWo, x, ln1_g, ln1_b, pH1, pHh, pHl);
    // FFN1 + GELU
    mma_gemm<1, 1, 1><<<dim3(4, MT), 256, GEMM_SMEM>>>(
        pHh, pHl, pWth + W_F1, ffn_b1, nullptr, pTh, pTl, NN, FF, CC);
    // FFN2
    mma_gemm<1, 0, 0><<<dim3(2, MT), 256, GEMM_SMEM>>>(
        pTh, pTl, pWth + W_F2, ffn_b2, pAgg, nullptr, nullptr, NN, CC, FF);
    // LN2
    ln_kernel<0><<<NN / 4, 256>>>(pAgg, pH1, ln2_g, ln2_b, out, nullptr, nullptr);
}

// round 8
// speedup vs baseline: 2.6863x; 1.0398x over previous
#include <cuda_runtime.h>
#include <cuda_bf16.h>
#include <cstdint>

#define NN 50000
#define EE 800000
#define CC 256
#define HH 8
#define DD 32
#define FF 512
#define SCALE 0.17677669529663689f

#define W_QKV 0
#define W_WO  196608
#define W_F1  262144
#define W_F2  393216
#define W_TOT 524288

// ---------------- scratch ----------------
__device__ float g_QKV[(size_t)NN * 768];     // fused Q|K|V fp32
__device__ float g_agg[(size_t)NN * CC];      // ffn2 out
__device__ float g_wo[(size_t)NN * CC];       // Wo out
__device__ float g_h1[(size_t)NN * CC];       // ln1 out fp32
__device__ __nv_bfloat16 g_Xh[(size_t)NN * CC],  g_Xl[(size_t)NN * CC];
__device__ __nv_bfloat16 g_Ah[(size_t)NN * CC],  g_Al[(size_t)NN * CC];   // attn agg split
__device__ __nv_bfloat16 g_Hh[(size_t)NN * CC],  g_Hl[(size_t)NN * CC];   // h1 split
__device__ __nv_bfloat16 g_Th[(size_t)NN * FF],  g_Tl[(size_t)NN * FF];   // ffn hidden split
__device__ __nv_bfloat16 g_Wh[W_TOT];                                     // weights bf16, k-major
__device__ int g_cnt[NN], g_ofs[NN], g_cur[NN];
__device__ int g_ss[EE];                      // src sorted by dst

// ---------------- helpers ----------------
__device__ __forceinline__ uint32_t smem_u32(const void* p) {
    uint32_t a;
    asm("{ .reg .u64 t; cvta.to.shared.u64 t, %1; cvt.u32.u64 %0, t; }" : "=r"(a) : "l"(p));
    return a;
}
#define SWZ(off) ((off) ^ (((off) >> 3) & 0x70))

__device__ __forceinline__ void ldm_x4(uint32_t* r, uint32_t addr) {
    asm volatile("ldmatrix.sync.aligned.m8n8.x4.shared.b16 {%0,%1,%2,%3}, [%4];"
        : "=r"(r[0]), "=r"(r[1]), "=r"(r[2]), "=r"(r[3]) : "r"(addr));
}
__device__ __forceinline__ void mma_bf16(float* d, const uint32_t* a, const uint32_t* b) {
    asm volatile("mma.sync.aligned.m16n8k16.row.col.f32.bf16.bf16.f32 "
        "{%0,%1,%2,%3}, {%4,%5,%6,%7}, {%8,%9}, {%0,%1,%2,%3};"
        : "+f"(d[0]), "+f"(d[1]), "+f"(d[2]), "+f"(d[3])
        : "r"(a[0]), "r"(a[1]), "r"(a[2]), "r"(a[3]), "r"(b[0]), "r"(b[1]));
}
__device__ __forceinline__ void split2(float x, float y, uint32_t& hi, uint32_t& lo) {
    __nv_bfloat162 h = __float22bfloat162_rn(make_float2(x, y));
    float2 hf = __bfloat1622float2(h);
    __nv_bfloat162 l = __float22bfloat162_rn(make_float2(x - hf.x, y - hf.y));
    hi = *(uint32_t*)&h;
    lo = *(uint32_t*)&l;
}
__device__ __forceinline__ void cpa16(uint32_t dst, const void* src, uint32_t sz) {
    asm volatile("cp.async.cg.shared.global [%0], [%1], 16, %2;"
        :: "r"(dst), "l"(src), "r"(sz) : "memory");
}
#define CP_COMMIT() asm volatile("cp.async.commit_group;" ::: "memory")
#define CP_WAIT1()  asm volatile("cp.async.wait_group 1;" ::: "memory")

// ---------------- weight prep: transpose to k-major bf16 ----------------
__global__ void prep_weights(const float* __restrict__ Wq, const float* __restrict__ Wk,
                             const float* __restrict__ Wv, const float* __restrict__ Wo,
                             const float* __restrict__ F1, const float* __restrict__ F2)
{
    int idx = blockIdx.x * 256 + threadIdx.x;
    if (idx >= W_TOT) return;
    float w;
    if (idx < W_WO) {
        int n = idx >> 8, k = idx & 255;
        if (n < 256)      w = Wq[k * 256 + n];
        else if (n < 512) w = Wk[k * 256 + (n - 256)];
        else              w = Wv[k * 256 + (n - 512)];
    } else if (idx < W_F1) {
        int l = idx - W_WO;
        int n = l >> 8, k = l & 255;
        w = Wo[k * 256 + n];
    } else if (idx < W_F2) {
        int l = idx - W_F1;
        int n = l >> 8, k = l & 255;
        w = F1[k * 512 + n];
    } else {
        int l = idx - W_F2;
        int n = l >> 9, k = l & 511;
        w = F2[k * 256 + n];
    }
    g_Wh[idx] = __float2bfloat16(w);
}

// ---------------- fp32 -> bf16 hi/lo split ----------------
__global__ void conv_split(const float* __restrict__ in, __nv_bfloat16* __restrict__ oh,
                           __nv_bfloat16* __restrict__ ol, int n4)
{
    int i = blockIdx.x * 256 + threadIdx.x;
    if (i >= n4) return;
    float4 v = ((const float4*)in)[i];
    uint32_t h0, l0, h1, l1;
    split2(v.x, v.y, h0, l0);
    split2(v.z, v.w, h1, l1);
    ((uint2*)oh)[i] = make_uint2(h0, h1);
    ((uint2*)ol)[i] = make_uint2(l0, l1);
}

// ---------------- pipelined 2-term split GEMM (unchanged from R7) ----------------
#define STG 49152
#define GEMM_SMEM (2 * STG)

template<int BIAS, int GELU, int OSPLIT>
__global__ __launch_bounds__(256, 2) void mma_gemm(
    const __nv_bfloat16* __restrict__ Agh, const __nv_bfloat16* __restrict__ Agl,
    const __nv_bfloat16* __restrict__ Bgh,
    const float* __restrict__ bias, float* __restrict__ C,
    __nv_bfloat16* __restrict__ Ch, __nv_bfloat16* __restrict__ Cl,
    int M, int N, int K)
{
    extern __shared__ char smem[];
    uint32_t sb = smem_u32(smem);
    int tid = threadIdx.x, wid = tid >> 5, lane = tid & 31;
    int row0 = blockIdx.y * 128;
    int col0 = blockIdx.x * 128;
    int Am0 = (wid >> 2) * 64;
    int Bn0 = (wid & 3) * 32;

    uint32_t arow[4], brow[2];
#pragma unroll
    for (int mt = 0; mt < 4; mt++)
        arow[mt] = (uint32_t)((Am0 + mt * 16 + (lane & 15)) * 128 + (lane >> 4) * 16);
#pragma unroll
    for (int ntp = 0; ntp < 2; ntp++)
        brow[ntp] = (uint32_t)((Bn0 + ntp * 16 + (lane >> 4) * 8 + (lane & 7)) * 128
                               + ((lane >> 3) & 1) * 16);

    float d[4][4][4];
#pragma unroll
    for (int i = 0; i < 4; i++)
#pragma unroll
        for (int j = 0; j < 4; j++)
#pragma unroll
            for (int e = 0; e < 4; e++) d[i][j][e] = 0.f;

    auto load_stage = [&](int st, int kt) {
        uint32_t base = sb + st * STG;
#pragma unroll
        for (int j = 0; j < 4; j++) {
            int id = tid + 256 * j;
            int r = id >> 3, c = id & 7;
            uint32_t off = SWZ((uint32_t)(r * 128 + c * 16));
            int gr = row0 + r;
            uint32_t sz = (gr < M) ? 16u : 0u;
            int grc = (gr < M) ? gr : (M - 1);
            cpa16(base + off, Agh + (size_t)grc * K + kt + c * 8, sz);
            cpa16(base + 16384 + off, Agl + (size_t)grc * K + kt + c * 8, sz);
            int gn = col0 + r;
            cpa16(base + 32768 + off, Bgh + (size_t)gn * K + kt + c * 8, 16u);
        }
    };

    load_stage(0, 0);
    CP_COMMIT();

    const int nIter = K >> 6;
    for (int it = 0; it < nIter; ++it) {
        if (it + 1 < nIter) load_stage((it + 1) & 1, (it + 1) << 6);
        CP_COMMIT();
        CP_WAIT1();
        __syncthreads();

        uint32_t sAh = sb + (it & 1) * STG;
        uint32_t sAl = sAh + 16384, sBh = sAh + 32768;
#pragma unroll
        for (int ks = 0; ks < 4; ks++) {
            uint32_t aH[4][4], aL[4][4], bH[4][2];
#pragma unroll
            for (int mt = 0; mt < 4; mt++) {
                ldm_x4(aH[mt], sAh + SWZ(arow[mt] + ks * 32));
                ldm_x4(aL[mt], sAl + SWZ(arow[mt] + ks * 32));
            }
#pragma unroll
            for (int ntp = 0; ntp < 2; ntp++)
                ldm_x4(&bH[ntp * 2][0], sBh + SWZ(brow[ntp] + ks * 32));
#pragma unroll
            for (int mt = 0; mt < 4; mt++)
#pragma unroll
                for (int nt = 0; nt < 4; nt++) {
                    mma_bf16(d[mt][nt], aH[mt], bH[nt]);
                    mma_bf16(d[mt][nt], aL[mt], bH[nt]);
                }
        }
        __syncthreads();
    }

#pragma unroll
    for (int nt = 0; nt < 4; nt++) {
        int c = col0 + Bn0 + nt * 8 + (lane & 3) * 2;
        float b0 = 0.f, b1 = 0.f;
        if (BIAS) { b0 = bias[c]; b1 = bias[c + 1]; }
#pragma unroll
        for (int mt = 0; mt < 4; mt++) {
            int r0 = row0 + Am0 + mt * 16 + (lane >> 2);
#pragma unroll
            for (int half = 0; half < 2; half++) {
                int r = r0 + half * 8;
                if (r < M) {
                    float v0 = d[mt][nt][half * 2 + 0] + b0;
                    float v1 = d[mt][nt][half * 2 + 1] + b1;
                    if (GELU) {
                        v0 = 0.5f * v0 * (1.f + erff(v0 * 0.70710678118654752f));
                        v1 = 0.5f * v1 * (1.f + erff(v1 * 0.70710678118654752f));
                    }
                    if (OSPLIT) {
                        uint32_t h, l;
                        split2(v0, v1, h, l);
                        *(uint32_t*)(Ch + (size_t)r * N + c) = h;
                        *(uint32_t*)(Cl + (size_t)r * N + c) = l;
                    } else {
                        *(float2*)(C + (size_t)r * N + c) = make_float2(v0, v1);
                    }
                }
            }
        }
    }
}

// ---------------- CSR sort: hist -> scan -> scatter ----------------
__global__ void zero_cnt() {
    int i = blockIdx.x * 256 + threadIdx.x;
    if (i < NN) g_cnt[i] = 0;
}
__global__ void hist_kernel(const int* __restrict__ ei) {
    int e = blockIdx.x * 256 + threadIdx.x;
    if (e < EE) atomicAdd(&g_cnt[ei[EE + e]], 1);
}
__global__ __launch_bounds__(1024) void scan_kernel() {
    __shared__ int part[1024];
    const int CH = 49;
    int t = threadIdx.x;
    int base = t * CH;
    int s = 0;
    for (int j = 0; j < CH; j++) {
        int i = base + j;
        if (i < NN) s += g_cnt[i];
    }
    part[t] = s;
    __syncthreads();
    for (int off = 1; off < 1024; off <<= 1) {
        int v = (t >= off) ? part[t - off] : 0;
        __syncthreads();
        part[t] += v;
        __syncthreads();
    }
    int run = (t == 0) ? 0 : part[t - 1];
    for (int j = 0; j < CH; j++) {
        int i = base + j;
        if (i < NN) {
            g_ofs[i] = run;
            g_cur[i] = run;
            run += g_cnt[i];
        }
    }
}
__global__ void scatter_kernel(const int* __restrict__ ei) {
    int e = blockIdx.x * 256 + threadIdx.x;
    if (e >= EE) return;
    int dst = ei[EE + e];
    int pos = atomicAdd(&g_cur[dst], 1);
    g_ss[pos] = ei[e];
}

// ---------------- fused per-dst attention: single-pass online softmax ----------------
// 1 warp = 1 dst. lane -> head h = lane>>2, sub = lane&3 (8 V-dims each).
// Online rescaling == reference's (zero-init max, exp, sum) up to fp rounding.
__global__ __launch_bounds__(256) void attn_kernel(
    __nv_bfloat16* __restrict__ oh, __nv_bfloat16* __restrict__ ol)
{
    int tid = threadIdx.x;
    int w = tid >> 5, lane = tid & 31;
    int h = lane >> 2, sub = lane & 3;
    int dst = blockIdx.x * 8 + w;

    const float* qp = g_QKV + (size_t)dst * 768 + h * DD + sub * 8;
    float4 q0 = ((const float4*)qp)[0], q1 = ((const float4*)qp)[1];
    int beg = g_ofs[dst], cnt = g_cnt[dst];

    float m = 0.f, sum = 0.f;
    float4 a0 = make_float4(0.f, 0.f, 0.f, 0.f);
    float4 a1 = make_float4(0.f, 0.f, 0.f, 0.f);

    int i = 0;
    for (; i + 1 < cnt; i += 2) {
        int s0 = g_ss[beg + i], s1 = g_ss[beg + i + 1];
        const float* b0p = g_QKV + (size_t)s0 * 768 + h * DD + sub * 8;
        const float* b1p = g_QKV + (size_t)s1 * 768 + h * DD + sub * 8;
        // 8 independent LDG.128 issued up front (K + V for both edges)
        float4 ka = ((const float4*)(b0p + 256))[0], kb = ((const float4*)(b0p + 256))[1];
        float4 kc = ((const float4*)(b1p + 256))[0], kd = ((const float4*)(b1p + 256))[1];
        float4 va = ((const float4*)(b0p + 512))[0], vb = ((const float4*)(b0p + 512))[1];
        float4 vc = ((const float4*)(b1p + 512))[0], vd = ((const float4*)(b1p + 512))[1];
        float d0 = q0.x * ka.x + q0.y * ka.y + q0.z * ka.z + q0.w * ka.w
                 + q1.x * kb.x + q1.y * kb.y + q1.z * kb.z + q1.w * kb.w;
        float d1 = q0.x * kc.x + q0.y * kc.y + q0.z * kc.z + q0.w * kc.w
                 + q1.x * kd.x + q1.y * kd.y + q1.z * kd.z + q1.w * kd.w;
        d0 += __shfl_xor_sync(0xffffffffu, d0, 1);
        d1 += __shfl_xor_sync(0xffffffffu, d1, 1);
        d0 += __shfl_xor_sync(0xffffffffu, d0, 2);
        d1 += __shfl_xor_sync(0xffffffffu, d1, 2);
        float sa = d0 * SCALE, sb2 = d1 * SCALE;
        float nm = fmaxf(m, fmaxf(sa, sb2));
        float f  = __expf(m - nm);
        float wa = __expf(sa - nm), wb = __expf(sb2 - nm);
        m = nm;
        sum = sum * f + wa + wb;
        a0.x = a0.x * f + wa * va.x + wb * vc.x;
        a0.y = a0.y * f + wa * va.y + wb * vc.y;
        a0.z = a0.z * f + wa * va.z + wb * vc.z;
        a0.w = a0.w * f + wa * va.w + wb * vc.w;
        a1.x = a1.x * f + wa * vb.x + wb * vd.x;
        a1.y = a1.y * f + wa * vb.y + wb * vd.y;
        a1.z = a1.z * f + wa * vb.z + wb * vd.z;
        a1.w = a1.w * f + wa * vb.w + wb * vd.w;
    }
    if (i < cnt) {
        int s0 = g_ss[beg + i];
        const float* b0p = g_QKV + (size_t)s0 * 768 + h * DD + sub * 8;
        float4 ka = ((const float4*)(b0p + 256))[0], kb = ((const float4*)(b0p + 256))[1];
        float4 va = ((const float4*)(b0p + 512))[0], vb = ((const float4*)(b0p + 512))[1];
        float d0 = q0.x * ka.x + q0.y * ka.y + q0.z * ka.z + q0.w * ka.w
                 + q1.x * kb.x + q1.y * kb.y + q1.z * kb.z + q1.w * kb.w;
        d0 += __shfl_xor_sync(0xffffffffu, d0, 1);
        d0 += __shfl_xor_sync(0xffffffffu, d0, 2);
        float sa = d0 * SCALE;
        float nm = fmaxf(m, sa);
        float f  = __expf(m - nm);
        float wa = __expf(sa - nm);
        m = nm;
        sum = sum * f + wa;
        a0.x = a0.x * f + wa * va.x; a0.y = a0.y * f + wa * va.y;
        a0.z = a0.z * f + wa * va.z; a0.w = a0.w * f + wa * va.w;
        a1.x = a1.x * f + wa * vb.x; a1.y = a1.y * f + wa * vb.y;
        a1.z = a1.z * f + wa * vb.z; a1.w = a1.w * f + wa * vb.w;
    }

    float inv = 1.f / (sum + 1e-8f);
    uint32_t h0, l0, h1, l1, h2, l2, h3, l3;
    split2(a0.x * inv, a0.y * inv, h0, l0);
    split2(a0.z * inv, a0.w * inv, h1, l1);
    split2(a1.x * inv, a1.y * inv, h2, l2);
    split2(a1.z * inv, a1.w * inv, h3, l3);
    size_t ob = (size_t)dst * CC + h * DD + sub * 8;
    *(uint4*)(oh + ob) = make_uint4(h0, h1, h2, h3);
    *(uint4*)(ol + ob) = make_uint4(l0, l1, l2, l3);
}

// ---------------- layernorm ----------------
template<int SPLIT>
__global__ __launch_bounds__(256) void ln_kernel(
    const float* __restrict__ a, const float* __restrict__ b,
    const float* __restrict__ g, const float* __restrict__ bb,
    float* __restrict__ out, __nv_bfloat16* __restrict__ oh,
    __nv_bfloat16* __restrict__ ol)
{
    __shared__ float red[8][2];
    int r = threadIdx.x >> 6;
    int t = threadIdx.x & 63;
    size_t row = (size_t)blockIdx.x * 4 + r;
    float4 va = ((const float4*)(a + row * CC))[t];
    float4 vb = ((const float4*)(b + row * CC))[t];
    float4 v = make_float4(va.x + vb.x, va.y + vb.y, va.z + vb.z, va.w + vb.w);
    float s = v.x + v.y + v.z + v.w;
    float q = v.x * v.x + v.y * v.y + v.z * v.z + v.w * v.w;
#pragma unroll
    for (int o = 16; o; o >>= 1) {
        s += __shfl_xor_sync(0xffffffffu, s, o);
        q += __shfl_xor_sync(0xffffffffu, q, o);
    }
    int wid = threadIdx.x >> 5;
    if ((threadIdx.x & 31) == 0) { red[wid][0] = s; red[wid][1] = q; }
    __syncthreads();
    int wp = r * 2;
    s = red[wp][0] + red[wp + 1][0];
    q = red[wp][1] + red[wp + 1][1];
    float mu = s * (1.f / 256.f);
    float var = q * (1.f / 256.f) - mu * mu;
    float rs = rsqrtf(var + 1e-5f);
    float4 gg = ((const float4*)g)[t];
    float4 bv = ((const float4*)bb)[t];
    float4 o;
    o.x = (v.x - mu) * rs * gg.x + bv.x;
    o.y = (v.y - mu) * rs * gg.y + bv.y;
    o.z = (v.z - mu) * rs * gg.z + bv.z;
    o.w = (v.w - mu) * rs * gg.w + bv.w;
    ((float4*)(out + row * CC))[t] = o;
    if (SPLIT) {
        uint32_t h0, l0, h1, l1;
        split2(o.x, o.y, h0, l0);
        split2(o.z, o.w, h1, l1);
        ((uint2*)(oh + row * CC))[t] = make_uint2(h0, h1);
        ((uint2*)(ol + row * CC))[t] = make_uint2(l0, l1);
    }
}

// ---------------- launch ----------------
extern "C" void kernel_launch(void* const* d_in, const int* in_sizes, int n_in,
                              void* d_out, int out_size)
{
    const float* x      = (const float*)d_in[0];
    const int*   ei     = (const int*)d_in[1];
    const float* Wq     = (const float*)d_in[3];
    const float* Wk     = (const float*)d_in[4];
    const float* Wv     = (const float*)d_in[5];
    const float* Wo_w   = (const float*)d_in[6];
    const float* Wo_b   = (const float*)d_in[7];
    const float* ln1_g  = (const float*)d_in[8];
    const float* ln1_b  = (const float*)d_in[9];
    const float* ln2_g  = (const float*)d_in[10];
    const float* ln2_b  = (const float*)d_in[11];
    const float* ffn_w1 = (const float*)d_in[12];
    const float* ffn_b1 = (const float*)d_in[13];
    const float* ffn_w2 = (const float*)d_in[14];
    const float* ffn_b2 = (const float*)d_in[15];
    float* out = (float*)d_out;

    float *pQKV, *pAgg, *pWo, *pH1;
    __nv_bfloat16 *pXh, *pXl, *pAh, *pAl, *pHh, *pHl, *pTh, *pTl, *pWth;
    cudaGetSymbolAddress((void**)&pQKV, g_QKV);
    cudaGetSymbolAddress((void**)&pAgg, g_agg);
    cudaGetSymbolAddress((void**)&pWo,  g_wo);
    cudaGetSymbolAddress((void**)&pH1,  g_h1);
    cudaGetSymbolAddress((void**)&pXh,  g_Xh);
    cudaGetSymbolAddress((void**)&pXl,  g_Xl);
    cudaGetSymbolAddress((void**)&pAh,  g_Ah);
    cudaGetSymbolAddress((void**)&pAl,  g_Al);
    cudaGetSymbolAddress((void**)&pHh,  g_Hh);
    cudaGetSymbolAddress((void**)&pHl,  g_Hl);
    cudaGetSymbolAddress((void**)&pTh,  g_Th);
    cudaGetSymbolAddress((void**)&pTl,  g_Tl);
    cudaGetSymbolAddress((void**)&pWth, g_Wh);

    cudaFuncSetAttribute(mma_gemm<0, 0, 0>, cudaFuncAttributeMaxDynamicSharedMemorySize, GEMM_SMEM);
    cudaFuncSetAttribute(mma_gemm<1, 0, 0>, cudaFuncAttributeMaxDynamicSharedMemorySize, GEMM_SMEM);
    cudaFuncSetAttribute(mma_gemm<1, 1, 1>, cudaFuncAttributeMaxDynamicSharedMemorySize, GEMM_SMEM);

    const int MT = (NN + 127) / 128;     // 391

    // prep
    prep_weights<<<(W_TOT + 255) / 256, 256>>>(Wq, Wk, Wv, Wo_w, ffn_w1, ffn_w2);
    conv_split<<<(NN * CC / 4 + 255) / 256, 256>>>(x, pXh, pXl, NN * CC / 4);

    // CSR sort by dst
    zero_cnt<<<(NN + 255) / 256, 256>>>();
    hist_kernel<<<(EE + 255) / 256, 256>>>(ei);
    scan_kernel<<<1, 1024>>>();
    scatter_kernel<<<(EE + 255) / 256, 256>>>(ei);

    // fused QKV
    mma_gemm<0, 0, 0><<<dim3(6, MT), 256, GEMM_SMEM>>>(
        pXh, pXl, pWth + W_QKV, nullptr, pQKV, nullptr, nullptr, NN, 768, CC);

    // fused attention (online softmax) -> split agg
    attn_kernel<<<NN / 8, 256>>>(pAh, pAl);

    // Wo projection
    mma_gemm<1, 0, 0><<<dim3(2, MT), 256, GEMM_SMEM>>>(
        pAh, pAl, pWth + W_WO, Wo_b, pWo, nullptr, nullptr, NN, CC, CC);
    // LN1
    ln_kernel<1><<<NN / 4, 256>>>(pWo, x, ln1_g, ln1_b, pH1, pHh, pHl);
    // FFN1 + GELU
    mma_gemm<1, 1, 1><<<dim3(4, MT), 256, GEMM_SMEM>>>(
        pHh, pHl, pWth + W_F1, ffn_b1, nullptr, pTh, pTl, NN, FF, CC);
    // FFN2
    mma_gemm<1, 0, 0><<<dim3(2, MT), 256, GEMM_SMEM>>>(
        pTh, pTl, pWth + W_F2, ffn_b2, pAgg, nullptr, nullptr, NN, CC, FF);
    // LN2
    ln_kernel<0><<<NN / 4, 256>>>(pAgg, pH1, ln2_g, ln2_b, out, nullptr, nullptr);
}

// round 9
// speedup vs baseline: 2.7467x; 1.0225x over previous
#include <cuda_runtime.h>
#include <cuda_bf16.h>
#include <cstdint>

#define NN 50000
#define EE 800000
#define CC 256
#define HH 8
#define DD 32
#define FF 512
#define SCALE 0.17677669529663689f

#define W_QKV 0
#define W_WO  196608
#define W_F1  262144
#define W_F2  393216
#define W_TOT 524288

// ---------------- scratch ----------------
__device__ float g_QKV[(size_t)NN * 768];     // fused Q|K|V fp32
__device__ float g_h1[(size_t)NN * CC];       // ln1 out fp32
__device__ __nv_bfloat16 g_Xh[(size_t)NN * CC],  g_Xl[(size_t)NN * CC];
__device__ __nv_bfloat16 g_Ah[(size_t)NN * CC],  g_Al[(size_t)NN * CC];   // attn agg split
__device__ __nv_bfloat16 g_Hh[(size_t)NN * CC],  g_Hl[(size_t)NN * CC];   // h1 split
__device__ __nv_bfloat16 g_Th[(size_t)NN * FF],  g_Tl[(size_t)NN * FF];   // ffn hidden split
__device__ __nv_bfloat16 g_Wh[W_TOT];                                     // weights bf16, k-major
__device__ int g_cnt[NN], g_ofs[NN], g_cur[NN];
__device__ int g_ss[EE];                      // src sorted by dst

// ---------------- helpers ----------------
__device__ __forceinline__ uint32_t smem_u32(const void* p) {
    uint32_t a;
    asm("{ .reg .u64 t; cvta.to.shared.u64 t, %1; cvt.u32.u64 %0, t; }" : "=r"(a) : "l"(p));
    return a;
}
#define SWZ(off) ((off) ^ (((off) >> 3) & 0x70))

__device__ __forceinline__ void ldm_x4(uint32_t* r, uint32_t addr) {
    asm volatile("ldmatrix.sync.aligned.m8n8.x4.shared.b16 {%0,%1,%2,%3}, [%4];"
        : "=r"(r[0]), "=r"(r[1]), "=r"(r[2]), "=r"(r[3]) : "r"(addr));
}
__device__ __forceinline__ void mma_bf16(float* d, const uint32_t* a, const uint32_t* b) {
    asm volatile("mma.sync.aligned.m16n8k16.row.col.f32.bf16.bf16.f32 "
        "{%0,%1,%2,%3}, {%4,%5,%6,%7}, {%8,%9}, {%0,%1,%2,%3};"
        : "+f"(d[0]), "+f"(d[1]), "+f"(d[2]), "+f"(d[3])
        : "r"(a[0]), "r"(a[1]), "r"(a[2]), "r"(a[3]), "r"(b[0]), "r"(b[1]));
}
__device__ __forceinline__ void split2(float x, float y, uint32_t& hi, uint32_t& lo) {
    __nv_bfloat162 h = __float22bfloat162_rn(make_float2(x, y));
    float2 hf = __bfloat1622float2(h);
    __nv_bfloat162 l = __float22bfloat162_rn(make_float2(x - hf.x, y - hf.y));
    hi = *(uint32_t*)&h;
    lo = *(uint32_t*)&l;
}
__device__ __forceinline__ void cpa16(uint32_t dst, const void* src, uint32_t sz) {
    asm volatile("cp.async.cg.shared.global [%0], [%1], 16, %2;"
        :: "r"(dst), "l"(src), "r"(sz) : "memory");
}
#define CP_COMMIT() asm volatile("cp.async.commit_group;" ::: "memory")
#define CP_WAIT1()  asm volatile("cp.async.wait_group 1;" ::: "memory")

// ---------------- weight prep: transpose to k-major bf16 ----------------
__global__ void prep_weights(const float* __restrict__ Wq, const float* __restrict__ Wk,
                             const float* __restrict__ Wv, const float* __restrict__ Wo,
                             const float* __restrict__ F1, const float* __restrict__ F2)
{
    int idx = blockIdx.x * 256 + threadIdx.x;
    if (idx >= W_TOT) return;
    float w;
    if (idx < W_WO) {
        int n = idx >> 8, k = idx & 255;
        if (n < 256)      w = Wq[k * 256 + n];
        else if (n < 512) w = Wk[k * 256 + (n - 256)];
        else              w = Wv[k * 256 + (n - 512)];
    } else if (idx < W_F1) {
        int l = idx - W_WO;
        int n = l >> 8, k = l & 255;
        w = Wo[k * 256 + n];
    } else if (idx < W_F2) {
        int l = idx - W_F1;
        int n = l >> 8, k = l & 255;
        w = F1[k * 512 + n];
    } else {
        int l = idx - W_F2;
        int n = l >> 9, k = l & 511;
        w = F2[k * 256 + n];
    }
    g_Wh[idx] = __float2bfloat16(w);
}

// ---------------- fp32 -> bf16 hi/lo split ----------------
__global__ void conv_split(const float* __restrict__ in, __nv_bfloat16* __restrict__ oh,
                           __nv_bfloat16* __restrict__ ol, int n4)
{
    int i = blockIdx.x * 256 + threadIdx.x;
    if (i >= n4) return;
    float4 v = ((const float4*)in)[i];
    uint32_t h0, l0, h1, l1;
    split2(v.x, v.y, h0, l0);
    split2(v.z, v.w, h1, l1);
    ((uint2*)oh)[i] = make_uint2(h0, h1);
    ((uint2*)ol)[i] = make_uint2(l0, l1);
}

// ---------------- pipelined 2-term split GEMM (QKV / FFN1) ----------------
#define STG 49152
#define GEMM_SMEM (2 * STG)

template<int BIAS, int GELU, int OSPLIT>
__global__ __launch_bounds__(256, 2) void mma_gemm(
    const __nv_bfloat16* __restrict__ Agh, const __nv_bfloat16* __restrict__ Agl,
    const __nv_bfloat16* __restrict__ Bgh,
    const float* __restrict__ bias, float* __restrict__ C,
    __nv_bfloat16* __restrict__ Ch, __nv_bfloat16* __restrict__ Cl,
    int M, int N, int K)
{
    extern __shared__ char smem[];
    uint32_t sb = smem_u32(smem);
    int tid = threadIdx.x, wid = tid >> 5, lane = tid & 31;
    int row0 = blockIdx.y * 128;
    int col0 = blockIdx.x * 128;
    int Am0 = (wid >> 2) * 64;
    int Bn0 = (wid & 3) * 32;

    uint32_t arow[4], brow[2];
#pragma unroll
    for (int mt = 0; mt < 4; mt++)
        arow[mt] = (uint32_t)((Am0 + mt * 16 + (lane & 15)) * 128 + (lane >> 4) * 16);
#pragma unroll
    for (int ntp = 0; ntp < 2; ntp++)
        brow[ntp] = (uint32_t)((Bn0 + ntp * 16 + (lane >> 4) * 8 + (lane & 7)) * 128
                               + ((lane >> 3) & 1) * 16);

    float d[4][4][4];
#pragma unroll
    for (int i = 0; i < 4; i++)
#pragma unroll
        for (int j = 0; j < 4; j++)
#pragma unroll
            for (int e = 0; e < 4; e++) d[i][j][e] = 0.f;

    auto load_stage = [&](int st, int kt) {
        uint32_t base = sb + st * STG;
#pragma unroll
        for (int j = 0; j < 4; j++) {
            int id = tid + 256 * j;
            int r = id >> 3, c = id & 7;
            uint32_t off = SWZ((uint32_t)(r * 128 + c * 16));
            int gr = row0 + r;
            uint32_t sz = (gr < M) ? 16u : 0u;
            int grc = (gr < M) ? gr : (M - 1);
            cpa16(base + off, Agh + (size_t)grc * K + kt + c * 8, sz);
            cpa16(base + 16384 + off, Agl + (size_t)grc * K + kt + c * 8, sz);
            int gn = col0 + r;
            cpa16(base + 32768 + off, Bgh + (size_t)gn * K + kt + c * 8, 16u);
        }
    };

    load_stage(0, 0);
    CP_COMMIT();

    const int nIter = K >> 6;
    for (int it = 0; it < nIter; ++it) {
        if (it + 1 < nIter) load_stage((it + 1) & 1, (it + 1) << 6);
        CP_COMMIT();
        CP_WAIT1();
        __syncthreads();

        uint32_t sAh = sb + (it & 1) * STG;
        uint32_t sAl = sAh + 16384, sBh = sAh + 32768;
#pragma unroll
        for (int ks = 0; ks < 4; ks++) {
            uint32_t aH[4][4], aL[4][4], bH[4][2];
#pragma unroll
            for (int mt = 0; mt < 4; mt++) {
                ldm_x4(aH[mt], sAh + SWZ(arow[mt] + ks * 32));
                ldm_x4(aL[mt], sAl + SWZ(arow[mt] + ks * 32));
            }
#pragma unroll
            for (int ntp = 0; ntp < 2; ntp++)
                ldm_x4(&bH[ntp * 2][0], sBh + SWZ(brow[ntp] + ks * 32));
#pragma unroll
            for (int mt = 0; mt < 4; mt++)
#pragma unroll
                for (int nt = 0; nt < 4; nt++) {
                    mma_bf16(d[mt][nt], aH[mt], bH[nt]);
                    mma_bf16(d[mt][nt], aL[mt], bH[nt]);
                }
        }
        __syncthreads();
    }

#pragma unroll
    for (int nt = 0; nt < 4; nt++) {
        int c = col0 + Bn0 + nt * 8 + (lane & 3) * 2;
        float b0 = 0.f, b1 = 0.f;
        if (BIAS) { b0 = bias[c]; b1 = bias[c + 1]; }
#pragma unroll
        for (int mt = 0; mt < 4; mt++) {
            int r0 = row0 + Am0 + mt * 16 + (lane >> 2);
#pragma unroll
            for (int half = 0; half < 2; half++) {
                int r = r0 + half * 8;
                if (r < M) {
                    float v0 = d[mt][nt][half * 2 + 0] + b0;
                    float v1 = d[mt][nt][half * 2 + 1] + b1;
                    if (GELU) {
                        v0 = 0.5f * v0 * (1.f + erff(v0 * 0.70710678118654752f));
                        v1 = 0.5f * v1 * (1.f + erff(v1 * 0.70710678118654752f));
                    }
                    if (OSPLIT) {
                        uint32_t h, l;
                        split2(v0, v1, h, l);
                        *(uint32_t*)(Ch + (size_t)r * N + c) = h;
                        *(uint32_t*)(Cl + (size_t)r * N + c) = l;
                    } else {
                        *(float2*)(C + (size_t)r * N + c) = make_float2(v0, v1);
                    }
                }
            }
        }
    }
}

// ---------------- GEMM + residual + LayerNorm fused (Wo+LN1, FFN2+LN2) ----------------
// CTA tile 128 x 256 (full row), 512 threads = 16 warps as 4(M) x 4(N).
// Warp tile 32x64: mt{0,1} x nt{0..7}, acc[2][8][4].
// Epilogue: v = acc + bias + residual; per-row mean/var via shfl + smem; LN write.
#define LSTG 65536
#define LN_SMEM (2 * LSTG)

template<int SPLIT>
__global__ __launch_bounds__(512, 1) void mma_gemm_ln(
    const __nv_bfloat16* __restrict__ Agh, const __nv_bfloat16* __restrict__ Agl,
    const __nv_bfloat16* __restrict__ Bgh,
    const float* __restrict__ bias, const float* __restrict__ Res,
    const float* __restrict__ lnG, const float* __restrict__ lnB,
    float* __restrict__ Out, __nv_bfloat16* __restrict__ Oh, __nv_bfloat16* __restrict__ Ol,
    int M, int K)
{
    extern __shared__ char smem[];
    uint32_t sb = smem_u32(smem);
    int tid = threadIdx.x, wid = tid >> 5, lane = tid & 31;
    int row0 = blockIdx.y * 128;
    int wM = wid >> 2, wN = wid & 3;
    int Am0 = wM * 32;
    int Bn0 = wN * 64;

    uint32_t arow[2], brow[4];
#pragma unroll
    for (int mt = 0; mt < 2; mt++)
        arow[mt] = (uint32_t)((Am0 + mt * 16 + (lane & 15)) * 128 + (lane >> 4) * 16);
#pragma unroll
    for (int ntp = 0; ntp < 4; ntp++)
        brow[ntp] = (uint32_t)((Bn0 + ntp * 16 + (lane >> 4) * 8 + (lane & 7)) * 128
                               + ((lane >> 3) & 1) * 16);

    float d[2][8][4];
#pragma unroll
    for (int i = 0; i < 2; i++)
#pragma unroll
        for (int j = 0; j < 8; j++)
#pragma unroll
            for (int e = 0; e < 4; e++) d[i][j][e] = 0.f;

    // stage: Ah 16KB | Al 16KB | Bh 32KB = 64KB
    auto load_stage = [&](int st, int kt) {
        uint32_t base = sb + st * LSTG;
#pragma unroll
        for (int j = 0; j < 2; j++) {
            int id = tid + 512 * j;
            int r = id >> 3, c = id & 7;
            uint32_t off = SWZ((uint32_t)(r * 128 + c * 16));
            int gr = row0 + r;
            uint32_t sz = (gr < M) ? 16u : 0u;
            int grc = (gr < M) ? gr : (M - 1);
            cpa16(base + off, Agh + (size_t)grc * K + kt + c * 8, sz);
            cpa16(base + 16384 + off, Agl + (size_t)grc * K + kt + c * 8, sz);
        }
#pragma unroll
        for (int j = 0; j < 4; j++) {
            int id = tid + 512 * j;
            int r = id >> 3, c = id & 7;
            uint32_t off = SWZ((uint32_t)(r * 128 + c * 16));
            cpa16(base + 32768 + off, Bgh + (size_t)r * K + kt + c * 8, 16u);
        }
    };

    load_stage(0, 0);
    CP_COMMIT();

    const int nIter = K >> 6;
    for (int it = 0; it < nIter; ++it) {
        if (it + 1 < nIter) load_stage((it + 1) & 1, (it + 1) << 6);
        CP_COMMIT();
        CP_WAIT1();
        __syncthreads();

        uint32_t sAh = sb + (it & 1) * LSTG;
        uint32_t sAl = sAh + 16384, sBh = sAh + 32768;
#pragma unroll
        for (int ks = 0; ks < 4; ks++) {
            uint32_t aH[2][4], aL[2][4], bH[8][2];
#pragma unroll
            for (int mt = 0; mt < 2; mt++) {
                ldm_x4(aH[mt], sAh + SWZ(arow[mt] + ks * 32));
                ldm_x4(aL[mt], sAl + SWZ(arow[mt] + ks * 32));
            }
#pragma unroll
            for (int ntp = 0; ntp < 4; ntp++)
                ldm_x4(&bH[ntp * 2][0], sBh + SWZ(brow[ntp] + ks * 32));
#pragma unroll
            for (int mt = 0; mt < 2; mt++)
#pragma unroll
                for (int nt = 0; nt < 8; nt++) {
                    mma_bf16(d[mt][nt], aH[mt], bH[nt]);
                    mma_bf16(d[mt][nt], aL[mt], bH[nt]);
                }
        }
        __syncthreads();
    }

    // ---- epilogue: bias + residual; row partial sums ----
    float* part = (float*)smem;   // [128 rows][4 wN][2] floats = 4KB (stages dead)
    float psum[2][2], psq[2][2];
#pragma unroll
    for (int mt = 0; mt < 2; mt++)
#pragma unroll
    for (int half = 0; half < 2; half++) {
        int lr = Am0 + mt * 16 + (lane >> 2) + half * 8;
        int r = row0 + lr;
        float s = 0.f, q = 0.f;
#pragma unroll
        for (int nt = 0; nt < 8; nt++) {
            int c = Bn0 + nt * 8 + (lane & 3) * 2;
            float2 res = (r < M) ? *(const float2*)(Res + (size_t)r * CC + c)
                                 : make_float2(0.f, 0.f);
            float v0 = d[mt][nt][half * 2 + 0] + bias[c] + res.x;
            float v1 = d[mt][nt][half * 2 + 1] + bias[c + 1] + res.y;
            d[mt][nt][half * 2 + 0] = v0;
            d[mt][nt][half * 2 + 1] = v1;
            s += v0 + v1;
            q += v0 * v0 + v1 * v1;
        }
        s += __shfl_xor_sync(0xffffffffu, s, 1);
        q += __shfl_xor_sync(0xffffffffu, q, 1);
        s += __shfl_xor_sync(0xffffffffu, s, 2);
        q += __shfl_xor_sync(0xffffffffu, q, 2);
        psum[mt][half] = s;
        psq[mt][half] = q;
    }
    if ((lane & 3) == 0) {
#pragma unroll
        for (int mt = 0; mt < 2; mt++)
#pragma unroll
        for (int half = 0; half < 2; half++) {
            int lr = Am0 + mt * 16 + (lane >> 2) + half * 8;
            part[(lr * 4 + wN) * 2 + 0] = psum[mt][half];
            part[(lr * 4 + wN) * 2 + 1] = psq[mt][half];
        }
    }
    __syncthreads();

    // ---- LN write ----
#pragma unroll
    for (int mt = 0; mt < 2; mt++)
#pragma unroll
    for (int half = 0; half < 2; half++) {
        int lr = Am0 + mt * 16 + (lane >> 2) + half * 8;
        int r = row0 + lr;
        if (r >= M) continue;
        float S = part[(lr * 4 + 0) * 2] + part[(lr * 4 + 1) * 2]
                + part[(lr * 4 + 2) * 2] + part[(lr * 4 + 3) * 2];
        float Q = part[(lr * 4 + 0) * 2 + 1] + part[(lr * 4 + 1) * 2 + 1]
                + part[(lr * 4 + 2) * 2 + 1] + part[(lr * 4 + 3) * 2 + 1];
        float mu = S * (1.f / 256.f);
        float var = Q * (1.f / 256.f) - mu * mu;
        float rs = rsqrtf(var + 1e-5f);
#pragma unroll
        for (int nt = 0; nt < 8; nt++) {
            int c = Bn0 + nt * 8 + (lane & 3) * 2;
            float g0 = lnG[c], g1 = lnG[c + 1];
            float bb0 = lnB[c], bb1 = lnB[c + 1];
            float o0 = (d[mt][nt][half * 2 + 0] - mu) * rs * g0 + bb0;
            float o1 = (d[mt][nt][half * 2 + 1] - mu) * rs * g1 + bb1;
            *(float2*)(Out + (size_t)r * CC + c) = make_float2(o0, o1);
            if (SPLIT) {
                uint32_t h, l;
                split2(o0, o1, h, l);
                *(uint32_t*)(Oh + (size_t)r * CC + c) = h;
                *(uint32_t*)(Ol + (size_t)r * CC + c) = l;
            }
        }
    }
}

// ---------------- CSR sort: hist -> scan -> scatter ----------------
__global__ void zero_cnt() {
    int i = blockIdx.x * 256 + threadIdx.x;
    if (i < NN) g_cnt[i] = 0;
}
__global__ void hist_kernel(const int* __restrict__ ei) {
    int e = blockIdx.x * 256 + threadIdx.x;
    if (e < EE) atomicAdd(&g_cnt[ei[EE + e]], 1);
}
__global__ __launch_bounds__(1024) void scan_kernel() {
    __shared__ int part[1024];
    const int CH = 49;
    int t = threadIdx.x;
    int base = t * CH;
    int s = 0;
    for (int j = 0; j < CH; j++) {
        int i = base + j;
        if (i < NN) s += g_cnt[i];
    }
    part[t] = s;
    __syncthreads();
    for (int off = 1; off < 1024; off <<= 1) {
        int v = (t >= off) ? part[t - off] : 0;
        __syncthreads();
        part[t] += v;
        __syncthreads();
    }
    int run = (t == 0) ? 0 : part[t - 1];
    for (int j = 0; j < CH; j++) {
        int i = base + j;
        if (i < NN) {
            g_ofs[i] = run;
            g_cur[i] = run;
            run += g_cnt[i];
        }
    }
}
__global__ void scatter_kernel(const int* __restrict__ ei) {
    int e = blockIdx.x * 256 + threadIdx.x;
    if (e >= EE) return;
    int dst = ei[EE + e];
    int pos = atomicAdd(&g_cur[dst], 1);
    g_ss[pos] = ei[e];
}

// ---------------- fused per-dst attention: single-pass online softmax ----------------
__global__ __launch_bounds__(256) void attn_kernel(
    __nv_bfloat16* __restrict__ oh, __nv_bfloat16* __restrict__ ol)
{
    int tid = threadIdx.x;
    int w = tid >> 5, lane = tid & 31;
    int h = lane >> 2, sub = lane & 3;
    int dst = blockIdx.x * 8 + w;

    const float* qp = g_QKV + (size_t)dst * 768 + h * DD + sub * 8;
    float4 q0 = ((const float4*)qp)[0], q1 = ((const float4*)qp)[1];
    int beg = g_ofs[dst], cnt = g_cnt[dst];

    float m = 0.f, sum = 0.f;
    float4 a0 = make_float4(0.f, 0.f, 0.f, 0.f);
    float4 a1 = make_float4(0.f, 0.f, 0.f, 0.f);

    int i = 0;
    for (; i + 1 < cnt; i += 2) {
        int s0 = g_ss[beg + i], s1 = g_ss[beg + i + 1];
        const float* b0p = g_QKV + (size_t)s0 * 768 + h * DD + sub * 8;
        const float* b1p = g_QKV + (size_t)s1 * 768 + h * DD + sub * 8;
        float4 ka = ((const float4*)(b0p + 256))[0], kb = ((const float4*)(b0p + 256))[1];
        float4 kc = ((const float4*)(b1p + 256))[0], kd = ((const float4*)(b1p + 256))[1];
        float4 va = ((const float4*)(b0p + 512))[0], vb = ((const float4*)(b0p + 512))[1];
        float4 vc = ((const float4*)(b1p + 512))[0], vd = ((const float4*)(b1p + 512))[1];
        float d0 = q0.x * ka.x + q0.y * ka.y + q0.z * ka.z + q0.w * ka.w
                 + q1.x * kb.x + q1.y * kb.y + q1.z * kb.z + q1.w * kb.w;
        float d1 = q0.x * kc.x + q0.y * kc.y + q0.z * kc.z + q0.w * kc.w
                 + q1.x * kd.x + q1.y * kd.y + q1.z * kd.z + q1.w * kd.w;
        d0 += __shfl_xor_sync(0xffffffffu, d0, 1);
        d1 += __shfl_xor_sync(0xffffffffu, d1, 1);
        d0 += __shfl_xor_sync(0xffffffffu, d0, 2);
        d1 += __shfl_xor_sync(0xffffffffu, d1, 2);
        float sa = d0 * SCALE, sb2 = d1 * SCALE;
        float nm = fmaxf(m, fmaxf(sa, sb2));
        float f  = __expf(m - nm);
        float wa = __expf(sa - nm), wb = __expf(sb2 - nm);
        m = nm;
        sum = sum * f + wa + wb;
        a0.x = a0.x * f + wa * va.x + wb * vc.x;
        a0.y = a0.y * f + wa * va.y + wb * vc.y;
        a0.z = a0.z * f + wa * va.z + wb * vc.z;
        a0.w = a0.w * f + wa * va.w + wb * vc.w;
        a1.x = a1.x * f + wa * vb.x + wb * vd.x;
        a1.y = a1.y * f + wa * vb.y + wb * vd.y;
        a1.z = a1.z * f + wa * vb.z + wb * vd.z;
        a1.w = a1.w * f + wa * vb.w + wb * vd.w;
    }
    if (i < cnt) {
        int s0 = g_ss[beg + i];
        const float* b0p = g_QKV + (size_t)s0 * 768 + h * DD + sub * 8;
        float4 ka = ((const float4*)(b0p + 256))[0], kb = ((const float4*)(b0p + 256))[1];
        float4 va = ((const float4*)(b0p + 512))[0], vb = ((const float4*)(b0p + 512))[1];
        float d0 = q0.x * ka.x + q0.y * ka.y + q0.z * ka.z + q0.w * ka.w
                 + q1.x * kb.x + q1.y * kb.y + q1.z * kb.z + q1.w * kb.w;
        d0 += __shfl_xor_sync(0xffffffffu, d0, 1);
        d0 += __shfl_xor_sync(0xffffffffu, d0, 2);
        float sa = d0 * SCALE;
        float nm = fmaxf(m, sa);
        float f  = __expf(m - nm);
        float wa = __expf(sa - nm);
        m = nm;
        sum = sum * f + wa;
        a0.x = a0.x * f + wa * va.x; a0.y = a0.y * f + wa * va.y;
        a0.z = a0.z * f + wa * va.z; a0.w = a0.w * f + wa * va.w;
        a1.x = a1.x * f + wa * vb.x; a1.y = a1.y * f + wa * vb.y;
        a1.z = a1.z * f + wa * vb.z; a1.w = a1.w * f + wa * vb.w;
    }

    float inv = 1.f / (sum + 1e-8f);
    uint32_t h0, l0, h1, l1, h2, l2, h3, l3;
    split2(a0.x * inv, a0.y * inv, h0, l0);
    split2(a0.z * inv, a0.w * inv, h1, l1);
    split2(a1.x * inv, a1.y * inv, h2, l2);
    split2(a1.z * inv, a1.w * inv, h3, l3);
    size_t ob = (size_t)dst * CC + h * DD + sub * 8;
    *(uint4*)(oh + ob) = make_uint4(h0, h1, h2, h3);
    *(uint4*)(ol + ob) = make_uint4(l0, l1, l2, l3);
}

// ---------------- launch ----------------
extern "C" void kernel_launch(void* const* d_in, const int* in_sizes, int n_in,
                              void* d_out, int out_size)
{
    const float* x      = (const float*)d_in[0];
    const int*   ei     = (const int*)d_in[1];
    const float* Wq     = (const float*)d_in[3];
    const float* Wk     = (const float*)d_in[4];
    const float* Wv     = (const float*)d_in[5];
    const float* Wo_w   = (const float*)d_in[6];
    const float* Wo_b   = (const float*)d_in[7];
    const float* ln1_g  = (const float*)d_in[8];
    const float* ln1_b  = (const float*)d_in[9];
    const float* ln2_g  = (const float*)d_in[10];
    const float* ln2_b  = (const float*)d_in[11];
    const float* ffn_w1 = (const float*)d_in[12];
    const float* ffn_b1 = (const float*)d_in[13];
    const float* ffn_w2 = (const float*)d_in[14];
    const float* ffn_b2 = (const float*)d_in[15];
    float* out = (float*)d_out;

    float *pQKV, *pH1;
    __nv_bfloat16 *pXh, *pXl, *pAh, *pAl, *pHh, *pHl, *pTh, *pTl, *pWth;
    cudaGetSymbolAddress((void**)&pQKV, g_QKV);
    cudaGetSymbolAddress((void**)&pH1,  g_h1);
    cudaGetSymbolAddress((void**)&pXh,  g_Xh);
    cudaGetSymbolAddress((void**)&pXl,  g_Xl);
    cudaGetSymbolAddress((void**)&pAh,  g_Ah);
    cudaGetSymbolAddress((void**)&pAl,  g_Al);
    cudaGetSymbolAddress((void**)&pHh,  g_Hh);
    cudaGetSymbolAddress((void**)&pHl,  g_Hl);
    cudaGetSymbolAddress((void**)&pTh,  g_Th);
    cudaGetSymbolAddress((void**)&pTl,  g_Tl);
    cudaGetSymbolAddress((void**)&pWth, g_Wh);

    cudaFuncSetAttribute(mma_gemm<0, 0, 0>, cudaFuncAttributeMaxDynamicSharedMemorySize, GEMM_SMEM);
    cudaFuncSetAttribute(mma_gemm<1, 1, 1>, cudaFuncAttributeMaxDynamicSharedMemorySize, GEMM_SMEM);
    cudaFuncSetAttribute(mma_gemm_ln<0>, cudaFuncAttributeMaxDynamicSharedMemorySize, LN_SMEM);
    cudaFuncSetAttribute(mma_gemm_ln<1>, cudaFuncAttributeMaxDynamicSharedMemorySize, LN_SMEM);

    const int MT = (NN + 127) / 128;     // 391

    // prep
    prep_weights<<<(W_TOT + 255) / 256, 256>>>(Wq, Wk, Wv, Wo_w, ffn_w1, ffn_w2);
    conv_split<<<(NN * CC / 4 + 255) / 256, 256>>>(x, pXh, pXl, NN * CC / 4);

    // CSR sort by dst
    zero_cnt<<<(NN + 255) / 256, 256>>>();
    hist_kernel<<<(EE + 255) / 256, 256>>>(ei);
    scan_kernel<<<1, 1024>>>();
    scatter_kernel<<<(EE + 255) / 256, 256>>>(ei);

    // fused QKV
    mma_gemm<0, 0, 0><<<dim3(6, MT), 256, GEMM_SMEM>>>(
        pXh, pXl, pWth + W_QKV, nullptr, pQKV, nullptr, nullptr, NN, 768, CC);

    // fused attention (online softmax) -> split agg
    attn_kernel<<<NN / 8, 256>>>(pAh, pAl);

    // Wo projection + residual(x) + LN1 -> h1 fp32 + split
    mma_gemm_ln<1><<<dim3(1, MT), 512, LN_SMEM>>>(
        pAh, pAl, pWth + W_WO, Wo_b, x, ln1_g, ln1_b, pH1, pHh, pHl, NN, CC);

    // FFN1 + GELU -> hidden split
    mma_gemm<1, 1, 1><<<dim3(4, MT), 256, GEMM_SMEM>>>(
        pHh, pHl, pWth + W_F1, ffn_b1, nullptr, pTh, pTl, NN, FF, CC);

    // FFN2 + residual(h1) + LN2 -> out
    mma_gemm_ln<0><<<dim3(1, MT), 512, LN_SMEM>>>(
        pTh, pTl, pWth + W_F2, ffn_b2, pH1, ln2_g, ln2_b, out, nullptr, nullptr, NN, FF);
}

// round 10
// speedup vs baseline: 3.0414x; 1.1073x over previous
#include <cuda_runtime.h>
#include <cuda_bf16.h>
#include <cstdint>

#define NN 50000
#define EE 800000
#define CC 256
#define HH 8
#define DD 32
#define FF 512
#define SCALE 0.17677669529663689f

#define W_QKV 0
#define W_WO  196608
#define W_F1  262144
#define W_F2  393216
#define W_TOT 524288

// ---------------- scratch ----------------
__device__ float g_Q[(size_t)NN * CC];        // Q fp32
__device__ __nv_bfloat16 g_KV[(size_t)NN * 512];  // K|V bf16 packed per node
__device__ float g_h1[(size_t)NN * CC];       // ln1 out fp32
__device__ __nv_bfloat16 g_Xh[(size_t)NN * CC],  g_Xl[(size_t)NN * CC];
__device__ __nv_bfloat16 g_Ah[(size_t)NN * CC],  g_Al[(size_t)NN * CC];   // attn agg split
__device__ __nv_bfloat16 g_Hh[(size_t)NN * CC],  g_Hl[(size_t)NN * CC];   // h1 split
__device__ __nv_bfloat16 g_Th[(size_t)NN * FF],  g_Tl[(size_t)NN * FF];   // ffn hidden split
__device__ __nv_bfloat16 g_Wh[W_TOT];                                     // weights bf16, k-major
__device__ int g_cnt[NN], g_ofs[NN], g_cur[NN];
__device__ int g_ss[EE];                      // src sorted by dst

// ---------------- helpers ----------------
__device__ __forceinline__ uint32_t smem_u32(const void* p) {
    uint32_t a;
    asm("{ .reg .u64 t; cvta.to.shared.u64 t, %1; cvt.u32.u64 %0, t; }" : "=r"(a) : "l"(p));
    return a;
}
#define SWZ(off) ((off) ^ (((off) >> 3) & 0x70))

__device__ __forceinline__ void ldm_x4(uint32_t* r, uint32_t addr) {
    asm volatile("ldmatrix.sync.aligned.m8n8.x4.shared.b16 {%0,%1,%2,%3}, [%4];"
        : "=r"(r[0]), "=r"(r[1]), "=r"(r[2]), "=r"(r[3]) : "r"(addr));
}
__device__ __forceinline__ void mma_bf16(float* d, const uint32_t* a, const uint32_t* b) {
    asm volatile("mma.sync.aligned.m16n8k16.row.col.f32.bf16.bf16.f32 "
        "{%0,%1,%2,%3}, {%4,%5,%6,%7}, {%8,%9}, {%0,%1,%2,%3};"
        : "+f"(d[0]), "+f"(d[1]), "+f"(d[2]), "+f"(d[3])
        : "r"(a[0]), "r"(a[1]), "r"(a[2]), "r"(a[3]), "r"(b[0]), "r"(b[1]));
}
__device__ __forceinline__ void split2(float x, float y, uint32_t& hi, uint32_t& lo) {
    __nv_bfloat162 h = __float22bfloat162_rn(make_float2(x, y));
    float2 hf = __bfloat1622float2(h);
    __nv_bfloat162 l = __float22bfloat162_rn(make_float2(x - hf.x, y - hf.y));
    hi = *(uint32_t*)&h;
    lo = *(uint32_t*)&l;
}
__device__ __forceinline__ void cpa16(uint32_t dst, const void* src, uint32_t sz) {
    asm volatile("cp.async.cg.shared.global [%0], [%1], 16, %2;"
        :: "r"(dst), "l"(src), "r"(sz) : "memory");
}
#define CP_COMMIT() asm volatile("cp.async.commit_group;" ::: "memory")
#define CP_WAIT1()  asm volatile("cp.async.wait_group 1;" ::: "memory")

// unpack 8 bf16 (uint4) -> 8 floats
__device__ __forceinline__ void bf8_to_f(const uint4& r, float* f) {
    float2 t;
    t = __bfloat1622float2(*(const __nv_bfloat162*)&r.x); f[0] = t.x; f[1] = t.y;
    t = __bfloat1622float2(*(const __nv_bfloat162*)&r.y); f[2] = t.x; f[3] = t.y;
    t = __bfloat1622float2(*(const __nv_bfloat162*)&r.z); f[4] = t.x; f[5] = t.y;
    t = __bfloat1622float2(*(const __nv_bfloat162*)&r.w); f[6] = t.x; f[7] = t.y;
}

// ---------------- weight prep: transpose to k-major bf16 ----------------
__global__ void prep_weights(const float* __restrict__ Wq, const float* __restrict__ Wk,
                             const float* __restrict__ Wv, const float* __restrict__ Wo,
                             const float* __restrict__ F1, const float* __restrict__ F2)
{
    int idx = blockIdx.x * 256 + threadIdx.x;
    if (idx >= W_TOT) return;
    float w;
    if (idx < W_WO) {
        int n = idx >> 8, k = idx & 255;
        if (n < 256)      w = Wq[k * 256 + n];
        else if (n < 512) w = Wk[k * 256 + (n - 256)];
        else              w = Wv[k * 256 + (n - 512)];
    } else if (idx < W_F1) {
        int l = idx - W_WO;
        int n = l >> 8, k = l & 255;
        w = Wo[k * 256 + n];
    } else if (idx < W_F2) {
        int l = idx - W_F1;
        int n = l >> 8, k = l & 255;
        w = F1[k * 512 + n];
    } else {
        int l = idx - W_F2;
        int n = l >> 9, k = l & 511;
        w = F2[k * 256 + n];
    }
    g_Wh[idx] = __float2bfloat16(w);
}

// ---------------- fp32 -> bf16 hi/lo split ----------------
__global__ void conv_split(const float* __restrict__ in, __nv_bfloat16* __restrict__ oh,
                           __nv_bfloat16* __restrict__ ol, int n4)
{
    int i = blockIdx.x * 256 + threadIdx.x;
    if (i >= n4) return;
    float4 v = ((const float4*)in)[i];
    uint32_t h0, l0, h1, l1;
    split2(v.x, v.y, h0, l0);
    split2(v.z, v.w, h1, l1);
    ((uint2*)oh)[i] = make_uint2(h0, h1);
    ((uint2*)ol)[i] = make_uint2(l0, l1);
}

// ---------------- pipelined 2-term split GEMM ----------------
// OMODE: 0 = fp32 C; 1 = bf16 split Ch/Cl; 2 = QKV mixed (Q fp32, K|V bf16)
#define STG 49152
#define GEMM_SMEM (2 * STG)

template<int BIAS, int GELU, int OMODE>
__global__ __launch_bounds__(256, 2) void mma_gemm(
    const __nv_bfloat16* __restrict__ Agh, const __nv_bfloat16* __restrict__ Agl,
    const __nv_bfloat16* __restrict__ Bgh,
    const float* __restrict__ bias, float* __restrict__ C,
    __nv_bfloat16* __restrict__ Ch, __nv_bfloat16* __restrict__ Cl,
    __nv_bfloat16* __restrict__ KV,
    int M, int N, int K)
{
    extern __shared__ char smem[];
    uint32_t sb = smem_u32(smem);
    int tid = threadIdx.x, wid = tid >> 5, lane = tid & 31;
    int row0 = blockIdx.y * 128;
    int col0 = blockIdx.x * 128;
    int Am0 = (wid >> 2) * 64;
    int Bn0 = (wid & 3) * 32;

    uint32_t arow[4], brow[2];
#pragma unroll
    for (int mt = 0; mt < 4; mt++)
        arow[mt] = (uint32_t)((Am0 + mt * 16 + (lane & 15)) * 128 + (lane >> 4) * 16);
#pragma unroll
    for (int ntp = 0; ntp < 2; ntp++)
        brow[ntp] = (uint32_t)((Bn0 + ntp * 16 + (lane >> 4) * 8 + (lane & 7)) * 128
                               + ((lane >> 3) & 1) * 16);

    float d[4][4][4];
#pragma unroll
    for (int i = 0; i < 4; i++)
#pragma unroll
        for (int j = 0; j < 4; j++)
#pragma unroll
            for (int e = 0; e < 4; e++) d[i][j][e] = 0.f;

    auto load_stage = [&](int st, int kt) {
        uint32_t base = sb + st * STG;
#pragma unroll
        for (int j = 0; j < 4; j++) {
            int id = tid + 256 * j;
            int r = id >> 3, c = id & 7;
            uint32_t off = SWZ((uint32_t)(r * 128 + c * 16));
            int gr = row0 + r;
            uint32_t sz = (gr < M) ? 16u : 0u;
            int grc = (gr < M) ? gr : (M - 1);
            cpa16(base + off, Agh + (size_t)grc * K + kt + c * 8, sz);
            cpa16(base + 16384 + off, Agl + (size_t)grc * K + kt + c * 8, sz);
            int gn = col0 + r;
            cpa16(base + 32768 + off, Bgh + (size_t)gn * K + kt + c * 8, 16u);
        }
    };

    load_stage(0, 0);
    CP_COMMIT();

    const int nIter = K >> 6;
    for (int it = 0; it < nIter; ++it) {
        if (it + 1 < nIter) load_stage((it + 1) & 1, (it + 1) << 6);
        CP_COMMIT();
        CP_WAIT1();
        __syncthreads();

        uint32_t sAh = sb + (it & 1) * STG;
        uint32_t sAl = sAh + 16384, sBh = sAh + 32768;
#pragma unroll
        for (int ks = 0; ks < 4; ks++) {
            uint32_t aH[4][4], aL[4][4], bH[4][2];
#pragma unroll
            for (int mt = 0; mt < 4; mt++) {
                ldm_x4(aH[mt], sAh + SWZ(arow[mt] + ks * 32));
                ldm_x4(aL[mt], sAl + SWZ(arow[mt] + ks * 32));
            }
#pragma unroll
            for (int ntp = 0; ntp < 2; ntp++)
                ldm_x4(&bH[ntp * 2][0], sBh + SWZ(brow[ntp] + ks * 32));
#pragma unroll
            for (int mt = 0; mt < 4; mt++)
#pragma unroll
                for (int nt = 0; nt < 4; nt++) {
                    mma_bf16(d[mt][nt], aH[mt], bH[nt]);
                    mma_bf16(d[mt][nt], aL[mt], bH[nt]);
                }
        }
        __syncthreads();
    }

#pragma unroll
    for (int nt = 0; nt < 4; nt++) {
        int c = col0 + Bn0 + nt * 8 + (lane & 3) * 2;
        float b0 = 0.f, b1 = 0.f;
        if (BIAS) { b0 = bias[c]; b1 = bias[c + 1]; }
#pragma unroll
        for (int mt = 0; mt < 4; mt++) {
            int r0 = row0 + Am0 + mt * 16 + (lane >> 2);
#pragma unroll
            for (int half = 0; half < 2; half++) {
                int r = r0 + half * 8;
                if (r < M) {
                    float v0 = d[mt][nt][half * 2 + 0] + b0;
                    float v1 = d[mt][nt][half * 2 + 1] + b1;
                    if (GELU) {
                        v0 = 0.5f * v0 * (1.f + erff(v0 * 0.70710678118654752f));
                        v1 = 0.5f * v1 * (1.f + erff(v1 * 0.70710678118654752f));
                    }
                    if (OMODE == 1) {
                        uint32_t h, l;
                        split2(v0, v1, h, l);
                        *(uint32_t*)(Ch + (size_t)r * N + c) = h;
                        *(uint32_t*)(Cl + (size_t)r * N + c) = l;
                    } else if (OMODE == 2) {
                        if (col0 < 256) {   // Q block: fp32
                            *(float2*)(C + (size_t)r * CC + c) = make_float2(v0, v1);
                        } else {            // K|V block: bf16
                            __nv_bfloat162 p = __float22bfloat162_rn(make_float2(v0, v1));
                            *(uint32_t*)(KV + (size_t)r * 512 + (c - 256)) = *(uint32_t*)&p;
                        }
                    } else {
                        *(float2*)(C + (size_t)r * N + c) = make_float2(v0, v1);
                    }
                }
            }
        }
    }
}

// ---------------- GEMM + residual + LayerNorm fused (Wo+LN1, FFN2+LN2) ----------------
#define LSTG 65536
#define LN_SMEM (2 * LSTG)

template<int SPLIT>
__global__ __launch_bounds__(512, 1) void mma_gemm_ln(
    const __nv_bfloat16* __restrict__ Agh, const __nv_bfloat16* __restrict__ Agl,
    const __nv_bfloat16* __restrict__ Bgh,
    const float* __restrict__ bias, const float* __restrict__ Res,
    const float* __restrict__ lnG, const float* __restrict__ lnB,
    float* __restrict__ Out, __nv_bfloat16* __restrict__ Oh, __nv_bfloat16* __restrict__ Ol,
    int M, int K)
{
    extern __shared__ char smem[];
    uint32_t sb = smem_u32(smem);
    int tid = threadIdx.x, wid = tid >> 5, lane = tid & 31;
    int row0 = blockIdx.y * 128;
    int wM = wid >> 2, wN = wid & 3;
    int Am0 = wM * 32;
    int Bn0 = wN * 64;

    uint32_t arow[2], brow[4];
#pragma unroll
    for (int mt = 0; mt < 2; mt++)
        arow[mt] = (uint32_t)((Am0 + mt * 16 + (lane & 15)) * 128 + (lane >> 4) * 16);
#pragma unroll
    for (int ntp = 0; ntp < 4; ntp++)
        brow[ntp] = (uint32_t)((Bn0 + ntp * 16 + (lane >> 4) * 8 + (lane & 7)) * 128
                               + ((lane >> 3) & 1) * 16);

    float d[2][8][4];
#pragma unroll
    for (int i = 0; i < 2; i++)
#pragma unroll
        for (int j = 0; j < 8; j++)
#pragma unroll
            for (int e = 0; e < 4; e++) d[i][j][e] = 0.f;

    auto load_stage = [&](int st, int kt) {
        uint32_t base = sb + st * LSTG;
#pragma unroll
        for (int j = 0; j < 2; j++) {
            int id = tid + 512 * j;
            int r = id >> 3, c = id & 7;
            uint32_t off = SWZ((uint32_t)(r * 128 + c * 16));
            int gr = row0 + r;
            uint32_t sz = (gr < M) ? 16u : 0u;
            int grc = (gr < M) ? gr : (M - 1);
            cpa16(base + off, Agh + (size_t)grc * K + kt + c * 8, sz);
            cpa16(base + 16384 + off, Agl + (size_t)grc * K + kt + c * 8, sz);
        }
#pragma unroll
        for (int j = 0; j < 4; j++) {
            int id = tid + 512 * j;
            int r = id >> 3, c = id & 7;
            uint32_t off = SWZ((uint32_t)(r * 128 + c * 16));
            cpa16(base + 32768 + off, Bgh + (size_t)r * K + kt + c * 8, 16u);
        }
    };

    load_stage(0, 0);
    CP_COMMIT();

    const int nIter = K >> 6;
    for (int it = 0; it < nIter; ++it) {
        if (it + 1 < nIter) load_stage((it + 1) & 1, (it + 1) << 6);
        CP_COMMIT();
        CP_WAIT1();
        __syncthreads();

        uint32_t sAh = sb + (it & 1) * LSTG;
        uint32_t sAl = sAh + 16384, sBh = sAh + 32768;
#pragma unroll
        for (int ks = 0; ks < 4; ks++) {
            uint32_t aH[2][4], aL[2][4], bH[8][2];
#pragma unroll
            for (int mt = 0; mt < 2; mt++) {
                ldm_x4(aH[mt], sAh + SWZ(arow[mt] + ks * 32));
                ldm_x4(aL[mt], sAl + SWZ(arow[mt] + ks * 32));
            }
#pragma unroll
            for (int ntp = 0; ntp < 4; ntp++)
                ldm_x4(&bH[ntp * 2][0], sBh + SWZ(brow[ntp] + ks * 32));
#pragma unroll
            for (int mt = 0; mt < 2; mt++)
#pragma unroll
                for (int nt = 0; nt < 8; nt++) {
                    mma_bf16(d[mt][nt], aH[mt], bH[nt]);
                    mma_bf16(d[mt][nt], aL[mt], bH[nt]);
                }
        }
        __syncthreads();
    }

    float* part = (float*)smem;
    float psum[2][2], psq[2][2];
#pragma unroll
    for (int mt = 0; mt < 2; mt++)
#pragma unroll
    for (int half = 0; half < 2; half++) {
        int lr = Am0 + mt * 16 + (lane >> 2) + half * 8;
        int r = row0 + lr;
        float s = 0.f, q = 0.f;
#pragma unroll
        for (int nt = 0; nt < 8; nt++) {
            int c = Bn0 + nt * 8 + (lane & 3) * 2;
            float2 res = (r < M) ? *(const float2*)(Res + (size_t)r * CC + c)
                                 : make_float2(0.f, 0.f);
            float v0 = d[mt][nt][half * 2 + 0] + bias[c] + res.x;
            float v1 = d[mt][nt][half * 2 + 1] + bias[c + 1] + res.y;
            d[mt][nt][half * 2 + 0] = v0;
            d[mt][nt][half * 2 + 1] = v1;
            s += v0 + v1;
            q += v0 * v0 + v1 * v1;
        }
        s += __shfl_xor_sync(0xffffffffu, s, 1);
        q += __shfl_xor_sync(0xffffffffu, q, 1);
        s += __shfl_xor_sync(0xffffffffu, s, 2);
        q += __shfl_xor_sync(0xffffffffu, q, 2);
        psum[mt][half] = s;
        psq[mt][half] = q;
    }
    if ((lane & 3) == 0) {
#pragma unroll
        for (int mt = 0; mt < 2; mt++)
#pragma unroll
        for (int half = 0; half < 2; half++) {
            int lr = Am0 + mt * 16 + (lane >> 2) + half * 8;
            part[(lr * 4 + wN) * 2 + 0] = psum[mt][half];
            part[(lr * 4 + wN) * 2 + 1] = psq[mt][half];
        }
    }
    __syncthreads();

#pragma unroll
    for (int mt = 0; mt < 2; mt++)
#pragma unroll
    for (int half = 0; half < 2; half++) {
        int lr = Am0 + mt * 16 + (lane >> 2) + half * 8;
        int r = row0 + lr;
        if (r >= M) continue;
        float S = part[(lr * 4 + 0) * 2] + part[(lr * 4 + 1) * 2]
                + part[(lr * 4 + 2) * 2] + part[(lr * 4 + 3) * 2];
        float Q = part[(lr * 4 + 0) * 2 + 1] + part[(lr * 4 + 1) * 2 + 1]
                + part[(lr * 4 + 2) * 2 + 1] + part[(lr * 4 + 3) * 2 + 1];
        float mu = S * (1.f / 256.f);
        float var = Q * (1.f / 256.f) - mu * mu;
        float rs = rsqrtf(var + 1e-5f);
#pragma unroll
        for (int nt = 0; nt < 8; nt++) {
            int c = Bn0 + nt * 8 + (lane & 3) * 2;
            float o0 = (d[mt][nt][half * 2 + 0] - mu) * rs * lnG[c] + lnB[c];
            float o1 = (d[mt][nt][half * 2 + 1] - mu) * rs * lnG[c + 1] + lnB[c + 1];
            *(float2*)(Out + (size_t)r * CC + c) = make_float2(o0, o1);
            if (SPLIT) {
                uint32_t h, l;
                split2(o0, o1, h, l);
                *(uint32_t*)(Oh + (size_t)r * CC + c) = h;
                *(uint32_t*)(Ol + (size_t)r * CC + c) = l;
            }
        }
    }
}

// ---------------- CSR sort: hist -> scan -> scatter ----------------
__global__ void zero_cnt() {
    int i = blockIdx.x * 256 + threadIdx.x;
    if (i < NN) g_cnt[i] = 0;
}
__global__ void hist_kernel(const int* __restrict__ ei) {
    int e = blockIdx.x * 256 + threadIdx.x;
    if (e < EE) atomicAdd(&g_cnt[ei[EE + e]], 1);
}
__global__ __launch_bounds__(1024) void scan_kernel() {
    __shared__ int part[1024];
    const int CH = 49;
    int t = threadIdx.x;
    int base = t * CH;
    int s = 0;
    for (int j = 0; j < CH; j++) {
        int i = base + j;
        if (i < NN) s += g_cnt[i];
    }
    part[t] = s;
    __syncthreads();
    for (int off = 1; off < 1024; off <<= 1) {
        int v = (t >= off) ? part[t - off] : 0;
        __syncthreads();
        part[t] += v;
        __syncthreads();
    }
    int run = (t == 0) ? 0 : part[t - 1];
    for (int j = 0; j < CH; j++) {
        int i = base + j;
        if (i < NN) {
            g_ofs[i] = run;
            g_cur[i] = run;
            run += g_cnt[i];
        }
    }
}
__global__ void scatter_kernel(const int* __restrict__ ei) {
    int e = blockIdx.x * 256 + threadIdx.x;
    if (e >= EE) return;
    int dst = ei[EE + e];
    int pos = atomicAdd(&g_cur[dst], 1);
    g_ss[pos] = ei[e];
}

// ---------------- fused per-dst attention: single-pass online softmax, bf16 K/V ----------------
__global__ __launch_bounds__(256) void attn_kernel(
    __nv_bfloat16* __restrict__ oh, __nv_bfloat16* __restrict__ ol)
{
    int tid = threadIdx.x;
    int w = tid >> 5, lane = tid & 31;
    int h = lane >> 2, sub = lane & 3;
    int dst = blockIdx.x * 8 + w;

    const float* qp = g_Q + (size_t)dst * CC + h * DD + sub * 8;
    float4 q0 = ((const float4*)qp)[0], q1 = ((const float4*)qp)[1];
    const float* qf0 = &q0.x;
    const float* qf1 = &q1.x;
    int beg = g_ofs[dst], cnt = g_cnt[dst];

    float m = 0.f, sum = 0.f;
    float a[8];
#pragma unroll
    for (int e = 0; e < 8; e++) a[e] = 0.f;

    int i = 0;
    for (; i + 1 < cnt; i += 2) {
        int s0 = g_ss[beg + i], s1 = g_ss[beg + i + 1];
        const __nv_bfloat16* b0p = g_KV + (size_t)s0 * 512 + h * DD + sub * 8;
        const __nv_bfloat16* b1p = g_KV + (size_t)s1 * 512 + h * DD + sub * 8;
        // 4 independent LDG.128 (K,V for both edges)
        uint4 k0r = *(const uint4*)b0p;
        uint4 k1r = *(const uint4*)b1p;
        uint4 v0r = *(const uint4*)(b0p + 256);
        uint4 v1r = *(const uint4*)(b1p + 256);
        float kf0[8], kf1[8], vf0[8], vf1[8];
        bf8_to_f(k0r, kf0); bf8_to_f(k1r, kf1);
        bf8_to_f(v0r, vf0); bf8_to_f(v1r, vf1);
        float d0 = 0.f, d1 = 0.f;
#pragma unroll
        for (int e = 0; e < 4; e++) {
            d0 += qf0[e] * kf0[e] + qf1[e] * kf0[4 + e];
            d1 += qf0[e] * kf1[e] + qf1[e] * kf1[4 + e];
        }
        d0 += __shfl_xor_sync(0xffffffffu, d0, 1);
        d1 += __shfl_xor_sync(0xffffffffu, d1, 1);
        d0 += __shfl_xor_sync(0xffffffffu, d0, 2);
        d1 += __shfl_xor_sync(0xffffffffu, d1, 2);
        float sa = d0 * SCALE, sb2 = d1 * SCALE;
        float nm = fmaxf(m, fmaxf(sa, sb2));
        float f  = __expf(m - nm);
        float wa = __expf(sa - nm), wb = __expf(sb2 - nm);
        m = nm;
        sum = sum * f + wa + wb;
#pragma unroll
        for (int e = 0; e < 8; e++)
            a[e] = a[e] * f + wa * vf0[e] + wb * vf1[e];
    }
    if (i < cnt) {
        int s0 = g_ss[beg + i];
        const __nv_bfloat16* b0p = g_KV + (size_t)s0 * 512 + h * DD + sub * 8;
        uint4 k0r = *(const uint4*)b0p;
        uint4 v0r = *(const uint4*)(b0p + 256);
        float kf0[8], vf0[8];
        bf8_to_f(k0r, kf0);
        bf8_to_f(v0r, vf0);
        float d0 = 0.f;
#pragma unroll
        for (int e = 0; e < 4; e++)
            d0 += qf0[e] * kf0[e] + qf1[e] * kf0[4 + e];
        d0 += __shfl_xor_sync(0xffffffffu, d0, 1);
        d0 += __shfl_xor_sync(0xffffffffu, d0, 2);
        float sa = d0 * SCALE;
        float nm = fmaxf(m, sa);
        float f  = __expf(m - nm);
        float wa = __expf(sa - nm);
        m = nm;
        sum = sum * f + wa;
#pragma unroll
        for (int e = 0; e < 8; e++)
            a[e] = a[e] * f + wa * vf0[e];
    }

    float inv = 1.f / (sum + 1e-8f);
    uint32_t h0, l0, h1, l1, h2, l2, h3, l3;
    split2(a[0] * inv, a[1] * inv, h0, l0);
    split2(a[2] * inv, a[3] * inv, h1, l1);
    split2(a[4] * inv, a[5] * inv, h2, l2);
    split2(a[6] * inv, a[7] * inv, h3, l3);
    size_t ob = (size_t)dst * CC + h * DD + sub * 8;
    *(uint4*)(oh + ob) = make_uint4(h0, h1, h2, h3);
    *(uint4*)(ol + ob) = make_uint4(l0, l1, l2, l3);
}

// ---------------- launch ----------------
extern "C" void kernel_launch(void* const* d_in, const int* in_sizes, int n_in,
                              void* d_out, int out_size)
{
    const float* x      = (const float*)d_in[0];
    const int*   ei     = (const int*)d_in[1];
    const float* Wq     = (const float*)d_in[3];
    const float* Wk     = (const float*)d_in[4];
    const float* Wv     = (const float*)d_in[5];
    const float* Wo_w   = (const float*)d_in[6];
    const float* Wo_b   = (const float*)d_in[7];
    const float* ln1_g  = (const float*)d_in[8];
    const float* ln1_b  = (const float*)d_in[9];
    const float* ln2_g  = (const float*)d_in[10];
    const float* ln2_b  = (const float*)d_in[11];
    const float* ffn_w1 = (const float*)d_in[12];
    const float* ffn_b1 = (const float*)d_in[13];
    const float* ffn_w2 = (const float*)d_in[14];
    const float* ffn_b2 = (const float*)d_in[15];
    float* out = (float*)d_out;

    float *pQ, *pH1;
    __nv_bfloat16 *pKV, *pXh, *pXl, *pAh, *pAl, *pHh, *pHl, *pTh, *pTl, *pWth;
    cudaGetSymbolAddress((void**)&pQ,   g_Q);
    cudaGetSymbolAddress((void**)&pKV,  g_KV);
    cudaGetSymbolAddress((void**)&pH1,  g_h1);
    cudaGetSymbolAddress((void**)&pXh,  g_Xh);
    cudaGetSymbolAddress((void**)&pXl,  g_Xl);
    cudaGetSymbolAddress((void**)&pAh,  g_Ah);
    cudaGetSymbolAddress((void**)&pAl,  g_Al);
    cudaGetSymbolAddress((void**)&pHh,  g_Hh);
    cudaGetSymbolAddress((void**)&pHl,  g_Hl);
    cudaGetSymbolAddress((void**)&pTh,  g_Th);
    cudaGetSymbolAddress((void**)&pTl,  g_Tl);
    cudaGetSymbolAddress((void**)&pWth, g_Wh);

    cudaFuncSetAttribute(mma_gemm<0, 0, 2>, cudaFuncAttributeMaxDynamicSharedMemorySize, GEMM_SMEM);
    cudaFuncSetAttribute(mma_gemm<1, 1, 1>, cudaFuncAttributeMaxDynamicSharedMemorySize, GEMM_SMEM);
    cudaFuncSetAttribute(mma_gemm_ln<0>, cudaFuncAttributeMaxDynamicSharedMemorySize, LN_SMEM);
    cudaFuncSetAttribute(mma_gemm_ln<1>, cudaFuncAttributeMaxDynamicSharedMemorySize, LN_SMEM);

    const int MT = (NN + 127) / 128;     // 391

    // prep
    prep_weights<<<(W_TOT + 255) / 256, 256>>>(Wq, Wk, Wv, Wo_w, ffn_w1, ffn_w2);
    conv_split<<<(NN * CC / 4 + 255) / 256, 256>>>(x, pXh, pXl, NN * CC / 4);

    // CSR sort by dst
    zero_cnt<<<(NN + 255) / 256, 256>>>();
    hist_kernel<<<(EE + 255) / 256, 256>>>(ei);
    scan_kernel<<<1, 1024>>>();
    scatter_kernel<<<(EE + 255) / 256, 256>>>(ei);

    // fused QKV: Q fp32, K|V bf16
    mma_gemm<0, 0, 2><<<dim3(6, MT), 256, GEMM_SMEM>>>(
        pXh, pXl, pWth + W_QKV, nullptr, pQ, nullptr, nullptr, pKV, NN, 768, CC);

    // fused attention (online softmax, bf16 K/V) -> split agg
    attn_kernel<<<NN / 8, 256>>>(pAh, pAl);

    // Wo projection + residual(x) + LN1 -> h1 fp32 + split
    mma_gemm_ln<1><<<dim3(1, MT), 512, LN_SMEM>>>(
        pAh, pAl, pWth + W_WO, Wo_b, x, ln1_g, ln1_b, pH1, pHh, pHl, NN, CC);

    // FFN1 + GELU -> hidden split
    mma_gemm<1, 1, 1><<<dim3(4, MT), 256, GEMM_SMEM>>>(
        pHh, pHl, pWth + W_F1, ffn_b1, nullptr, pTh, pTl, nullptr, NN, FF, CC);

    // FFN2 + residual(h1) + LN2 -> out
    mma_gemm_ln<0><<<dim3(1, MT), 512, LN_SMEM>>>(
        pTh, pTl, pWth + W_F2, ffn_b2, pH1, ln2_g, ln2_b, out, nullptr, nullptr, NN, FF);
}

// round 11
// speedup vs baseline: 4.0131x; 1.3195x over previous
#include <cuda_runtime.h>
#include <cuda_fp16.h>
#include <cstdint>

#define NN 50000
#define EE 800000
#define CC 256
#define HH 8
#define DD 32
#define FF 512
#define SCALE 0.17677669529663689f

#define W_QKV 0
#define W_WO  196608
#define W_F1  262144
#define W_F2  393216
#define W_TOT 524288

// ---------------- scratch ----------------
__device__ float g_Q[(size_t)NN * CC];            // Q fp32
__device__ __half g_KV[(size_t)NN * 512];         // K|V fp16 packed per node
__device__ float g_h1[(size_t)NN * CC];           // ln1 out fp32
__device__ __half g_Xf[(size_t)NN * CC];          // x fp16
__device__ __half g_Af[(size_t)NN * CC];          // attn agg fp16
__device__ __half g_Hf[(size_t)NN * CC];          // h1 fp16
__device__ __half g_Tf[(size_t)NN * FF];          // ffn hidden fp16
__device__ __half g_W[W_TOT];                     // weights fp16, k-major
__device__ int g_cnt[NN], g_ofs[NN], g_cur[NN];
__device__ int g_ss[EE];                          // src sorted by dst

// ---------------- helpers ----------------
__device__ __forceinline__ uint32_t smem_u32(const void* p) {
    uint32_t a;
    asm("{ .reg .u64 t; cvta.to.shared.u64 t, %1; cvt.u32.u64 %0, t; }" : "=r"(a) : "l"(p));
    return a;
}
#define SWZ(off) ((off) ^ (((off) >> 3) & 0x70))

__device__ __forceinline__ void ldm_x4(uint32_t* r, uint32_t addr) {
    asm volatile("ldmatrix.sync.aligned.m8n8.x4.shared.b16 {%0,%1,%2,%3}, [%4];"
        : "=r"(r[0]), "=r"(r[1]), "=r"(r[2]), "=r"(r[3]) : "r"(addr));
}
__device__ __forceinline__ void mma_f16(float* d, const uint32_t* a, const uint32_t* b) {
    asm volatile("mma.sync.aligned.m16n8k16.row.col.f32.f16.f16.f32 "
        "{%0,%1,%2,%3}, {%4,%5,%6,%7}, {%8,%9}, {%0,%1,%2,%3};"
        : "+f"(d[0]), "+f"(d[1]), "+f"(d[2]), "+f"(d[3])
        : "r"(a[0]), "r"(a[1]), "r"(a[2]), "r"(a[3]), "r"(b[0]), "r"(b[1]));
}
__device__ __forceinline__ uint32_t f2h2(float x, float y) {
    __half2 h = __float22half2_rn(make_float2(x, y));
    return *(uint32_t*)&h;
}
__device__ __forceinline__ void cpa16(uint32_t dst, const void* src, uint32_t sz) {
    asm volatile("cp.async.cg.shared.global [%0], [%1], 16, %2;"
        :: "r"(dst), "l"(src), "r"(sz) : "memory");
}
#define CP_COMMIT() asm volatile("cp.async.commit_group;" ::: "memory")
#define CP_WAIT1()  asm volatile("cp.async.wait_group 1;" ::: "memory")

// unpack 8 fp16 (uint4) -> 8 floats
__device__ __forceinline__ void h8_to_f(const uint4& r, float* f) {
    float2 t;
    t = __half22float2(*(const __half2*)&r.x); f[0] = t.x; f[1] = t.y;
    t = __half22float2(*(const __half2*)&r.y); f[2] = t.x; f[3] = t.y;
    t = __half22float2(*(const __half2*)&r.z); f[4] = t.x; f[5] = t.y;
    t = __half22float2(*(const __half2*)&r.w); f[6] = t.x; f[7] = t.y;
}

// ---------------- weight prep: transpose to k-major fp16 ----------------
__global__ void prep_weights(const float* __restrict__ Wq, const float* __restrict__ Wk,
                             const float* __restrict__ Wv, const float* __restrict__ Wo,
                             const float* __restrict__ F1, const float* __restrict__ F2)
{
    int idx = blockIdx.x * 256 + threadIdx.x;
    if (idx >= W_TOT) return;
    float w;
    if (idx < W_WO) {
        int n = idx >> 8, k = idx & 255;
        if (n < 256)      w = Wq[k * 256 + n];
        else if (n < 512) w = Wk[k * 256 + (n - 256)];
        else              w = Wv[k * 256 + (n - 512)];
    } else if (idx < W_F1) {
        int l = idx - W_WO;
        int n = l >> 8, k = l & 255;
        w = Wo[k * 256 + n];
    } else if (idx < W_F2) {
        int l = idx - W_F1;
        int n = l >> 8, k = l & 255;
        w = F1[k * 512 + n];
    } else {
        int l = idx - W_F2;
        int n = l >> 9, k = l & 511;
        w = F2[k * 256 + n];
    }
    g_W[idx] = __float2half(w);
}

// ---------------- fp32 -> fp16 convert (vectorized) ----------------
__global__ void conv_f16(const float* __restrict__ in, __half* __restrict__ o, int n4)
{
    int i = blockIdx.x * 256 + threadIdx.x;
    if (i >= n4) return;
    float4 v = ((const float4*)in)[i];
    ((uint2*)o)[i] = make_uint2(f2h2(v.x, v.y), f2h2(v.z, v.w));
}

// ---------------- pipelined fp16 GEMM ----------------
// OMODE: 0 = fp32 C; 1 = fp16 Cf; 2 = QKV mixed (Q fp32, K|V fp16)
#define STG 32768
#define GEMM_SMEM (2 * STG)

template<int BIAS, int GELU, int OMODE>
__global__ __launch_bounds__(256, 2) void mma_gemm(
    const __half* __restrict__ Ag, const __half* __restrict__ Bg,
    const float* __restrict__ bias, float* __restrict__ C,
    __half* __restrict__ Cf, __half* __restrict__ KV,
    int M, int N, int K)
{
    extern __shared__ char smem[];
    uint32_t sb = smem_u32(smem);
    int tid = threadIdx.x, wid = tid >> 5, lane = tid & 31;
    int row0 = blockIdx.y * 128;
    int col0 = blockIdx.x * 128;
    int Am0 = (wid >> 2) * 64;
    int Bn0 = (wid & 3) * 32;

    uint32_t arow[4], brow[2];
#pragma unroll
    for (int mt = 0; mt < 4; mt++)
        arow[mt] = (uint32_t)((Am0 + mt * 16 + (lane & 15)) * 128 + (lane >> 4) * 16);
#pragma unroll
    for (int ntp = 0; ntp < 2; ntp++)
        brow[ntp] = (uint32_t)((Bn0 + ntp * 16 + (lane >> 4) * 8 + (lane & 7)) * 128
                               + ((lane >> 3) & 1) * 16);

    float d[4][4][4];
#pragma unroll
    for (int i = 0; i < 4; i++)
#pragma unroll
        for (int j = 0; j < 4; j++)
#pragma unroll
            for (int e = 0; e < 4; e++) d[i][j][e] = 0.f;

    // stage: A 16KB | B 16KB
    auto load_stage = [&](int st, int kt) {
        uint32_t base = sb + st * STG;
#pragma unroll
        for (int j = 0; j < 4; j++) {
            int id = tid + 256 * j;
            int r = id >> 3, c = id & 7;
            uint32_t off = SWZ((uint32_t)(r * 128 + c * 16));
            int gr = row0 + r;
            uint32_t sz = (gr < M) ? 16u : 0u;
            int grc = (gr < M) ? gr : (M - 1);
            cpa16(base + off, Ag + (size_t)grc * K + kt + c * 8, sz);
            int gn = col0 + r;
            cpa16(base + 16384 + off, Bg + (size_t)gn * K + kt + c * 8, 16u);
        }
    };

    load_stage(0, 0);
    CP_COMMIT();

    const int nIter = K >> 6;
    for (int it = 0; it < nIter; ++it) {
        if (it + 1 < nIter) load_stage((it + 1) & 1, (it + 1) << 6);
        CP_COMMIT();
        CP_WAIT1();
        __syncthreads();

        uint32_t sA = sb + (it & 1) * STG;
        uint32_t sB = sA + 16384;
#pragma unroll
        for (int ks = 0; ks < 4; ks++) {
            uint32_t aF[4][4], bF[4][2];
#pragma unroll
            for (int mt = 0; mt < 4; mt++)
                ldm_x4(aF[mt], sA + SWZ(arow[mt] + ks * 32));
#pragma unroll
            for (int ntp = 0; ntp < 2; ntp++)
                ldm_x4(&bF[ntp * 2][0], sB + SWZ(brow[ntp] + ks * 32));
#pragma unroll
            for (int mt = 0; mt < 4; mt++)
#pragma unroll
                for (int nt = 0; nt < 4; nt++)
                    mma_f16(d[mt][nt], aF[mt], bF[nt]);
        }
        __syncthreads();
    }

#pragma unroll
    for (int nt = 0; nt < 4; nt++) {
        int c = col0 + Bn0 + nt * 8 + (lane & 3) * 2;
        float b0 = 0.f, b1 = 0.f;
        if (BIAS) { b0 = bias[c]; b1 = bias[c + 1]; }
#pragma unroll
        for (int mt = 0; mt < 4; mt++) {
            int r0 = row0 + Am0 + mt * 16 + (lane >> 2);
#pragma unroll
            for (int half = 0; half < 2; half++) {
                int r = r0 + half * 8;
                if (r < M) {
                    float v0 = d[mt][nt][half * 2 + 0] + b0;
                    float v1 = d[mt][nt][half * 2 + 1] + b1;
                    if (GELU) {
                        v0 = 0.5f * v0 * (1.f + erff(v0 * 0.70710678118654752f));
                        v1 = 0.5f * v1 * (1.f + erff(v1 * 0.70710678118654752f));
                    }
                    if (OMODE == 1) {
                        *(uint32_t*)(Cf + (size_t)r * N + c) = f2h2(v0, v1);
                    } else if (OMODE == 2) {
                        if (col0 < 256) {   // Q block: fp32
                            *(float2*)(C + (size_t)r * CC + c) = make_float2(v0, v1);
                        } else {            // K|V block: fp16
                            *(uint32_t*)(KV + (size_t)r * 512 + (c - 256)) = f2h2(v0, v1);
                        }
                    } else {
                        *(float2*)(C + (size_t)r * N + c) = make_float2(v0, v1);
                    }
                }
            }
        }
    }
}

// ---------------- GEMM + residual + LayerNorm fused (Wo+LN1, FFN2+LN2) ----------------
// CTA 128x256 (full row), 512 threads = 16 warps 4(M)x4(N).
#define LSTG 49152
#define LN_SMEM (2 * LSTG)

template<int SPLIT>
__global__ __launch_bounds__(512, 1) void mma_gemm_ln(
    const __half* __restrict__ Ag, const __half* __restrict__ Bg,
    const float* __restrict__ bias, const float* __restrict__ Res,
    const float* __restrict__ lnG, const float* __restrict__ lnB,
    float* __restrict__ Out, __half* __restrict__ Of,
    int M, int K)
{
    extern __shared__ char smem[];
    uint32_t sb = smem_u32(smem);
    int tid = threadIdx.x, wid = tid >> 5, lane = tid & 31;
    int row0 = blockIdx.y * 128;
    int wM = wid >> 2, wN = wid & 3;
    int Am0 = wM * 32;
    int Bn0 = wN * 64;

    uint32_t arow[2], brow[4];
#pragma unroll
    for (int mt = 0; mt < 2; mt++)
        arow[mt] = (uint32_t)((Am0 + mt * 16 + (lane & 15)) * 128 + (lane >> 4) * 16);
#pragma unroll
    for (int ntp = 0; ntp < 4; ntp++)
        brow[ntp] = (uint32_t)((Bn0 + ntp * 16 + (lane >> 4) * 8 + (lane & 7)) * 128
                               + ((lane >> 3) & 1) * 16);

    float d[2][8][4];
#pragma unroll
    for (int i = 0; i < 2; i++)
#pragma unroll
        for (int j = 0; j < 8; j++)
#pragma unroll
            for (int e = 0; e < 4; e++) d[i][j][e] = 0.f;

    // stage: A 16KB | B 32KB = 48KB
    auto load_stage = [&](int st, int kt) {
        uint32_t base = sb + st * LSTG;
#pragma unroll
        for (int j = 0; j < 2; j++) {
            int id = tid + 512 * j;
            int r = id >> 3, c = id & 7;
            uint32_t off = SWZ((uint32_t)(r * 128 + c * 16));
            int gr = row0 + r;
            uint32_t sz = (gr < M) ? 16u : 0u;
            int grc = (gr < M) ? gr : (M - 1);
            cpa16(base + off, Ag + (size_t)grc * K + kt + c * 8, sz);
        }
#pragma unroll
        for (int j = 0; j < 4; j++) {
            int id = tid + 512 * j;
            int r = id >> 3, c = id & 7;
            uint32_t off = SWZ((uint32_t)(r * 128 + c * 16));
            cpa16(base + 16384 + off, Bg + (size_t)r * K + kt + c * 8, 16u);
        }
    };

    load_stage(0, 0);
    CP_COMMIT();

    const int nIter = K >> 6;
    for (int it = 0; it < nIter; ++it) {
        if (it + 1 < nIter) load_stage((it + 1) & 1, (it + 1) << 6);
        CP_COMMIT();
        CP_WAIT1();
        __syncthreads();

        uint32_t sA = sb + (it & 1) * LSTG;
        uint32_t sB = sA + 16384;
#pragma unroll
        for (int ks = 0; ks < 4; ks++) {
            uint32_t aF[2][4], bF[8][2];
#pragma unroll
            for (int mt = 0; mt < 2; mt++)
                ldm_x4(aF[mt], sA + SWZ(arow[mt] + ks * 32));
#pragma unroll
            for (int ntp = 0; ntp < 4; ntp++)
                ldm_x4(&bF[ntp * 2][0], sB + SWZ(brow[ntp] + ks * 32));
#pragma unroll
            for (int mt = 0; mt < 2; mt++)
#pragma unroll
                for (int nt = 0; nt < 8; nt++)
                    mma_f16(d[mt][nt], aF[mt], bF[nt]);
        }
        __syncthreads();
    }

    // ---- epilogue: bias + residual; row partial sums ----
    float* part = (float*)smem;   // [128][4][2] floats = 4KB (stages dead)
    float psum[2][2], psq[2][2];
#pragma unroll
    for (int mt = 0; mt < 2; mt++)
#pragma unroll
    for (int half = 0; half < 2; half++) {
        int lr = Am0 + mt * 16 + (lane >> 2) + half * 8;
        int r = row0 + lr;
        float s = 0.f, q = 0.f;
#pragma unroll
        for (int nt = 0; nt < 8; nt++) {
            int c = Bn0 + nt * 8 + (lane & 3) * 2;
            float2 res = (r < M) ? *(const float2*)(Res + (size_t)r * CC + c)
                                 : make_float2(0.f, 0.f);
            float v0 = d[mt][nt][half * 2 + 0] + bias[c] + res.x;
            float v1 = d[mt][nt][half * 2 + 1] + bias[c + 1] + res.y;
            d[mt][nt][half * 2 + 0] = v0;
            d[mt][nt][half * 2 + 1] = v1;
            s += v0 + v1;
            q += v0 * v0 + v1 * v1;
        }
        s += __shfl_xor_sync(0xffffffffu, s, 1);
        q += __shfl_xor_sync(0xffffffffu, q, 1);
        s += __shfl_xor_sync(0xffffffffu, s, 2);
        q += __shfl_xor_sync(0xffffffffu, q, 2);
        psum[mt][half] = s;
        psq[mt][half] = q;
    }
    if ((lane & 3) == 0) {
#pragma unroll
        for (int mt = 0; mt < 2; mt++)
#pragma unroll
        for (int half = 0; half < 2; half++) {
            int lr = Am0 + mt * 16 + (lane >> 2) + half * 8;
            part[(lr * 4 + wN) * 2 + 0] = psum[mt][half];
            part[(lr * 4 + wN) * 2 + 1] = psq[mt][half];
        }
    }
    __syncthreads();

#pragma unroll
    for (int mt = 0; mt < 2; mt++)
#pragma unroll
    for (int half = 0; half < 2; half++) {
        int lr = Am0 + mt * 16 + (lane >> 2) + half * 8;
        int r = row0 + lr;
        if (r >= M) continue;
        float S = part[(lr * 4 + 0) * 2] + part[(lr * 4 + 1) * 2]
                + part[(lr * 4 + 2) * 2] + part[(lr * 4 + 3) * 2];
        float Q = part[(lr * 4 + 0) * 2 + 1] + part[(lr * 4 + 1) * 2 + 1]
                + part[(lr * 4 + 2) * 2 + 1] + part[(lr * 4 + 3) * 2 + 1];
        float mu = S * (1.f / 256.f);
        float var = Q * (1.f / 256.f) - mu * mu;
        float rs = rsqrtf(var + 1e-5f);
#pragma unroll
        for (int nt = 0; nt < 8; nt++) {
            int c = Bn0 + nt * 8 + (lane & 3) * 2;
            float o0 = (d[mt][nt][half * 2 + 0] - mu) * rs * lnG[c] + lnB[c];
            float o1 = (d[mt][nt][half * 2 + 1] - mu) * rs * lnG[c + 1] + lnB[c + 1];
            *(float2*)(Out + (size_t)r * CC + c) = make_float2(o0, o1);
            if (SPLIT)
                *(uint32_t*)(Of + (size_t)r * CC + c) = f2h2(o0, o1);
        }
    }
}

// ---------------- CSR sort: hist -> scan -> scatter ----------------
__global__ void zero_cnt() {
    int i = blockIdx.x * 256 + threadIdx.x;
    if (i < NN) g_cnt[i] = 0;
}
__global__ void hist_kernel(const int* __restrict__ ei) {
    int e = blockIdx.x * 256 + threadIdx.x;
    if (e < EE) atomicAdd(&g_cnt[ei[EE + e]], 1);
}
__global__ __launch_bounds__(1024) void scan_kernel() {
    __shared__ int part[1024];
    const int CH = 49;
    int t = threadIdx.x;
    int base = t * CH;
    int s = 0;
    for (int j = 0; j < CH; j++) {
        int i = base + j;
        if (i < NN) s += g_cnt[i];
    }
    part[t] = s;
    __syncthreads();
    for (int off = 1; off < 1024; off <<= 1) {
        int v = (t >= off) ? part[t - off] : 0;
        __syncthreads();
        part[t] += v;
        __syncthreads();
    }
    int run = (t == 0) ? 0 : part[t - 1];
    for (int j = 0; j < CH; j++) {
        int i = base + j;
        if (i < NN) {
            g_ofs[i] = run;
            g_cur[i] = run;
            run += g_cnt[i];
        }
    }
}
__global__ void scatter_kernel(const int* __restrict__ ei) {
    int e = blockIdx.x * 256 + threadIdx.x;
    if (e >= EE) return;
    int dst = ei[EE + e];
    int pos = atomicAdd(&g_cur[dst], 1);
    g_ss[pos] = ei[e];
}

// ---------------- fused per-dst attention: single-pass online softmax, fp16 K/V ----------------
__global__ __launch_bounds__(256) void attn_kernel(__half* __restrict__ of)
{
    int tid = threadIdx.x;
    int w = tid >> 5, lane = tid & 31;
    int h = lane >> 2, sub = lane & 3;
    int dst = blockIdx.x * 8 + w;

    const float* qp = g_Q + (size_t)dst * CC + h * DD + sub * 8;
    float4 q0 = ((const float4*)qp)[0], q1 = ((const float4*)qp)[1];
    const float* qf0 = &q0.x;
    const float* qf1 = &q1.x;
    int beg = g_ofs[dst], cnt = g_cnt[dst];

    float m = 0.f, sum = 0.f;
    float a[8];
#pragma unroll
    for (int e = 0; e < 8; e++) a[e] = 0.f;

    int i = 0;
    for (; i + 1 < cnt; i += 2) {
        int s0 = g_ss[beg + i], s1 = g_ss[beg + i + 1];
        const __half* b0p = g_KV + (size_t)s0 * 512 + h * DD + sub * 8;
        const __half* b1p = g_KV + (size_t)s1 * 512 + h * DD + sub * 8;
        uint4 k0r = *(const uint4*)b0p;
        uint4 k1r = *(const uint4*)b1p;
        uint4 v0r = *(const uint4*)(b0p + 256);
        uint4 v1r = *(const uint4*)(b1p + 256);
        float kf0[8], kf1[8], vf0[8], vf1[8];
        h8_to_f(k0r, kf0); h8_to_f(k1r, kf1);
        h8_to_f(v0r, vf0); h8_to_f(v1r, vf1);
        float d0 = 0.f, d1 = 0.f;
#pragma unroll
        for (int e = 0; e < 4; e++) {
            d0 += qf0[e] * kf0[e] + qf1[e] * kf0[4 + e];
            d1 += qf0[e] * kf1[e] + qf1[e] * kf1[4 + e];
        }
        d0 += __shfl_xor_sync(0xffffffffu, d0, 1);
        d1 += __shfl_xor_sync(0xffffffffu, d1, 1);
        d0 += __shfl_xor_sync(0xffffffffu, d0, 2);
        d1 += __shfl_xor_sync(0xffffffffu, d1, 2);
        float sa = d0 * SCALE, sb2 = d1 * SCALE;
        float nm = fmaxf(m, fmaxf(sa, sb2));
        float f  = __expf(m - nm);
        float wa = __expf(sa - nm), wb = __expf(sb2 - nm);
        m = nm;
        sum = sum * f + wa + wb;
#pragma unroll
        for (int e = 0; e < 8; e++)
            a[e] = a[e] * f + wa * vf0[e] + wb * vf1[e];
    }
    if (i < cnt) {
        int s0 = g_ss[beg + i];
        const __half* b0p = g_KV + (size_t)s0 * 512 + h * DD + sub * 8;
        uint4 k0r = *(const uint4*)b0p;
        uint4 v0r = *(const uint4*)(b0p + 256);
        float kf0[8], vf0[8];
        h8_to_f(k0r, kf0);
        h8_to_f(v0r, vf0);
        float d0 = 0.f;
#pragma unroll
        for (int e = 0; e < 4; e++)
            d0 += qf0[e] * kf0[e] + qf1[e] * kf0[4 + e];
        d0 += __shfl_xor_sync(0xffffffffu, d0, 1);
        d0 += __shfl_xor_sync(0xffffffffu, d0, 2);
        float sa = d0 * SCALE;
        float nm = fmaxf(m, sa);
        float f  = __expf(m - nm);
        float wa = __expf(sa - nm);
        m = nm;
        sum = sum * f + wa;
#pragma unroll
        for (int e = 0; e < 8; e++)
            a[e] = a[e] * f + wa * vf0[e];
    }

    float inv = 1.f / (sum + 1e-8f);
    uint4 o;
    o.x = f2h2(a[0] * inv, a[1] * inv);
    o.y = f2h2(a[2] * inv, a[3] * inv);
    o.z = f2h2(a[4] * inv, a[5] * inv);
    o.w = f2h2(a[6] * inv, a[7] * inv);
    *(uint4*)(of + (size_t)dst * CC + h * DD + sub * 8) = o;
}

// ---------------- launch ----------------
extern "C" void kernel_launch(void* const* d_in, const int* in_sizes, int n_in,
                              void* d_out, int out_size)
{
    const float* x      = (const float*)d_in[0];
    const int*   ei     = (const int*)d_in[1];
    const float* Wq     = (const float*)d_in[3];
    const float* Wk     = (const float*)d_in[4];
    const float* Wv     = (const float*)d_in[5];
    const float* Wo_w   = (const float*)d_in[6];
    const float* Wo_b   = (const float*)d_in[7];
    const float* ln1_g  = (const float*)d_in[8];
    const float* ln1_b  = (const float*)d_in[9];
    const float* ln2_g  = (const float*)d_in[10];
    const float* ln2_b  = (const float*)d_in[11];
    const float* ffn_w1 = (const float*)d_in[12];
    const float* ffn_b1 = (const float*)d_in[13];
    const float* ffn_w2 = (const float*)d_in[14];
    const float* ffn_b2 = (const float*)d_in[15];
    float* out = (float*)d_out;

    float *pQ, *pH1;
    __half *pKV, *pXf, *pAf, *pHf, *pTf, *pW;
    cudaGetSymbolAddress((void**)&pQ,   g_Q);
    cudaGetSymbolAddress((void**)&pKV,  g_KV);
    cudaGetSymbolAddress((void**)&pH1,  g_h1);
    cudaGetSymbolAddress((void**)&pXf,  g_Xf);
    cudaGetSymbolAddress((void**)&pAf,  g_Af);
    cudaGetSymbolAddress((void**)&pHf,  g_Hf);
    cudaGetSymbolAddress((void**)&pTf,  g_Tf);
    cudaGetSymbolAddress((void**)&pW,   g_W);

    cudaFuncSetAttribute(mma_gemm<0, 0, 2>, cudaFuncAttributeMaxDynamicSharedMemorySize, GEMM_SMEM);
    cudaFuncSetAttribute(mma_gemm<1, 1, 1>, cudaFuncAttributeMaxDynamicSharedMemorySize, GEMM_SMEM);
    cudaFuncSetAttribute(mma_gemm_ln<0>, cudaFuncAttributeMaxDynamicSharedMemorySize, LN_SMEM);
    cudaFuncSetAttribute(mma_gemm_ln<1>, cudaFuncAttributeMaxDynamicSharedMemorySize, LN_SMEM);

    const int MT = (NN + 127) / 128;     // 391

    // prep
    prep_weights<<<(W_TOT + 255) / 256, 256>>>(Wq, Wk, Wv, Wo_w, ffn_w1, ffn_w2);
    conv_f16<<<(NN * CC / 4 + 255) / 256, 256>>>(x, pXf, NN * CC / 4);

    // CSR sort by dst
    zero_cnt<<<(NN + 255) / 256, 256>>>();
    hist_kernel<<<(EE + 255) / 256, 256>>>(ei);
    scan_kernel<<<1, 1024>>>();
    scatter_kernel<<<(EE + 255) / 256, 256>>>(ei);

    // fused QKV: Q fp32, K|V fp16
    mma_gemm<0, 0, 2><<<dim3(6, MT), 256, GEMM_SMEM>>>(
        pXf, pW + W_QKV, nullptr, pQ, nullptr, pKV, NN, 768, CC);

    // fused attention (online softmax, fp16 K/V) -> fp16 agg
    attn_kernel<<<NN / 8, 256>>>(pAf);

    // Wo projection + residual(x) + LN1 -> h1 fp32 + fp16
    mma_gemm_ln<1><<<dim3(1, MT), 512, LN_SMEM>>>(
        pAf, pW + W_WO, Wo_b, x, ln1_g, ln1_b, pH1, pHf, NN, CC);

    // FFN1 + GELU -> hidden fp16
    mma_gemm<1, 1, 1><<<dim3(4, MT), 256, GEMM_SMEM>>>(
        pHf, pW + W_F1, ffn_b1, nullptr, pTf, nullptr, NN, FF, CC);

    // FFN2 + residual(h1) + LN2 -> out
    mma_gemm_ln<0><<<dim3(1, MT), 512, LN_SMEM>>>(
        pTf, pW + W_F2, ffn_b2, pH1, ln2_g, ln2_b, out, nullptr, NN, FF);
}

// round 12
// speedup vs baseline: 4.8638x; 1.2120x over previous
#include <cuda_runtime.h>
#include <cuda_fp16.h>
#include <cstdint>

#define NN 50000
#define EE 800000
#define CC 256
#define HH 8
#define DD 32
#define FF 512
#define SCALE 0.17677669529663689f

#define W_QKV 0
#define W_WO  196608
#define W_F1  262144
#define W_F2  393216
#define W_TOT 524288

// ---------------- scratch ----------------
__device__ float g_Q[(size_t)NN * CC];            // Q fp32
__device__ __half g_KV[(size_t)NN * 512];         // K|V fp16 packed per node
__device__ float g_h1[(size_t)NN * CC];           // ln1 out fp32
__device__ __half g_Xf[(size_t)NN * CC];          // x fp16
__device__ __half g_Af[(size_t)NN * CC];          // attn agg fp16
__device__ __half g_Hf[(size_t)NN * CC];          // h1 fp16
__device__ __half g_Tf[(size_t)NN * FF];          // ffn hidden fp16
__device__ __half g_W[W_TOT];                     // weights fp16, k-major
__device__ int g_cnt[NN], g_ofs[NN], g_cur[NN];
__device__ int g_ss[EE];                          // src sorted by dst

// ---------------- helpers ----------------
__device__ __forceinline__ uint32_t smem_u32(const void* p) {
    uint32_t a;
    asm("{ .reg .u64 t; cvta.to.shared.u64 t, %1; cvt.u32.u64 %0, t; }" : "=r"(a) : "l"(p));
    return a;
}
#define SWZ(off) ((off) ^ (((off) >> 3) & 0x70))

__device__ __forceinline__ void ldm_x4(uint32_t* r, uint32_t addr) {
    asm volatile("ldmatrix.sync.aligned.m8n8.x4.shared.b16 {%0,%1,%2,%3}, [%4];"
        : "=r"(r[0]), "=r"(r[1]), "=r"(r[2]), "=r"(r[3]) : "r"(addr));
}
__device__ __forceinline__ void mma_f16(float* d, const uint32_t* a, const uint32_t* b) {
    asm volatile("mma.sync.aligned.m16n8k16.row.col.f32.f16.f16.f32 "
        "{%0,%1,%2,%3}, {%4,%5,%6,%7}, {%8,%9}, {%0,%1,%2,%3};"
        : "+f"(d[0]), "+f"(d[1]), "+f"(d[2]), "+f"(d[3])
        : "r"(a[0]), "r"(a[1]), "r"(a[2]), "r"(a[3]), "r"(b[0]), "r"(b[1]));
}
__device__ __forceinline__ uint32_t f2h2(float x, float y) {
    __half2 h = __float22half2_rn(make_float2(x, y));
    return *(uint32_t*)&h;
}
__device__ __forceinline__ void cpa16(uint32_t dst, const void* src, uint32_t sz) {
    asm volatile("cp.async.cg.shared.global [%0], [%1], 16, %2;"
        :: "r"(dst), "l"(src), "r"(sz) : "memory");
}
#define CP_COMMIT() asm volatile("cp.async.commit_group;" ::: "memory")
#define CP_WAIT1()  asm volatile("cp.async.wait_group 1;" ::: "memory")

// unpack 8 fp16 (uint4) -> 8 floats
__device__ __forceinline__ void h8_to_f(const uint4& r, float* f) {
    float2 t;
    t = __half22float2(*(const __half2*)&r.x); f[0] = t.x; f[1] = t.y;
    t = __half22float2(*(const __half2*)&r.y); f[2] = t.x; f[3] = t.y;
    t = __half22float2(*(const __half2*)&r.z); f[4] = t.x; f[5] = t.y;
    t = __half22float2(*(const __half2*)&r.w); f[6] = t.x; f[7] = t.y;
}

// ---------------- weight prep: transpose to k-major fp16 ----------------
__global__ void prep_weights(const float* __restrict__ Wq, const float* __restrict__ Wk,
                             const float* __restrict__ Wv, const float* __restrict__ Wo,
                             const float* __restrict__ F1, const float* __restrict__ F2)
{
    int idx = blockIdx.x * 256 + threadIdx.x;
    if (idx >= W_TOT) return;
    float w;
    if (idx < W_WO) {
        int n = idx >> 8, k = idx & 255;
        if (n < 256)      w = Wq[k * 256 + n];
        else if (n < 512) w = Wk[k * 256 + (n - 256)];
        else              w = Wv[k * 256 + (n - 512)];
    } else if (idx < W_F1) {
        int l = idx - W_WO;
        int n = l >> 8, k = l & 255;
        w = Wo[k * 256 + n];
    } else if (idx < W_F2) {
        int l = idx - W_F1;
        int n = l >> 8, k = l & 255;
        w = F1[k * 512 + n];
    } else {
        int l = idx - W_F2;
        int n = l >> 9, k = l & 511;
        w = F2[k * 256 + n];
    }
    g_W[idx] = __float2half(w);
}

// ---------------- fp32 -> fp16 convert (vectorized) ----------------
__global__ void conv_f16(const float* __restrict__ in, __half* __restrict__ o, int n4)
{
    int i = blockIdx.x * 256 + threadIdx.x;
    if (i >= n4) return;
    float4 v = ((const float4*)in)[i];
    ((uint2*)o)[i] = make_uint2(f2h2(v.x, v.y), f2h2(v.z, v.w));
}

// ---------------- pipelined fp16 GEMM ----------------
// OMODE: 0 = fp32 C; 1 = fp16 Cf; 2 = QKV mixed (Q fp32, K|V fp16)
#define STG 32768
#define GEMM_SMEM (2 * STG)

template<int BIAS, int GELU, int OMODE>
__global__ __launch_bounds__(256, 2) void mma_gemm(
    const __half* __restrict__ Ag, const __half* __restrict__ Bg,
    const float* __restrict__ bias, float* __restrict__ C,
    __half* __restrict__ Cf, __half* __restrict__ KV,
    int M, int N, int K)
{
    extern __shared__ char smem[];
    uint32_t sb = smem_u32(smem);
    int tid = threadIdx.x, wid = tid >> 5, lane = tid & 31;
    int row0 = blockIdx.y * 128;
    int col0 = blockIdx.x * 128;
    int Am0 = (wid >> 2) * 64;
    int Bn0 = (wid & 3) * 32;

    uint32_t arow[4], brow[2];
#pragma unroll
    for (int mt = 0; mt < 4; mt++)
        arow[mt] = (uint32_t)((Am0 + mt * 16 + (lane & 15)) * 128 + (lane >> 4) * 16);
#pragma unroll
    for (int ntp = 0; ntp < 2; ntp++)
        brow[ntp] = (uint32_t)((Bn0 + ntp * 16 + (lane >> 4) * 8 + (lane & 7)) * 128
                               + ((lane >> 3) & 1) * 16);

    float d[4][4][4];
#pragma unroll
    for (int i = 0; i < 4; i++)
#pragma unroll
        for (int j = 0; j < 4; j++)
#pragma unroll
            for (int e = 0; e < 4; e++) d[i][j][e] = 0.f;

    auto load_stage = [&](int st, int kt) {
        uint32_t base = sb + st * STG;
#pragma unroll
        for (int j = 0; j < 4; j++) {
            int id = tid + 256 * j;
            int r = id >> 3, c = id & 7;
            uint32_t off = SWZ((uint32_t)(r * 128 + c * 16));
            int gr = row0 + r;
            uint32_t sz = (gr < M) ? 16u : 0u;
            int grc = (gr < M) ? gr : (M - 1);
            cpa16(base + off, Ag + (size_t)grc * K + kt + c * 8, sz);
            int gn = col0 + r;
            cpa16(base + 16384 + off, Bg + (size_t)gn * K + kt + c * 8, 16u);
        }
    };

    load_stage(0, 0);
    CP_COMMIT();

    const int nIter = K >> 6;
    for (int it = 0; it < nIter; ++it) {
        if (it + 1 < nIter) load_stage((it + 1) & 1, (it + 1) << 6);
        CP_COMMIT();
        CP_WAIT1();
        __syncthreads();

        uint32_t sA = sb + (it & 1) * STG;
        uint32_t sB = sA + 16384;
#pragma unroll
        for (int ks = 0; ks < 4; ks++) {
            uint32_t aF[4][4], bF[4][2];
#pragma unroll
            for (int mt = 0; mt < 4; mt++)
                ldm_x4(aF[mt], sA + SWZ(arow[mt] + ks * 32));
#pragma unroll
            for (int ntp = 0; ntp < 2; ntp++)
                ldm_x4(&bF[ntp * 2][0], sB + SWZ(brow[ntp] + ks * 32));
#pragma unroll
            for (int mt = 0; mt < 4; mt++)
#pragma unroll
                for (int nt = 0; nt < 4; nt++)
                    mma_f16(d[mt][nt], aF[mt], bF[nt]);
        }
        __syncthreads();
    }

#pragma unroll
    for (int nt = 0; nt < 4; nt++) {
        int c = col0 + Bn0 + nt * 8 + (lane & 3) * 2;
        float b0 = 0.f, b1 = 0.f;
        if (BIAS) { b0 = bias[c]; b1 = bias[c + 1]; }
#pragma unroll
        for (int mt = 0; mt < 4; mt++) {
            int r0 = row0 + Am0 + mt * 16 + (lane >> 2);
#pragma unroll
            for (int half = 0; half < 2; half++) {
                int r = r0 + half * 8;
                if (r < M) {
                    float v0 = d[mt][nt][half * 2 + 0] + b0;
                    float v1 = d[mt][nt][half * 2 + 1] + b1;
                    if (GELU) {
                        v0 = 0.5f * v0 * (1.f + erff(v0 * 0.70710678118654752f));
                        v1 = 0.5f * v1 * (1.f + erff(v1 * 0.70710678118654752f));
                    }
                    if (OMODE == 1) {
                        *(uint32_t*)(Cf + (size_t)r * N + c) = f2h2(v0, v1);
                    } else if (OMODE == 2) {
                        if (col0 < 256) {
                            *(float2*)(C + (size_t)r * CC + c) = make_float2(v0, v1);
                        } else {
                            *(uint32_t*)(KV + (size_t)r * 512 + (c - 256)) = f2h2(v0, v1);
                        }
                    } else {
                        *(float2*)(C + (size_t)r * N + c) = make_float2(v0, v1);
                    }
                }
            }
        }
    }
}

// ---------------- GEMM + residual + LayerNorm fused (Wo+LN1, FFN2+LN2) ----------------
#define LSTG 49152
#define LN_SMEM (2 * LSTG)

template<int SPLIT>
__global__ __launch_bounds__(512, 1) void mma_gemm_ln(
    const __half* __restrict__ Ag, const __half* __restrict__ Bg,
    const float* __restrict__ bias, const float* __restrict__ Res,
    const float* __restrict__ lnG, const float* __restrict__ lnB,
    float* __restrict__ Out, __half* __restrict__ Of,
    int M, int K)
{
    extern __shared__ char smem[];
    uint32_t sb = smem_u32(smem);
    int tid = threadIdx.x, wid = tid >> 5, lane = tid & 31;
    int row0 = blockIdx.y * 128;
    int wM = wid >> 2, wN = wid & 3;
    int Am0 = wM * 32;
    int Bn0 = wN * 64;

    uint32_t arow[2], brow[4];
#pragma unroll
    for (int mt = 0; mt < 2; mt++)
        arow[mt] = (uint32_t)((Am0 + mt * 16 + (lane & 15)) * 128 + (lane >> 4) * 16);
#pragma unroll
    for (int ntp = 0; ntp < 4; ntp++)
        brow[ntp] = (uint32_t)((Bn0 + ntp * 16 + (lane >> 4) * 8 + (lane & 7)) * 128
                               + ((lane >> 3) & 1) * 16);

    float d[2][8][4];
#pragma unroll
    for (int i = 0; i < 2; i++)
#pragma unroll
        for (int j = 0; j < 8; j++)
#pragma unroll
            for (int e = 0; e < 4; e++) d[i][j][e] = 0.f;

    auto load_stage = [&](int st, int kt) {
        uint32_t base = sb + st * LSTG;
#pragma unroll
        for (int j = 0; j < 2; j++) {
            int id = tid + 512 * j;
            int r = id >> 3, c = id & 7;
            uint32_t off = SWZ((uint32_t)(r * 128 + c * 16));
            int gr = row0 + r;
            uint32_t sz = (gr < M) ? 16u : 0u;
            int grc = (gr < M) ? gr : (M - 1);
            cpa16(base + off, Ag + (size_t)grc * K + kt + c * 8, sz);
        }
#pragma unroll
        for (int j = 0; j < 4; j++) {
            int id = tid + 512 * j;
            int r = id >> 3, c = id & 7;
            uint32_t off = SWZ((uint32_t)(r * 128 + c * 16));
            cpa16(base + 16384 + off, Bg + (size_t)r * K + kt + c * 8, 16u);
        }
    };

    load_stage(0, 0);
    CP_COMMIT();

    const int nIter = K >> 6;
    for (int it = 0; it < nIter; ++it) {
        if (it + 1 < nIter) load_stage((it + 1) & 1, (it + 1) << 6);
        CP_COMMIT();
        CP_WAIT1();
        __syncthreads();

        uint32_t sA = sb + (it & 1) * LSTG;
        uint32_t sB = sA + 16384;
#pragma unroll
        for (int ks = 0; ks < 4; ks++) {
            uint32_t aF[2][4], bF[8][2];
#pragma unroll
            for (int mt = 0; mt < 2; mt++)
                ldm_x4(aF[mt], sA + SWZ(arow[mt] + ks * 32));
#pragma unroll
            for (int ntp = 0; ntp < 4; ntp++)
                ldm_x4(&bF[ntp * 2][0], sB + SWZ(brow[ntp] + ks * 32));
#pragma unroll
            for (int mt = 0; mt < 2; mt++)
#pragma unroll
                for (int nt = 0; nt < 8; nt++)
                    mma_f16(d[mt][nt], aF[mt], bF[nt]);
        }
        __syncthreads();
    }

    float* part = (float*)smem;
    float psum[2][2], psq[2][2];
#pragma unroll
    for (int mt = 0; mt < 2; mt++)
#pragma unroll
    for (int half = 0; half < 2; half++) {
        int lr = Am0 + mt * 16 + (lane >> 2) + half * 8;
        int r = row0 + lr;
        float s = 0.f, q = 0.f;
#pragma unroll
        for (int nt = 0; nt < 8; nt++) {
            int c = Bn0 + nt * 8 + (lane & 3) * 2;
            float2 res = (r < M) ? *(const float2*)(Res + (size_t)r * CC + c)
                                 : make_float2(0.f, 0.f);
            float v0 = d[mt][nt][half * 2 + 0] + bias[c] + res.x;
            float v1 = d[mt][nt][half * 2 + 1] + bias[c + 1] + res.y;
            d[mt][nt][half * 2 + 0] = v0;
            d[mt][nt][half * 2 + 1] = v1;
            s += v0 + v1;
            q += v0 * v0 + v1 * v1;
        }
        s += __shfl_xor_sync(0xffffffffu, s, 1);
        q += __shfl_xor_sync(0xffffffffu, q, 1);
        s += __shfl_xor_sync(0xffffffffu, s, 2);
        q += __shfl_xor_sync(0xffffffffu, q, 2);
        psum[mt][half] = s;
        psq[mt][half] = q;
    }
    if ((lane & 3) == 0) {
#pragma unroll
        for (int mt = 0; mt < 2; mt++)
#pragma unroll
        for (int half = 0; half < 2; half++) {
            int lr = Am0 + mt * 16 + (lane >> 2) + half * 8;
            part[(lr * 4 + wN) * 2 + 0] = psum[mt][half];
            part[(lr * 4 + wN) * 2 + 1] = psq[mt][half];
        }
    }
    __syncthreads();

#pragma unroll
    for (int mt = 0; mt < 2; mt++)
#pragma unroll
    for (int half = 0; half < 2; half++) {
        int lr = Am0 + mt * 16 + (lane >> 2) + half * 8;
        int r = row0 + lr;
        if (r >= M) continue;
        float S = part[(lr * 4 + 0) * 2] + part[(lr * 4 + 1) * 2]
                + part[(lr * 4 + 2) * 2] + part[(lr * 4 + 3) * 2];
        float Q = part[(lr * 4 + 0) * 2 + 1] + part[(lr * 4 + 1) * 2 + 1]
                + part[(lr * 4 + 2) * 2 + 1] + part[(lr * 4 + 3) * 2 + 1];
        float mu = S * (1.f / 256.f);
        float var = Q * (1.f / 256.f) - mu * mu;
        float rs = rsqrtf(var + 1e-5f);
#pragma unroll
        for (int nt = 0; nt < 8; nt++) {
            int c = Bn0 + nt * 8 + (lane & 3) * 2;
            float o0 = (d[mt][nt][half * 2 + 0] - mu) * rs * lnG[c] + lnB[c];
            float o1 = (d[mt][nt][half * 2 + 1] - mu) * rs * lnG[c + 1] + lnB[c + 1];
            *(float2*)(Out + (size_t)r * CC + c) = make_float2(o0, o1);
            if (SPLIT)
                *(uint32_t*)(Of + (size_t)r * CC + c) = f2h2(o0, o1);
        }
    }
}

// ---------------- CSR sort: hist -> scan -> scatter ----------------
__global__ void zero_cnt() {
    int i = blockIdx.x * 256 + threadIdx.x;
    if (i < NN) g_cnt[i] = 0;
}
__global__ void hist_kernel(const int* __restrict__ ei) {
    int e = blockIdx.x * 256 + threadIdx.x;
    if (e < EE) atomicAdd(&g_cnt[ei[EE + e]], 1);
}
__global__ __launch_bounds__(1024) void scan_kernel() {
    __shared__ int part[1024];
    const int CH = 49;
    int t = threadIdx.x;
    int base = t * CH;
    int s = 0;
    for (int j = 0; j < CH; j++) {
        int i = base + j;
        if (i < NN) s += g_cnt[i];
    }
    part[t] = s;
    __syncthreads();
    for (int off = 1; off < 1024; off <<= 1) {
        int v = (t >= off) ? part[t - off] : 0;
        __syncthreads();
        part[t] += v;
        __syncthreads();
    }
    int run = (t == 0) ? 0 : part[t - 1];
    for (int j = 0; j < CH; j++) {
        int i = base + j;
        if (i < NN) {
            g_ofs[i] = run;
            g_cur[i] = run;
            run += g_cnt[i];
        }
    }
}
__global__ void scatter_kernel(const int* __restrict__ ei) {
    int e = blockIdx.x * 256 + threadIdx.x;
    if (e >= EE) return;
    int dst = ei[EE + e];
    int pos = atomicAdd(&g_cur[dst], 1);
    g_ss[pos] = ei[e];
}

// ---------------- fused per-dst attention: single-pass online softmax, fp16 K/V ----------------
__global__ __launch_bounds__(256) void attn_kernel(__half* __restrict__ of)
{
    int tid = threadIdx.x;
    int w = tid >> 5, lane = tid & 31;
    int h = lane >> 2, sub = lane & 3;
    int dst = blockIdx.x * 8 + w;

    const float* qp = g_Q + (size_t)dst * CC + h * DD + sub * 8;
    float4 q0 = ((const float4*)qp)[0], q1 = ((const float4*)qp)[1];
    const float* qf0 = &q0.x;
    const float* qf1 = &q1.x;
    int beg = g_ofs[dst], cnt = g_cnt[dst];

    float m = 0.f, sum = 0.f;
    float a[8];
#pragma unroll
    for (int e = 0; e < 8; e++) a[e] = 0.f;

    int i = 0;
    for (; i + 1 < cnt; i += 2) {
        int s0 = g_ss[beg + i], s1 = g_ss[beg + i + 1];
        const __half* b0p = g_KV + (size_t)s0 * 512 + h * DD + sub * 8;
        const __half* b1p = g_KV + (size_t)s1 * 512 + h * DD + sub * 8;
        uint4 k0r = *(const uint4*)b0p;
        uint4 k1r = *(const uint4*)b1p;
        uint4 v0r = *(const uint4*)(b0p + 256);
        uint4 v1r = *(const uint4*)(b1p + 256);
        float kf0[8], kf1[8], vf0[8], vf1[8];
        h8_to_f(k0r, kf0); h8_to_f(k1r, kf1);
        h8_to_f(v0r, vf0); h8_to_f(v1r, vf1);
        float d0 = 0.f, d1 = 0.f;
#pragma unroll
        for (int e = 0; e < 4; e++) {
            d0 += qf0[e] * kf0[e] + qf1[e] * kf0[4 + e];
            d1 += qf0[e] * kf1[e] + qf1[e] * kf1[4 + e];
        }
        d0 += __shfl_xor_sync(0xffffffffu, d0, 1);
        d1 += __shfl_xor_sync(0xffffffffu, d1, 1);
        d0 += __shfl_xor_sync(0xffffffffu, d0, 2);
        d1 += __shfl_xor_sync(0xffffffffu, d1, 2);
        float sa = d0 * SCALE, sb2 = d1 * SCALE;
        float nm = fmaxf(m, fmaxf(sa, sb2));
        float f  = __expf(m - nm);
        float wa = __expf(sa - nm), wb = __expf(sb2 - nm);
        m = nm;
        sum = sum * f + wa + wb;
#pragma unroll
        for (int e = 0; e < 8; e++)
            a[e] = a[e] * f + wa * vf0[e] + wb * vf1[e];
    }
    if (i < cnt) {
        int s0 = g_ss[beg + i];
        const __half* b0p = g_KV + (size_t)s0 * 512 + h * DD + sub * 8;
        uint4 k0r = *(const uint4*)b0p;
        uint4 v0r = *(const uint4*)(b0p + 256);
        float kf0[8], vf0[8];
        h8_to_f(k0r, kf0);
        h8_to_f(v0r, vf0);
        float d0 = 0.f;
#pragma unroll
        for (int e = 0; e < 4; e++)
            d0 += qf0[e] * kf0[e] + qf1[e] * kf0[4 + e];
        d0 += __shfl_xor_sync(0xffffffffu, d0, 1);
        d0 += __shfl_xor_sync(0xffffffffu, d0, 2);
        float sa = d0 * SCALE;
        float nm = fmaxf(m, sa);
        float f  = __expf(m - nm);
        float wa = __expf(sa - nm);
        m = nm;
        sum = sum * f + wa;
#pragma unroll
        for (int e = 0; e < 8; e++)
            a[e] = a[e] * f + wa * vf0[e];
    }

    float inv = 1.f / (sum + 1e-8f);
    uint4 o;
    o.x = f2h2(a[0] * inv, a[1] * inv);
    o.y = f2h2(a[2] * inv, a[3] * inv);
    o.z = f2h2(a[4] * inv, a[5] * inv);
    o.w = f2h2(a[6] * inv, a[7] * inv);
    *(uint4*)(of + (size_t)dst * CC + h * DD + sub * 8) = o;
}

// ---------------- launch ----------------
extern "C" void kernel_launch(void* const* d_in, const int* in_sizes, int n_in,
                              void* d_out, int out_size)
{
    const float* x      = (const float*)d_in[0];
    const int*   ei     = (const int*)d_in[1];
    const float* Wq     = (const float*)d_in[3];
    const float* Wk     = (const float*)d_in[4];
    const float* Wv     = (const float*)d_in[5];
    const float* Wo_w   = (const float*)d_in[6];
    const float* Wo_b   = (const float*)d_in[7];
    const float* ln1_g  = (const float*)d_in[8];
    const float* ln1_b  = (const float*)d_in[9];
    const float* ln2_g  = (const float*)d_in[10];
    const float* ln2_b  = (const float*)d_in[11];
    const float* ffn_w1 = (const float*)d_in[12];
    const float* ffn_b1 = (const float*)d_in[13];
    const float* ffn_w2 = (const float*)d_in[14];
    const float* ffn_b2 = (const float*)d_in[15];
    float* out = (float*)d_out;

    float *pQ, *pH1;
    __half *pKV, *pXf, *pAf, *pHf, *pTf, *pW;
    cudaGetSymbolAddress((void**)&pQ,   g_Q);
    cudaGetSymbolAddress((void**)&pKV,  g_KV);
    cudaGetSymbolAddress((void**)&pH1,  g_h1);
    cudaGetSymbolAddress((void**)&pXf,  g_Xf);
    cudaGetSymbolAddress((void**)&pAf,  g_Af);
    cudaGetSymbolAddress((void**)&pHf,  g_Hf);
    cudaGetSymbolAddress((void**)&pTf,  g_Tf);
    cudaGetSymbolAddress((void**)&pW,   g_W);

    cudaFuncSetAttribute(mma_gemm<0, 0, 2>, cudaFuncAttributeMaxDynamicSharedMemorySize, GEMM_SMEM);
    cudaFuncSetAttribute(mma_gemm<1, 1, 1>, cudaFuncAttributeMaxDynamicSharedMemorySize, GEMM_SMEM);
    cudaFuncSetAttribute(mma_gemm_ln<0>, cudaFuncAttributeMaxDynamicSharedMemorySize, LN_SMEM);
    cudaFuncSetAttribute(mma_gemm_ln<1>, cudaFuncAttributeMaxDynamicSharedMemorySize, LN_SMEM);

    // lazy host-side resources (created on the first, non-captured call; reused after)
    static cudaStream_t s2 = nullptr;
    static cudaEvent_t evRoot = nullptr, evSort = nullptr;
    if (s2 == nullptr) {
        cudaStreamCreateWithFlags(&s2, cudaStreamNonBlocking);
        cudaEventCreateWithFlags(&evRoot, cudaEventDisableTiming);
        cudaEventCreateWithFlags(&evSort, cudaEventDisableTiming);
    }

    const int MT = (NN + 127) / 128;     // 391

    // ---- fork: CSR sort chain on side stream s2 ----
    cudaEventRecord(evRoot, 0);
    cudaStreamWaitEvent(s2, evRoot, 0);
    zero_cnt<<<(NN + 255) / 256, 256, 0, s2>>>();
    hist_kernel<<<(EE + 255) / 256, 256, 0, s2>>>(ei);
    scan_kernel<<<1, 1024, 0, s2>>>();
    scatter_kernel<<<(EE + 255) / 256, 256, 0, s2>>>(ei);
    cudaEventRecord(evSort, s2);

    // ---- main stream: prep + QKV (independent of sort) ----
    prep_weights<<<(W_TOT + 255) / 256, 256>>>(Wq, Wk, Wv, Wo_w, ffn_w1, ffn_w2);
    conv_f16<<<(NN * CC / 4 + 255) / 256, 256>>>(x, pXf, NN * CC / 4);
    mma_gemm<0, 0, 2><<<dim3(6, MT), 256, GEMM_SMEM>>>(
        pXf, pW + W_QKV, nullptr, pQ, nullptr, pKV, NN, 768, CC);

    // ---- join: attention needs QKV + sorted CSR ----
    cudaStreamWaitEvent(0, evSort, 0);
    attn_kernel<<<NN / 8, 256>>>(pAf);

    // Wo projection + residual(x) + LN1 -> h1 fp32 + fp16
    mma_gemm_ln<1><<<dim3(1, MT), 512, LN_SMEM>>>(
        pAf, pW + W_WO, Wo_b, x, ln1_g, ln1_b, pH1, pHf, NN, CC);

    // FFN1 + GELU -> hidden fp16
    mma_gemm<1, 1, 1><<<dim3(4, MT), 256, GEMM_SMEM>>>(
        pHf, pW + W_F1, ffn_b1, nullptr, pTf, nullptr, NN, FF, CC);

    // FFN2 + residual(h1) + LN2 -> out
    mma_gemm_ln<0><<<dim3(1, MT), 512, LN_SMEM>>>(
        pTf, pW + W_F2, ffn_b2, pH1, ln2_g, ln2_b, out, nullptr, NN, FF);
}